// round 6
// baseline (speedup 1.0000x reference)
#include <cuda_runtime.h>
#include <cuda_bf16.h>
#include <mma.h>
#include <stdint.h>
#include <math.h>

using namespace nvcuda;

#define TT   512
#define BB   128
#define HH   512
#define CC   32
#define TIN  128
#define NCHN 2048
#define HORZ 96
#define NELEM (TT*BB*HH)

// ---------------- scratch ----------------
__device__ float g_conv[BB*NCHN*TIN];   // (B, 2048, Tin)
__device__ float g_bufA[NELEM];         // X after bn1: (tau, h, b)
__device__ float g_bufB[NELEM];         // mem3:        (tau, h, b)
__device__ float g_V[NELEM];            // (m = t*BB+b, n)
__device__ __nv_bfloat16 g_Xhi[NELEM];  // mem3 (m, k) split
__device__ __nv_bfloat16 g_Xlo[NELEM];
__device__ __nv_bfloat16 g_Yhi[NELEM];  // Y = X @ Aop^T (m, k) split
__device__ __nv_bfloat16 g_Ylo[NELEM];
__device__ __nv_bfloat16 g_Wvhi[HH*HH], g_Wvlo[HH*HH];
__device__ __nv_bfloat16 g_Aophi[HH*HH], g_Aoplo[HH*HH];
__device__ float g_u[HH], g_w2[HH], g_cc[1];
__device__ float g_c1[BB*TT], g_c2[BB*TT];
__device__ float g_wpart[4*BB*TT];
__device__ float g_wsum[BB*TT];
__device__ float g_feat[BB*HH];
__device__ float g_featn[BB*HH];
__device__ float g_chm[NCHN];
__device__ float g_chr[NCHN];

__device__ __forceinline__ void split2(float x, float y, uint32_t& hi, uint32_t& lo) {
    __nv_bfloat16 hx = __float2bfloat16(x), hy = __float2bfloat16(y);
    __nv_bfloat16 lx = __float2bfloat16(x - __bfloat162float(hx));
    __nv_bfloat16 ly = __float2bfloat16(y - __bfloat162float(hy));
    __nv_bfloat162 h(hx, hy), l(lx, ly);
    hi = *(uint32_t*)&h; lo = *(uint32_t*)&l;
}
__device__ __forceinline__ void split1(float x, __nv_bfloat16& hi, __nv_bfloat16& lo) {
    hi = __float2bfloat16(x);
    lo = __float2bfloat16(x - __bfloat162float(hi));
}

// ============== conv + channel stats + bn1t (R5-identical) ==============
__global__ void conv_kernel(const float* __restrict__ x,
                            const float* __restrict__ w,
                            const float* __restrict__ cb) {
    __shared__ float xs[130][33];
    __shared__ float ws[8*96];
    int b  = blockIdx.y;
    int c0 = blockIdx.x * 8;
    int t  = threadIdx.x;
    for (int i = t; i < 130*32; i += 128) {
        int r = i >> 5, ci = i & 31;
        int tt = r - 1;
        xs[r][ci] = (tt >= 0 && tt < TIN) ? x[(b*TIN + tt)*CC + ci] : 0.0f;
    }
    for (int i = t; i < 8*96; i += 128) ws[i] = w[c0*96 + i];
    __syncthreads();
    float acc[8];
    #pragma unroll
    for (int cc = 0; cc < 8; cc++) acc[cc] = cb[c0+cc];
    #pragma unroll
    for (int i = 0; i < 32; i++) {
        float x0 = xs[t][i], x1 = xs[t+1][i], x2 = xs[t+2][i];
        #pragma unroll
        for (int cc = 0; cc < 8; cc++) {
            acc[cc] += ws[cc*96 + i*3+0]*x0 + ws[cc*96 + i*3+1]*x1 + ws[cc*96 + i*3+2]*x2;
        }
    }
    #pragma unroll
    for (int cc = 0; cc < 8; cc++)
        g_conv[(b*NCHN + c0+cc)*TIN + t] = acc[cc];
}

__global__ void chan_stats_kernel() {
    int c = blockIdx.x;
    int tid = threadIdx.x;
    float s = 0.f, sq = 0.f;
    for (int i = tid; i < BB*TIN; i += 256) {
        int b = i >> 7, t = i & 127;
        float v = g_conv[(b*NCHN + c)*TIN + t];
        s += v; sq += v*v;
    }
    __shared__ float ss[256], sqs[256];
    ss[tid] = s; sqs[tid] = sq;
    __syncthreads();
    for (int o = 128; o > 0; o >>= 1) {
        if (tid < o) { ss[tid] += ss[tid+o]; sqs[tid] += sqs[tid+o]; }
        __syncthreads();
    }
    if (tid == 0) {
        float m   = ss[0] * (1.0f/(BB*TIN));
        float var = sqs[0] * (1.0f/(BB*TIN)) - m*m;
        g_chm[c] = m;
        g_chr[c] = rsqrtf(var + 1e-5f);
    }
}

__global__ void bn1t_kernel(const float* __restrict__ g,
                            const float* __restrict__ bb) {
    __shared__ float sm_t[128*33];
    int c = blockIdx.x, bq = blockIdx.y;
    int ts = c >> 9, h = c & 511;
    int tid = threadIdx.x;
    float chm = g_chm[c], chr = g_chr[c], gg = g[c], bo = bb[c];
    int bl = tid >> 2, tq = tid & 3;
    int b = bq*32 + bl;
    const float* src = g_conv + ((size_t)b*NCHN + c)*TIN;
    #pragma unroll
    for (int it = 0; it < 8; it++) {
        int tbase = (tq + it*4)*4;
        float4 v = *(const float4*)(src + tbase);
        sm_t[(tbase+0)*33 + bl] = (v.x - chm) * chr * gg + bo;
        sm_t[(tbase+1)*33 + bl] = (v.y - chm) * chr * gg + bo;
        sm_t[(tbase+2)*33 + bl] = (v.z - chm) * chr * gg + bo;
        sm_t[(tbase+3)*33 + bl] = (v.w - chm) * chr * gg + bo;
    }
    __syncthreads();
    int bl2 = tid & 31, tch = tid >> 5;
    #pragma unroll 8
    for (int it = 0; it < 32; it++) {
        int t = tch*32 + it;
        g_bufA[((size_t)(t*4 + ts)*HH + h)*BB + bq*32 + bl2] = sm_t[t*33 + bl2];
    }
}

// ============== fused lif1 -> bn2 -> lif2 -> bn3 -> lif3 (R5-identical) ======
__global__ __launch_bounds__(128) void snn_fused_kernel(
        const float* __restrict__ be,  const float* __restrict__ g2a,
        const float* __restrict__ b2a, const float* __restrict__ be2,
        const float* __restrict__ g3a, const float* __restrict__ b3a,
        const float* __restrict__ be3) {
    __shared__ int scnt[2][2][4];
    int tid = threadIdx.x;
    int h = blockIdx.x;
    int warp = tid >> 5, lane = tid & 31;
    float beta1 = fminf(fmaxf(be[h],  0.0f), 0.99f);
    float beta2 = fminf(fmaxf(be2[h], 0.0f), 0.99f);
    float beta3 = fminf(fmaxf(be3[h], 0.0f), 0.99f);
    float g2 = g2a[h], b2 = b2a[h], g3 = g3a[h], b3 = b3a[h];
    const float* src = g_bufA + (size_t)h*BB + tid;
    float* dst       = g_bufB + (size_t)h*BB + tid;
    float mem1 = 0.f, mem2 = 0.f, mem3 = 0.f;

    float cur[4];
    #pragma unroll
    for (int j = 0; j < 4; j++) cur[j] = src[(size_t)j*HH*BB];

    for (int t0 = 0; t0 < TT; t0 += 4) {
        float nxt[4] = {0.f, 0.f, 0.f, 0.f};
        if (t0 + 4 < TT) {
            #pragma unroll
            for (int j = 0; j < 4; j++) nxt[j] = src[(size_t)(t0+4+j)*HH*BB];
        }
        #pragma unroll
        for (int j = 0; j < 4; j++) {
            int t = t0 + j, par = t & 1;
            float reset = (mem1 > 1.0f) ? 1.0f : 0.0f;
            mem1 = beta1*mem1 + cur[j] - reset;
            float s1 = (mem1 > 1.0f) ? 1.0f : 0.0f;
            unsigned bal = __ballot_sync(0xffffffffu, mem1 > 1.0f);
            if (lane == 0) scnt[0][par][warp] = __popc(bal);
            __syncthreads();
            float sq = (float)(scnt[0][par][0] + scnt[0][par][1]
                             + scnt[0][par][2] + scnt[0][par][3]);
            float m    = sq * (1.0f/BB);
            float rstd = rsqrtf(sq*(1.0f/BB) - m*m + 1e-5f);
            float gg = g2*rstd;
            float bo = b2 - m*gg;
            float h2 = s1*gg + bo;

            float reset2 = (mem2 > 1.0f) ? 1.0f : 0.0f;
            mem2 = beta2*mem2 + h2 - reset2;
            float s2 = (mem2 > 1.0f) ? 1.0f : 0.0f;
            bal = __ballot_sync(0xffffffffu, mem2 > 1.0f);
            if (lane == 0) scnt[1][par][warp] = __popc(bal);
            __syncthreads();
            sq = (float)(scnt[1][par][0] + scnt[1][par][1]
                       + scnt[1][par][2] + scnt[1][par][3]);
            m    = sq * (1.0f/BB);
            rstd = rsqrtf(sq*(1.0f/BB) - m*m + 1e-5f);
            gg = g3*rstd;
            bo = b3 - m*gg;
            float h3 = s2*gg + bo;

            float reset3 = (mem3 > 1.0f) ? 1.0f : 0.0f;
            mem3 = beta3*mem3 + h3 - reset3;
            dst[(size_t)t*HH*BB] = mem3;
        }
        #pragma unroll
        for (int j = 0; j < 4; j++) cur[j] = nxt[j];
    }
}

// ============== prep: u, w2, c0 ==============
__global__ void prep_uwc_kernel(const float* __restrict__ wq,
                                const float* __restrict__ bk,
                                const float* __restrict__ wk,
                                const float* __restrict__ bq) {
    int k = blockIdx.x*128 + threadIdx.x;
    float su = 0.f, sw = 0.f;
    for (int n = 0; n < HH; n++) {
        su += wq[n*HH + k] * bk[n];
        sw += wk[n*HH + k] * bq[n];
    }
    g_u[k] = su; g_w2[k] = sw;
    if (blockIdx.x == 0 && threadIdx.x == 0) {
        float c = 0.f;
        for (int n = 0; n < HH; n++) c += bq[n]*bk[n];
        g_cc[0] = c;
    }
}

// ============== prep: split Wv to bf16 hi/lo ==============
__global__ void wv_split_kernel(const float* __restrict__ wv) {
    int n = blockIdx.x, tid = threadIdx.x;
    int idx = n*HH + tid*4;
    float4 v = *(const float4*)(wv + idx);
    uint32_t h0, l0, h1, l1;
    split2(v.x, v.y, h0, l0); split2(v.z, v.w, h1, l1);
    *(uint32_t*)&g_Wvhi[idx]   = h0; *(uint32_t*)&g_Wvhi[idx+2] = h1;
    *(uint32_t*)&g_Wvlo[idx]   = l0; *(uint32_t*)&g_Wvlo[idx+2] = l1;
}

// ============== prep: Aop[n][k] = sum_j Wq[j][k]*Wk[j][n], split ==============
__global__ void aop_kernel(const float* __restrict__ wq,
                           const float* __restrict__ wk) {
    int k  = blockIdx.x*128 + threadIdx.x;
    int n0 = blockIdx.y*16;
    float acc[16] = {};
    for (int j = 0; j < HH; j++) {
        float a = wq[j*HH + k];
        #pragma unroll
        for (int i = 0; i < 16; i++)
            acc[i] += a * wk[j*HH + n0 + i];
    }
    #pragma unroll
    for (int i = 0; i < 16; i++) {
        __nv_bfloat16 hi, lo;
        split1(acc[i], hi, lo);
        g_Aophi[(n0+i)*HH + k] = hi;
        g_Aoplo[(n0+i)*HH + k] = lo;
    }
}

// ============== transpose+split: mem3 (t,h,b) -> Xhi/Xlo (m=t*BB+b, k=h) =====
__global__ __launch_bounds__(256) void xpose_kernel() {
    __shared__ float smt[32][129];
    int t = blockIdx.x, h0 = blockIdx.y*32;
    int tid = threadIdx.x;
    int b = tid & 127, hq = tid >> 7;   // 0..1
    #pragma unroll
    for (int i = 0; i < 16; i++) {
        int hh2 = hq*16 + i;
        smt[hh2][b] = g_bufB[((size_t)t*HH + h0 + hh2)*BB + b];
    }
    __syncthreads();
    int b2 = tid & 127, half = tid >> 7;
    __nv_bfloat16 hi16[16], lo16[16];
    #pragma unroll
    for (int i = 0; i < 16; i++)
        split1(smt[half*16 + i][b2], hi16[i], lo16[i]);
    size_t base = ((size_t)t*BB + b2)*HH + h0 + half*16;
    *(uint4*)&g_Xhi[base]     = *(uint4*)&hi16[0];
    *(uint4*)&g_Xhi[base + 8] = *(uint4*)&hi16[8];
    *(uint4*)&g_Xlo[base]     = *(uint4*)&lo16[0];
    *(uint4*)&g_Xlo[base + 8] = *(uint4*)&lo16[8];
}

// ============== c1[m]=X_m.u, c2[m]=X_m.w2 ==============
__global__ __launch_bounds__(128) void c12_kernel() {
    __shared__ float su[HH], sw[HH];
    int t = blockIdx.x, tid = threadIdx.x;
    for (int i = tid; i < HH; i += 128) { su[i] = g_u[i]; sw[i] = g_w2[i]; }
    __syncthreads();
    float c1 = 0.f, c2 = 0.f;
    const float* src = g_bufB + (size_t)t*HH*BB + tid;
    #pragma unroll 4
    for (int h = 0; h < HH; h++) {
        float v = src[(size_t)h*BB];
        c1 += v * su[h];
        c2 += v * sw[h];
    }
    g_c1[t*BB + tid] = c1;
    g_c2[t*BB + tid] = c2;
}

// ============== wmma GEMM core (pre-split bf16 operands) ==============
#define BK   32
#define LDA  40
#define LDS  132
#define SM_DYN (128*LDS*4)   // 67584 B

typedef wmma::fragment<wmma::matrix_a, 16,16,16, __nv_bfloat16, wmma::row_major> FragA;
typedef wmma::fragment<wmma::matrix_b, 16,16,16, __nv_bfloat16, wmma::col_major> FragB;
typedef wmma::fragment<wmma::accumulator, 16,16,16, float> FragC;

__device__ __forceinline__ void mma_tile_bf16(
        const __nv_bfloat16* __restrict__ Ahi, const __nv_bfloat16* __restrict__ Alo, size_t sA,
        const __nv_bfloat16* __restrict__ Bhi, const __nv_bfloat16* __restrict__ Blo, size_t sB,
        char* sm, float* stage) {
    __nv_bfloat16* sAhi = (__nv_bfloat16*)sm;
    __nv_bfloat16* sAlo = sAhi + 128*LDA;
    __nv_bfloat16* sBhi = sAlo + 128*LDA;
    __nv_bfloat16* sBlo = sBhi + 128*LDA;

    int tid = threadIdx.x, wid = tid >> 5;
    int r = tid >> 1, half = tid & 1;
    int wm = (wid & 1) * 64;
    int wn = (wid >> 1) * 32;

    FragC acc[4][2];
    #pragma unroll
    for (int i = 0; i < 4; i++)
        #pragma unroll
        for (int j = 0; j < 2; j++)
            wmma::fill_fragment(acc[i][j], 0.0f);

    for (int k0 = 0; k0 < HH; k0 += BK) {
        size_t go = (size_t)r*sA + k0 + half*16;
        int so = r*LDA + half*16;
        *(uint4*)(sAhi + so)     = *(const uint4*)(Ahi + go);
        *(uint4*)(sAhi + so + 8) = *(const uint4*)(Ahi + go + 8);
        *(uint4*)(sAlo + so)     = *(const uint4*)(Alo + go);
        *(uint4*)(sAlo + so + 8) = *(const uint4*)(Alo + go + 8);
        size_t gb = (size_t)r*sB + k0 + half*16;
        *(uint4*)(sBhi + so)     = *(const uint4*)(Bhi + gb);
        *(uint4*)(sBhi + so + 8) = *(const uint4*)(Bhi + gb + 8);
        *(uint4*)(sBlo + so)     = *(const uint4*)(Blo + gb);
        *(uint4*)(sBlo + so + 8) = *(const uint4*)(Blo + gb + 8);
        __syncthreads();
        #pragma unroll
        for (int kk = 0; kk < BK; kk += 16) {
            FragA ah[4], al[4];
            #pragma unroll
            for (int i = 0; i < 4; i++) {
                wmma::load_matrix_sync(ah[i], sAhi + (wm + i*16)*LDA + kk, LDA);
                wmma::load_matrix_sync(al[i], sAlo + (wm + i*16)*LDA + kk, LDA);
            }
            #pragma unroll
            for (int j = 0; j < 2; j++) {
                FragB bh, bl;
                wmma::load_matrix_sync(bh, sBhi + (wn + j*16)*LDA + kk, LDA);
                wmma::load_matrix_sync(bl, sBlo + (wn + j*16)*LDA + kk, LDA);
                #pragma unroll
                for (int i = 0; i < 4; i++) {
                    wmma::mma_sync(acc[i][j], ah[i], bh, acc[i][j]);
                    wmma::mma_sync(acc[i][j], ah[i], bl, acc[i][j]);
                    wmma::mma_sync(acc[i][j], al[i], bh, acc[i][j]);
                }
            }
        }
        __syncthreads();
    }
    #pragma unroll
    for (int i = 0; i < 4; i++)
        #pragma unroll
        for (int j = 0; j < 2; j++)
            wmma::store_matrix_sync(stage + (wm + i*16)*LDS + wn + j*16,
                                    acc[i][j], LDS, wmma::mem_row_major);
    __syncthreads();
}

// ============== xw: sel0 -> V = X Wv^T + bv (fp32); sel1 -> Y = X Aop^T (bf16)
__global__ __launch_bounds__(256) void xw_mma_kernel(const float* __restrict__ bv) {
    extern __shared__ char sm[];
    float* stage = (float*)sm;
    int bx = blockIdx.x;
    int ntile = bx & 3, sel = bx >> 2;
    int n0 = ntile*128, m0 = blockIdx.y*128;

    const __nv_bfloat16* Bhi = sel ? g_Aophi : g_Wvhi;
    const __nv_bfloat16* Blo = sel ? g_Aoplo : g_Wvlo;

    mma_tile_bf16(g_Xhi + (size_t)m0*HH, g_Xlo + (size_t)m0*HH, HH,
                  Bhi + (size_t)n0*HH,   Blo + (size_t)n0*HH,   HH, sm, stage);

    int tid = threadIdx.x;
    int c = tid & 127, rr = tid >> 7;
    if (sel == 0) {
        float bs = bv[n0 + c];
        for (int r2 = rr; r2 < 128; r2 += 2)
            g_V[(size_t)(m0 + r2)*HH + n0 + c] = stage[r2*LDS + c] + bs;
    } else {
        for (int r2 = rr; r2 < 128; r2 += 2) {
            __nv_bfloat16 hi, lo;
            split1(stage[r2*LDS + c], hi, lo);
            g_Yhi[(size_t)(m0 + r2)*HH + n0 + c] = hi;
            g_Ylo[(size_t)(m0 + r2)*HH + n0 + c] = lo;
        }
    }
}

// ============== attention: sigmoid((Y.X + c1 + c2 + c0)*s) column sums =======
__global__ __launch_bounds__(256) void attn_mma_kernel() {
    extern __shared__ char sm[];
    float* stage = (float*)sm;
    __shared__ float c1row[128];
    int b  = blockIdx.z;
    int n0 = blockIdx.x * 128;
    int m0 = blockIdx.y * 128;
    int tid = threadIdx.x;

    mma_tile_bf16(g_Yhi + ((size_t)m0*BB + b)*HH, g_Ylo + ((size_t)m0*BB + b)*HH, (size_t)BB*HH,
                  g_Xhi + ((size_t)n0*BB + b)*HH, g_Xlo + ((size_t)n0*BB + b)*HH, (size_t)BB*HH,
                  sm, stage);

    if (tid < 128) c1row[tid] = g_c1[(size_t)(m0 + tid)*BB + b];
    __syncthreads();

    const float scale = 0.04419417382415922f;  // 512^-0.5
    if (tid < 128) {
        float c2v = g_c2[(size_t)(n0 + tid)*BB + b] + g_cc[0];
        float s = 0.f;
        #pragma unroll 4
        for (int rr = 0; rr < 128; rr++) {
            float lg = (stage[rr*LDS + tid] + c1row[rr] + c2v) * scale;
            s += 1.0f / (1.0f + __expf(-lg));
        }
        g_wpart[blockIdx.y*(BB*TT) + b*TT + n0 + tid] = s;
    }
}

// ============== tail kernels (unchanged) ==============
__global__ void reduce_w_kernel() {
    int i = blockIdx.x*256 + threadIdx.x;
    g_wsum[i] = g_wpart[i] + g_wpart[BB*TT + i]
              + g_wpart[2*BB*TT + i] + g_wpart[3*BB*TT + i];
}

__global__ void feat_v_kernel() {
    int b = blockIdx.y;
    int d = blockIdx.x*128 + threadIdx.x;
    float acc = 0.f;
    #pragma unroll 4
    for (int s = 0; s < TT; s++)
        acc += g_wsum[b*TT + s] * g_V[((size_t)s*BB + b)*HH + d];
    g_feat[b*HH + d] = acc * (1.0f/TT);
}

__global__ void feat_bn_kernel(const float* __restrict__ g,
                               const float* __restrict__ bb) {
    int d = threadIdx.x;
    float s = 0.f, sq = 0.f;
    for (int b = 0; b < BB; b++) {
        float v = g_feat[b*HH + d];
        s += v; sq += v*v;
    }
    float m = s * (1.0f/BB);
    float rstd = rsqrtf(sq*(1.0f/BB) - m*m + 1e-5f);
    float gg = g[d]*rstd;
    float bo = bb[d] - m*gg;
    for (int b = 0; b < BB; b++)
        g_featn[b*HH + d] = g_feat[b*HH + d]*gg + bo;
}

__global__ void final_lin_kernel(const float* __restrict__ wh,
                                 const float* __restrict__ bh,
                                 float* __restrict__ out) {
    __shared__ float fs[HH];
    int b = blockIdx.x;
    int o = threadIdx.x;
    for (int i = o; i < HH; i += 96) fs[i] = g_featn[b*HH + i];
    __syncthreads();
    float acc = bh[o];
    for (int d = 0; d < HH; d++) acc += fs[d] * wh[o*HH + d];
    out[b*HORZ + o] = acc;
}

// ---------------- launch ------------------------------------------------------
extern "C" void kernel_launch(void* const* d_in, const int* in_sizes, int n_in,
                              void* d_out, int out_size) {
    const float* x        = (const float*)d_in[0];
    const float* conv_w   = (const float*)d_in[1];
    const float* conv_b   = (const float*)d_in[2];
    const float* bn1_g    = (const float*)d_in[3];
    const float* bn1_b    = (const float*)d_in[4];
    const float* beta_enc = (const float*)d_in[5];
    const float* bn2_g    = (const float*)d_in[6];
    const float* bn2_b    = (const float*)d_in[7];
    const float* beta2    = (const float*)d_in[8];
    const float* bn3_g    = (const float*)d_in[9];
    const float* bn3_b    = (const float*)d_in[10];
    const float* beta3    = (const float*)d_in[11];
    const float* wq       = (const float*)d_in[12];
    const float* bq       = (const float*)d_in[13];
    const float* wk       = (const float*)d_in[14];
    const float* bk       = (const float*)d_in[15];
    const float* wv       = (const float*)d_in[16];
    const float* bv       = (const float*)d_in[17];
    const float* bna_g    = (const float*)d_in[18];
    const float* bna_b    = (const float*)d_in[19];
    const float* wh       = (const float*)d_in[20];
    const float* bh       = (const float*)d_in[21];
    float* out = (float*)d_out;

    cudaFuncSetAttribute(xw_mma_kernel,   cudaFuncAttributeMaxDynamicSharedMemorySize, SM_DYN);
    cudaFuncSetAttribute(attn_mma_kernel, cudaFuncAttributeMaxDynamicSharedMemorySize, SM_DYN);

    // cheap weight-side prep (independent of activations)
    prep_uwc_kernel<<<4, 128>>>(wq, bk, wk, bq);
    wv_split_kernel<<<HH, 128>>>(wv);
    aop_kernel<<<dim3(4, 32), 128>>>(wq, wk);

    conv_kernel<<<dim3(NCHN/8, BB), 128>>>(x, conv_w, conv_b);
    chan_stats_kernel<<<NCHN, 256>>>();
    bn1t_kernel<<<dim3(NCHN, 4), 128>>>(bn1_g, bn1_b);

    snn_fused_kernel<<<HH, 128>>>(beta_enc, bn2_g, bn2_b, beta2, bn3_g, bn3_b, beta3);

    xpose_kernel<<<dim3(TT, 16), 256>>>();
    c12_kernel<<<TT, 128>>>();

    xw_mma_kernel<<<dim3(8, TT), 256, SM_DYN>>>(bv);
    attn_mma_kernel<<<dim3(TT/128, TT/128, BB), 256, SM_DYN>>>();

    reduce_w_kernel<<<(BB*TT)/256, 256>>>();
    feat_v_kernel<<<dim3(HH/128, BB), 128>>>();
    feat_bn_kernel<<<1, HH>>>(bna_g, bna_b);
    final_lin_kernel<<<BB, HORZ>>>(wh, bh, out);
}

// round 7
// speedup vs baseline: 1.4244x; 1.4244x over previous
#include <cuda_runtime.h>
#include <cuda_bf16.h>
#include <mma.h>
#include <stdint.h>
#include <math.h>

using namespace nvcuda;

#define TT   512
#define BB   128
#define HH   512
#define CC   32
#define TIN  128
#define NCHN 2048
#define HORZ 96
#define NELEM (TT*BB*HH)

// ---------------- scratch ----------------
__device__ float g_conv[BB*NCHN*TIN];   // (B, 2048, Tin)
__device__ float g_bufA[NELEM];         // X after bn1: (tau, h, b)
__device__ float g_bufB[NELEM];         // mem3:        (tau, h, b)
__device__ float g_Q[NELEM];            // (m = t*BB+b, n)
__device__ float g_K[NELEM];
__device__ float g_V[NELEM];
__device__ float g_wpart[4*BB*TT];
__device__ float g_wsum[BB*TT];
__device__ float g_feat[BB*HH];
__device__ float g_featn[BB*HH];
__device__ float g_chm[NCHN];
__device__ float g_chr[NCHN];

__device__ __forceinline__ void split2(float x, float y, uint32_t& hi, uint32_t& lo) {
    __nv_bfloat16 hx = __float2bfloat16(x), hy = __float2bfloat16(y);
    __nv_bfloat16 lx = __float2bfloat16(x - __bfloat162float(hx));
    __nv_bfloat16 ly = __float2bfloat16(y - __bfloat162float(hy));
    __nv_bfloat162 h(hx, hy), l(lx, ly);
    hi = *(uint32_t*)&h; lo = *(uint32_t*)&l;
}

// ============== conv1d: issue-optimized, arithmetic identical to R1 ==========
// xs2[ci][col], col = t+1 maps x[t]; row stride 136 floats (16B aligned).
// ws4[cc][i] = float4(w0,w1,w2,0). Thread = (ccq 0..3) x (t4 0..31):
// computes channels ccq*2, ccq*2+1 at t = t4*4 .. t4*4+3.
__global__ __launch_bounds__(128) void conv_kernel(const float* __restrict__ x,
                            const float* __restrict__ w,
                            const float* __restrict__ cb) {
    __shared__ float xs2[32*136];
    __shared__ float ws4[8*32*4];
    int b  = blockIdx.y;
    int c0 = blockIdx.x * 8;
    int tid = threadIdx.x;

    // fill x transposed: xs2[ci*136 + r] = x[b, r-1, ci] (zero pad r=0,129)
    for (int i = tid; i < 130*32; i += 128) {
        int r = i >> 5, ci = i & 31;
        int tt = r - 1;
        xs2[ci*136 + r] = (tt >= 0 && tt < TIN) ? x[(b*TIN + tt)*CC + ci] : 0.0f;
    }
    // fill padded weights
    for (int i = tid; i < 256; i += 128) {
        int cc = i >> 5, ii = i & 31;
        const float* wp = w + (c0 + cc)*96 + ii*3;
        float* d = ws4 + i*4;
        d[0] = wp[0]; d[1] = wp[1]; d[2] = wp[2]; d[3] = 0.0f;
    }
    __syncthreads();

    int ccq = tid >> 5;          // 0..3
    int t4  = tid & 31;          // 0..31
    int t0  = t4 * 4;
    int cA = ccq*2, cB = ccq*2 + 1;

    float acc[2][4];
    acc[0][0] = acc[0][1] = acc[0][2] = acc[0][3] = cb[c0 + cA];
    acc[1][0] = acc[1][1] = acc[1][2] = acc[1][3] = cb[c0 + cB];

    #pragma unroll
    for (int i = 0; i < 32; i++) {
        float4 xa = *(const float4*)&xs2[i*136 + t0];      // x[t0-1..t0+2]
        float2 xb = *(const float2*)&xs2[i*136 + t0 + 4];  // x[t0+3..t0+4]
        #pragma unroll
        for (int c2 = 0; c2 < 2; c2++) {
            float4 wv = *(const float4*)&ws4[((ccq*2 + c2)*32 + i)*4];
            acc[c2][0] += wv.x*xa.x + wv.y*xa.y + wv.z*xa.z;
            acc[c2][1] += wv.x*xa.y + wv.y*xa.z + wv.z*xa.w;
            acc[c2][2] += wv.x*xa.z + wv.y*xa.w + wv.z*xb.x;
            acc[c2][3] += wv.x*xa.w + wv.y*xb.x + wv.z*xb.y;
        }
    }
    *(float4*)&g_conv[((size_t)b*NCHN + c0 + cA)*TIN + t0] =
        make_float4(acc[0][0], acc[0][1], acc[0][2], acc[0][3]);
    *(float4*)&g_conv[((size_t)b*NCHN + c0 + cB)*TIN + t0] =
        make_float4(acc[1][0], acc[1][1], acc[1][2], acc[1][3]);
}

__global__ void chan_stats_kernel() {
    int c = blockIdx.x;
    int tid = threadIdx.x;
    float s = 0.f, sq = 0.f;
    for (int i = tid; i < BB*TIN; i += 256) {
        int b = i >> 7, t = i & 127;
        float v = g_conv[(b*NCHN + c)*TIN + t];
        s += v; sq += v*v;
    }
    __shared__ float ss[256], sqs[256];
    ss[tid] = s; sqs[tid] = sq;
    __syncthreads();
    for (int o = 128; o > 0; o >>= 1) {
        if (tid < o) { ss[tid] += ss[tid+o]; sqs[tid] += sqs[tid+o]; }
        __syncthreads();
    }
    if (tid == 0) {
        float m   = ss[0] * (1.0f/(BB*TIN));
        float var = sqs[0] * (1.0f/(BB*TIN)) - m*m;
        g_chm[c] = m;
        g_chr[c] = rsqrtf(var + 1e-5f);
    }
}

// ============== BN1 apply + transpose -> (tau, h, b) ==============
__global__ void bn1t_kernel(const float* __restrict__ g,
                            const float* __restrict__ bb) {
    __shared__ float sm_t[128*33];
    int c = blockIdx.x, bq = blockIdx.y;
    int ts = c >> 9, h = c & 511;
    int tid = threadIdx.x;
    float chm = g_chm[c], chr = g_chr[c], gg = g[c], bo = bb[c];
    int bl = tid >> 2, tq = tid & 3;
    int b = bq*32 + bl;
    const float* src = g_conv + ((size_t)b*NCHN + c)*TIN;
    #pragma unroll
    for (int it = 0; it < 8; it++) {
        int tbase = (tq + it*4)*4;
        float4 v = *(const float4*)(src + tbase);
        sm_t[(tbase+0)*33 + bl] = (v.x - chm) * chr * gg + bo;
        sm_t[(tbase+1)*33 + bl] = (v.y - chm) * chr * gg + bo;
        sm_t[(tbase+2)*33 + bl] = (v.z - chm) * chr * gg + bo;
        sm_t[(tbase+3)*33 + bl] = (v.w - chm) * chr * gg + bo;
    }
    __syncthreads();
    int bl2 = tid & 31, tch = tid >> 5;
    #pragma unroll 8
    for (int it = 0; it < 32; it++) {
        int t = tch*32 + it;
        g_bufA[((size_t)(t*4 + ts)*HH + h)*BB + bq*32 + bl2] = sm_t[t*33 + bl2];
    }
}

// ============== fused lif1 -> bn2 -> lif2 -> bn3 -> lif3 ==============
__global__ __launch_bounds__(128) void snn_fused_kernel(
        const float* __restrict__ be,  const float* __restrict__ g2a,
        const float* __restrict__ b2a, const float* __restrict__ be2,
        const float* __restrict__ g3a, const float* __restrict__ b3a,
        const float* __restrict__ be3) {
    __shared__ int scnt[2][2][4];
    int tid = threadIdx.x;
    int h = blockIdx.x;
    int warp = tid >> 5, lane = tid & 31;
    float beta1 = fminf(fmaxf(be[h],  0.0f), 0.99f);
    float beta2 = fminf(fmaxf(be2[h], 0.0f), 0.99f);
    float beta3 = fminf(fmaxf(be3[h], 0.0f), 0.99f);
    float g2 = g2a[h], b2 = b2a[h], g3 = g3a[h], b3 = b3a[h];
    const float* src = g_bufA + (size_t)h*BB + tid;
    float* dst       = g_bufB + (size_t)h*BB + tid;
    float mem1 = 0.f, mem2 = 0.f, mem3 = 0.f;

    float cur[4];
    #pragma unroll
    for (int j = 0; j < 4; j++) cur[j] = src[(size_t)j*HH*BB];

    for (int t0 = 0; t0 < TT; t0 += 4) {
        float nxt[4] = {0.f, 0.f, 0.f, 0.f};
        if (t0 + 4 < TT) {
            #pragma unroll
            for (int j = 0; j < 4; j++) nxt[j] = src[(size_t)(t0+4+j)*HH*BB];
        }
        #pragma unroll
        for (int j = 0; j < 4; j++) {
            int t = t0 + j, par = t & 1;
            float reset = (mem1 > 1.0f) ? 1.0f : 0.0f;
            mem1 = beta1*mem1 + cur[j] - reset;
            float s1 = (mem1 > 1.0f) ? 1.0f : 0.0f;
            unsigned bal = __ballot_sync(0xffffffffu, mem1 > 1.0f);
            if (lane == 0) scnt[0][par][warp] = __popc(bal);
            __syncthreads();
            float sq = (float)(scnt[0][par][0] + scnt[0][par][1]
                             + scnt[0][par][2] + scnt[0][par][3]);
            float m    = sq * (1.0f/BB);
            float rstd = rsqrtf(sq*(1.0f/BB) - m*m + 1e-5f);
            float gg = g2*rstd;
            float bo = b2 - m*gg;
            float h2 = s1*gg + bo;

            float reset2 = (mem2 > 1.0f) ? 1.0f : 0.0f;
            mem2 = beta2*mem2 + h2 - reset2;
            float s2 = (mem2 > 1.0f) ? 1.0f : 0.0f;
            bal = __ballot_sync(0xffffffffu, mem2 > 1.0f);
            if (lane == 0) scnt[1][par][warp] = __popc(bal);
            __syncthreads();
            sq = (float)(scnt[1][par][0] + scnt[1][par][1]
                       + scnt[1][par][2] + scnt[1][par][3]);
            m    = sq * (1.0f/BB);
            rstd = rsqrtf(sq*(1.0f/BB) - m*m + 1e-5f);
            gg = g3*rstd;
            bo = b3 - m*gg;
            float h3 = s2*gg + bo;

            float reset3 = (mem3 > 1.0f) ? 1.0f : 0.0f;
            mem3 = beta3*mem3 + h3 - reset3;
            dst[(size_t)t*HH*BB] = mem3;
        }
        #pragma unroll
        for (int j = 0; j < 4; j++) cur[j] = nxt[j];
    }
}

// ============== wmma GEMM pieces (R5-identical) ==============
#define BK   32
#define LDA  40
#define LDAT 136
#define LDS  132
#define SM_DYN (128*LDS*4)   // 67584 B

__device__ __forceinline__ void load_split_tile(
        const float* __restrict__ src, size_t row_stride, int k0,
        __nv_bfloat16* sHi, __nv_bfloat16* sLo, int r, int half) {
    const float* p = src + (size_t)r*row_stride + k0 + half*16;
    uint32_t* dh = (uint32_t*)(sHi + r*LDA + half*16);
    uint32_t* dl = (uint32_t*)(sLo + r*LDA + half*16);
    #pragma unroll
    for (int i = 0; i < 4; i++) {
        float4 v = *(const float4*)(p + i*4);
        uint32_t h0, l0, h1, l1;
        split2(v.x, v.y, h0, l0); split2(v.z, v.w, h1, l1);
        dh[i*2] = h0; dh[i*2+1] = h1;
        dl[i*2] = l0; dl[i*2+1] = l1;
    }
}

typedef wmma::fragment<wmma::matrix_a, 16,16,16, __nv_bfloat16, wmma::row_major> FragA;
typedef wmma::fragment<wmma::matrix_a, 16,16,16, __nv_bfloat16, wmma::col_major> FragAc;
typedef wmma::fragment<wmma::matrix_b, 16,16,16, __nv_bfloat16, wmma::col_major> FragB;
typedef wmma::fragment<wmma::accumulator, 16,16,16, float> FragC;

// ============== QKV: C(sel) = mem3 @ W^T + bias ==============
__global__ __launch_bounds__(256) void qkv_mma_kernel(
        const float* __restrict__ Wq, const float* __restrict__ bq,
        const float* __restrict__ Wk, const float* __restrict__ bk,
        const float* __restrict__ Wv, const float* __restrict__ bv) {
    extern __shared__ char sm[];
    __nv_bfloat16* sAhi = (__nv_bfloat16*)sm;          // 32 x LDAT
    __nv_bfloat16* sAlo = sAhi + 32*LDAT;
    __nv_bfloat16* sBhi = sAlo + 32*LDAT;              // 128 x LDA
    __nv_bfloat16* sBlo = sBhi + 128*LDA;
    float* stage = (float*)sm;

    int bx = blockIdx.x;
    int ntile = bx & 3, sel = bx >> 2;
    int t = blockIdx.y;
    int n0 = ntile*128, m0 = t*128;
    const float* W    = (sel == 0) ? Wq : (sel == 1) ? Wk : Wv;
    const float* bias = (sel == 0) ? bq : (sel == 1) ? bk : bv;
    float* C          = (sel == 0) ? g_Q : (sel == 1) ? g_K : g_V;

    int tid = threadIdx.x, wid = tid >> 5;
    int wm = (wid & 1) * 64, wn = (wid >> 1) * 32;

    FragC acc[4][2];
    #pragma unroll
    for (int i = 0; i < 4; i++)
        #pragma unroll
        for (int j = 0; j < 2; j++)
            wmma::fill_fragment(acc[i][j], 0.0f);

    for (int k0 = 0; k0 < HH; k0 += BK) {
        {
            int k = tid >> 3;
            int bo_ = (tid & 7) * 4;
            const float* ap = g_bufB + ((size_t)t*HH + k0 + k)*BB;
            #pragma unroll
            for (int it = 0; it < 4; it++) {
                int bpos = bo_ + it*32;
                float4 v = *(const float4*)(ap + bpos);
                uint32_t h0, l0, h1, l1;
                split2(v.x, v.y, h0, l0); split2(v.z, v.w, h1, l1);
                *(uint32_t*)(sAhi + k*LDAT + bpos)     = h0;
                *(uint32_t*)(sAhi + k*LDAT + bpos + 2) = h1;
                *(uint32_t*)(sAlo + k*LDAT + bpos)     = l0;
                *(uint32_t*)(sAlo + k*LDAT + bpos + 2) = l1;
            }
        }
        load_split_tile(W + (size_t)n0*HH, HH, k0, sBhi, sBlo, tid >> 1, tid & 1);
        __syncthreads();
        #pragma unroll
        for (int kk = 0; kk < BK; kk += 16) {
            FragAc ah[4], al[4];
            #pragma unroll
            for (int i = 0; i < 4; i++) {
                wmma::load_matrix_sync(ah[i], sAhi + kk*LDAT + wm + i*16, LDAT);
                wmma::load_matrix_sync(al[i], sAlo + kk*LDAT + wm + i*16, LDAT);
            }
            #pragma unroll
            for (int j = 0; j < 2; j++) {
                FragB bh, bl;
                wmma::load_matrix_sync(bh, sBhi + (wn + j*16)*LDA + kk, LDA);
                wmma::load_matrix_sync(bl, sBlo + (wn + j*16)*LDA + kk, LDA);
                #pragma unroll
                for (int i = 0; i < 4; i++) {
                    wmma::mma_sync(acc[i][j], ah[i], bh, acc[i][j]);
                    wmma::mma_sync(acc[i][j], ah[i], bl, acc[i][j]);
                    wmma::mma_sync(acc[i][j], al[i], bh, acc[i][j]);
                }
            }
        }
        __syncthreads();
    }
    #pragma unroll
    for (int i = 0; i < 4; i++)
        #pragma unroll
        for (int j = 0; j < 2; j++)
            wmma::store_matrix_sync(stage + (wm + i*16)*LDS + wn + j*16,
                                    acc[i][j], LDS, wmma::mem_row_major);
    __syncthreads();

    int c = tid & 127, rr = tid >> 7;
    float bs = bias[n0 + c];
    for (int r2 = rr; r2 < 128; r2 += 2)
        C[(size_t)(m0 + r2)*HH + n0 + c] = stage[r2*LDS + c] + bs;
}

// ============== attention: sigmoid(QK^T * s) column sums ==============
__device__ __forceinline__ void mma_tile_128(
        const float* baseA, size_t strideA,
        const float* baseB, size_t strideB,
        char* sm, float* stage) {
    __nv_bfloat16* sAhi = (__nv_bfloat16*)sm;
    __nv_bfloat16* sAlo = sAhi + 128*LDA;
    __nv_bfloat16* sBhi = sAlo + 128*LDA;
    __nv_bfloat16* sBlo = sBhi + 128*LDA;

    int tid = threadIdx.x, wid = tid >> 5;
    int r = tid >> 1, half = tid & 1;
    int wm = (wid & 1) * 64;
    int wn = (wid >> 1) * 32;

    FragC acc[4][2];
    #pragma unroll
    for (int i = 0; i < 4; i++)
        #pragma unroll
        for (int j = 0; j < 2; j++)
            wmma::fill_fragment(acc[i][j], 0.0f);

    for (int k0 = 0; k0 < HH; k0 += BK) {
        load_split_tile(baseA, strideA, k0, sAhi, sAlo, r, half);
        load_split_tile(baseB, strideB, k0, sBhi, sBlo, r, half);
        __syncthreads();
        #pragma unroll
        for (int kk = 0; kk < BK; kk += 16) {
            FragA ah[4], al[4];
            #pragma unroll
            for (int i = 0; i < 4; i++) {
                wmma::load_matrix_sync(ah[i], sAhi + (wm + i*16)*LDA + kk, LDA);
                wmma::load_matrix_sync(al[i], sAlo + (wm + i*16)*LDA + kk, LDA);
            }
            #pragma unroll
            for (int j = 0; j < 2; j++) {
                FragB bh, bl;
                wmma::load_matrix_sync(bh, sBhi + (wn + j*16)*LDA + kk, LDA);
                wmma::load_matrix_sync(bl, sBlo + (wn + j*16)*LDA + kk, LDA);
                #pragma unroll
                for (int i = 0; i < 4; i++) {
                    wmma::mma_sync(acc[i][j], ah[i], bh, acc[i][j]);
                    wmma::mma_sync(acc[i][j], ah[i], bl, acc[i][j]);
                    wmma::mma_sync(acc[i][j], al[i], bh, acc[i][j]);
                }
            }
        }
        __syncthreads();
    }
    #pragma unroll
    for (int i = 0; i < 4; i++)
        #pragma unroll
        for (int j = 0; j < 2; j++)
            wmma::store_matrix_sync(stage + (wm + i*16)*LDS + wn + j*16,
                                    acc[i][j], LDS, wmma::mem_row_major);
    __syncthreads();
}

__global__ __launch_bounds__(256) void attn_mma_kernel() {
    extern __shared__ char sm[];
    float* stage = (float*)sm;
    int b  = blockIdx.z;
    int n0 = blockIdx.x * 128;
    int m0 = blockIdx.y * 128;

    mma_tile_128(g_Q + ((size_t)m0*BB + b)*HH, (size_t)BB*HH,
                 g_K + ((size_t)n0*BB + b)*HH, (size_t)BB*HH, sm, stage);

    const float scale = 0.04419417382415922f;  // 512^-0.5
    int tid = threadIdx.x;
    if (tid < 128) {
        float s = 0.f;
        #pragma unroll 4
        for (int rr = 0; rr < 128; rr++) {
            float v = stage[rr*LDS + tid];
            s += 1.0f / (1.0f + __expf(-v*scale));
        }
        g_wpart[blockIdx.y*(BB*TT) + b*TT + n0 + tid] = s;
    }
}

// ============== tail kernels (unchanged) ==============
__global__ void reduce_w_kernel() {
    int i = blockIdx.x*256 + threadIdx.x;
    g_wsum[i] = g_wpart[i] + g_wpart[BB*TT + i]
              + g_wpart[2*BB*TT + i] + g_wpart[3*BB*TT + i];
}

__global__ void feat_v_kernel() {
    int b = blockIdx.y;
    int d = blockIdx.x*128 + threadIdx.x;
    float acc = 0.f;
    #pragma unroll 4
    for (int s = 0; s < TT; s++)
        acc += g_wsum[b*TT + s] * g_V[((size_t)s*BB + b)*HH + d];
    g_feat[b*HH + d] = acc * (1.0f/TT);
}

__global__ void feat_bn_kernel(const float* __restrict__ g,
                               const float* __restrict__ bb) {
    int d = threadIdx.x;
    float s = 0.f, sq = 0.f;
    for (int b = 0; b < BB; b++) {
        float v = g_feat[b*HH + d];
        s += v; sq += v*v;
    }
    float m = s * (1.0f/BB);
    float rstd = rsqrtf(sq*(1.0f/BB) - m*m + 1e-5f);
    float gg = g[d]*rstd;
    float bo = bb[d] - m*gg;
    for (int b = 0; b < BB; b++)
        g_featn[b*HH + d] = g_feat[b*HH + d]*gg + bo;
}

__global__ void final_lin_kernel(const float* __restrict__ wh,
                                 const float* __restrict__ bh,
                                 float* __restrict__ out) {
    __shared__ float fs[HH];
    int b = blockIdx.x;
    int o = threadIdx.x;
    for (int i = o; i < HH; i += 96) fs[i] = g_featn[b*HH + i];
    __syncthreads();
    float acc = bh[o];
    for (int d = 0; d < HH; d++) acc += fs[d] * wh[o*HH + d];
    out[b*HORZ + o] = acc;
}

// ---------------- launch ------------------------------------------------------
extern "C" void kernel_launch(void* const* d_in, const int* in_sizes, int n_in,
                              void* d_out, int out_size) {
    const float* x        = (const float*)d_in[0];
    const float* conv_w   = (const float*)d_in[1];
    const float* conv_b   = (const float*)d_in[2];
    const float* bn1_g    = (const float*)d_in[3];
    const float* bn1_b    = (const float*)d_in[4];
    const float* beta_enc = (const float*)d_in[5];
    const float* bn2_g    = (const float*)d_in[6];
    const float* bn2_b    = (const float*)d_in[7];
    const float* beta2    = (const float*)d_in[8];
    const float* bn3_g    = (const float*)d_in[9];
    const float* bn3_b    = (const float*)d_in[10];
    const float* beta3    = (const float*)d_in[11];
    const float* wq       = (const float*)d_in[12];
    const float* bq       = (const float*)d_in[13];
    const float* wk       = (const float*)d_in[14];
    const float* bk       = (const float*)d_in[15];
    const float* wv       = (const float*)d_in[16];
    const float* bv       = (const float*)d_in[17];
    const float* bna_g    = (const float*)d_in[18];
    const float* bna_b    = (const float*)d_in[19];
    const float* wh       = (const float*)d_in[20];
    const float* bh       = (const float*)d_in[21];
    float* out = (float*)d_out;

    cudaFuncSetAttribute(qkv_mma_kernel,  cudaFuncAttributeMaxDynamicSharedMemorySize, SM_DYN);
    cudaFuncSetAttribute(attn_mma_kernel, cudaFuncAttributeMaxDynamicSharedMemorySize, SM_DYN);

    conv_kernel<<<dim3(NCHN/8, BB), 128>>>(x, conv_w, conv_b);
    chan_stats_kernel<<<NCHN, 256>>>();
    bn1t_kernel<<<dim3(NCHN, 4), 128>>>(bn1_g, bn1_b);

    snn_fused_kernel<<<HH, 128>>>(beta_enc, bn2_g, bn2_b, beta2, bn3_g, bn3_b, beta3);

    qkv_mma_kernel<<<dim3(12, TT), 256, SM_DYN>>>(wq, bq, wk, bk, wv, bv);
    attn_mma_kernel<<<dim3(TT/128, TT/128, BB), 256, SM_DYN>>>();

    reduce_w_kernel<<<(BB*TT)/256, 256>>>();
    feat_v_kernel<<<dim3(HH/128, BB), 128>>>();
    feat_bn_kernel<<<1, HH>>>(bna_g, bna_b);
    final_lin_kernel<<<BB, HORZ>>>(wh, bh, out);
}

// round 8
// speedup vs baseline: 1.4457x; 1.0150x over previous
#include <cuda_runtime.h>
#include <cuda_bf16.h>
#include <mma.h>
#include <stdint.h>
#include <math.h>

using namespace nvcuda;

#define TT   512
#define BB   128
#define HH   512
#define CC   32
#define TIN  128
#define NCHN 2048
#define HORZ 96
#define NELEM (TT*BB*HH)

// ---------------- scratch ----------------
__device__ float g_conv[BB*NCHN*TIN];   // (B, 2048, Tin)
__device__ float g_bufA[NELEM];         // X after bn1: (tau, h, b)
__device__ float g_bufB[NELEM];         // mem3:        (tau, h, b)
__device__ float g_Q[NELEM];            // Y = X @ Aop^T   (m = t*BB+b, n)
__device__ float g_K[NELEM];            // Xt = mem3 in (m, k)
__device__ float g_V[NELEM];            // V = X @ Wv^T + bv (m, n)
__device__ float g_Aop[HH*HH];
__device__ float g_u[HH], g_w2[HH], g_cc[1];
__device__ float g_c1[TT*BB], g_c2[TT*BB];
__device__ float g_wpart[4*BB*TT];
__device__ float g_wsum[BB*TT];
__device__ float g_feat[BB*HH];
__device__ float g_featn[BB*HH];
__device__ float g_chm[NCHN];
__device__ float g_chr[NCHN];

__device__ __forceinline__ void split2(float x, float y, uint32_t& hi, uint32_t& lo) {
    __nv_bfloat16 hx = __float2bfloat16(x), hy = __float2bfloat16(y);
    __nv_bfloat16 lx = __float2bfloat16(x - __bfloat162float(hx));
    __nv_bfloat16 ly = __float2bfloat16(y - __bfloat162float(hy));
    __nv_bfloat162 h(hx, hy), l(lx, ly);
    hi = *(uint32_t*)&h; lo = *(uint32_t*)&l;
}

// ============== conv / chan_stats / bn1t / snn_fused (R7-identical) =========
__global__ __launch_bounds__(128) void conv_kernel(const float* __restrict__ x,
                            const float* __restrict__ w,
                            const float* __restrict__ cb) {
    __shared__ float xs2[32*136];
    __shared__ float ws4[8*32*4];
    int b  = blockIdx.y;
    int c0 = blockIdx.x * 8;
    int tid = threadIdx.x;

    for (int i = tid; i < 130*32; i += 128) {
        int r = i >> 5, ci = i & 31;
        int tt = r - 1;
        xs2[ci*136 + r] = (tt >= 0 && tt < TIN) ? x[(b*TIN + tt)*CC + ci] : 0.0f;
    }
    for (int i = tid; i < 256; i += 128) {
        int cc = i >> 5, ii = i & 31;
        const float* wp = w + (c0 + cc)*96 + ii*3;
        float* d = ws4 + i*4;
        d[0] = wp[0]; d[1] = wp[1]; d[2] = wp[2]; d[3] = 0.0f;
    }
    __syncthreads();

    int ccq = tid >> 5;
    int t4  = tid & 31;
    int t0  = t4 * 4;
    int cA = ccq*2, cB = ccq*2 + 1;

    float acc[2][4];
    acc[0][0] = acc[0][1] = acc[0][2] = acc[0][3] = cb[c0 + cA];
    acc[1][0] = acc[1][1] = acc[1][2] = acc[1][3] = cb[c0 + cB];

    #pragma unroll
    for (int i = 0; i < 32; i++) {
        float4 xa = *(const float4*)&xs2[i*136 + t0];
        float2 xb = *(const float2*)&xs2[i*136 + t0 + 4];
        #pragma unroll
        for (int c2 = 0; c2 < 2; c2++) {
            float4 wv = *(const float4*)&ws4[((ccq*2 + c2)*32 + i)*4];
            acc[c2][0] += wv.x*xa.x + wv.y*xa.y + wv.z*xa.z;
            acc[c2][1] += wv.x*xa.y + wv.y*xa.z + wv.z*xa.w;
            acc[c2][2] += wv.x*xa.z + wv.y*xa.w + wv.z*xb.x;
            acc[c2][3] += wv.x*xa.w + wv.y*xb.x + wv.z*xb.y;
        }
    }
    *(float4*)&g_conv[((size_t)b*NCHN + c0 + cA)*TIN + t0] =
        make_float4(acc[0][0], acc[0][1], acc[0][2], acc[0][3]);
    *(float4*)&g_conv[((size_t)b*NCHN + c0 + cB)*TIN + t0] =
        make_float4(acc[1][0], acc[1][1], acc[1][2], acc[1][3]);
}

__global__ void chan_stats_kernel() {
    int c = blockIdx.x;
    int tid = threadIdx.x;
    float s = 0.f, sq = 0.f;
    for (int i = tid; i < BB*TIN; i += 256) {
        int b = i >> 7, t = i & 127;
        float v = g_conv[(b*NCHN + c)*TIN + t];
        s += v; sq += v*v;
    }
    __shared__ float ss[256], sqs[256];
    ss[tid] = s; sqs[tid] = sq;
    __syncthreads();
    for (int o = 128; o > 0; o >>= 1) {
        if (tid < o) { ss[tid] += ss[tid+o]; sqs[tid] += sqs[tid+o]; }
        __syncthreads();
    }
    if (tid == 0) {
        float m   = ss[0] * (1.0f/(BB*TIN));
        float var = sqs[0] * (1.0f/(BB*TIN)) - m*m;
        g_chm[c] = m;
        g_chr[c] = rsqrtf(var + 1e-5f);
    }
}

__global__ void bn1t_kernel(const float* __restrict__ g,
                            const float* __restrict__ bb) {
    __shared__ float sm_t[128*33];
    int c = blockIdx.x, bq = blockIdx.y;
    int ts = c >> 9, h = c & 511;
    int tid = threadIdx.x;
    float chm = g_chm[c], chr = g_chr[c], gg = g[c], bo = bb[c];
    int bl = tid >> 2, tq = tid & 3;
    int b = bq*32 + bl;
    const float* src = g_conv + ((size_t)b*NCHN + c)*TIN;
    #pragma unroll
    for (int it = 0; it < 8; it++) {
        int tbase = (tq + it*4)*4;
        float4 v = *(const float4*)(src + tbase);
        sm_t[(tbase+0)*33 + bl] = (v.x - chm) * chr * gg + bo;
        sm_t[(tbase+1)*33 + bl] = (v.y - chm) * chr * gg + bo;
        sm_t[(tbase+2)*33 + bl] = (v.z - chm) * chr * gg + bo;
        sm_t[(tbase+3)*33 + bl] = (v.w - chm) * chr * gg + bo;
    }
    __syncthreads();
    int bl2 = tid & 31, tch = tid >> 5;
    #pragma unroll 8
    for (int it = 0; it < 32; it++) {
        int t = tch*32 + it;
        g_bufA[((size_t)(t*4 + ts)*HH + h)*BB + bq*32 + bl2] = sm_t[t*33 + bl2];
    }
}

__global__ __launch_bounds__(128) void snn_fused_kernel(
        const float* __restrict__ be,  const float* __restrict__ g2a,
        const float* __restrict__ b2a, const float* __restrict__ be2,
        const float* __restrict__ g3a, const float* __restrict__ b3a,
        const float* __restrict__ be3) {
    __shared__ int scnt[2][2][4];
    int tid = threadIdx.x;
    int h = blockIdx.x;
    int warp = tid >> 5, lane = tid & 31;
    float beta1 = fminf(fmaxf(be[h],  0.0f), 0.99f);
    float beta2 = fminf(fmaxf(be2[h], 0.0f), 0.99f);
    float beta3 = fminf(fmaxf(be3[h], 0.0f), 0.99f);
    float g2 = g2a[h], b2 = b2a[h], g3 = g3a[h], b3 = b3a[h];
    const float* src = g_bufA + (size_t)h*BB + tid;
    float* dst       = g_bufB + (size_t)h*BB + tid;
    float mem1 = 0.f, mem2 = 0.f, mem3 = 0.f;

    float cur[4];
    #pragma unroll
    for (int j = 0; j < 4; j++) cur[j] = src[(size_t)j*HH*BB];

    for (int t0 = 0; t0 < TT; t0 += 4) {
        float nxt[4] = {0.f, 0.f, 0.f, 0.f};
        if (t0 + 4 < TT) {
            #pragma unroll
            for (int j = 0; j < 4; j++) nxt[j] = src[(size_t)(t0+4+j)*HH*BB];
        }
        #pragma unroll
        for (int j = 0; j < 4; j++) {
            int t = t0 + j, par = t & 1;
            float reset = (mem1 > 1.0f) ? 1.0f : 0.0f;
            mem1 = beta1*mem1 + cur[j] - reset;
            float s1 = (mem1 > 1.0f) ? 1.0f : 0.0f;
            unsigned bal = __ballot_sync(0xffffffffu, mem1 > 1.0f);
            if (lane == 0) scnt[0][par][warp] = __popc(bal);
            __syncthreads();
            float sq = (float)(scnt[0][par][0] + scnt[0][par][1]
                             + scnt[0][par][2] + scnt[0][par][3]);
            float m    = sq * (1.0f/BB);
            float rstd = rsqrtf(sq*(1.0f/BB) - m*m + 1e-5f);
            float gg = g2*rstd;
            float bo = b2 - m*gg;
            float h2 = s1*gg + bo;

            float reset2 = (mem2 > 1.0f) ? 1.0f : 0.0f;
            mem2 = beta2*mem2 + h2 - reset2;
            float s2 = (mem2 > 1.0f) ? 1.0f : 0.0f;
            bal = __ballot_sync(0xffffffffu, mem2 > 1.0f);
            if (lane == 0) scnt[1][par][warp] = __popc(bal);
            __syncthreads();
            sq = (float)(scnt[1][par][0] + scnt[1][par][1]
                       + scnt[1][par][2] + scnt[1][par][3]);
            m    = sq * (1.0f/BB);
            rstd = rsqrtf(sq*(1.0f/BB) - m*m + 1e-5f);
            gg = g3*rstd;
            bo = b3 - m*gg;
            float h3 = s2*gg + bo;

            float reset3 = (mem3 > 1.0f) ? 1.0f : 0.0f;
            mem3 = beta3*mem3 + h3 - reset3;
            dst[(size_t)t*HH*BB] = mem3;
        }
        #pragma unroll
        for (int j = 0; j < 4; j++) cur[j] = nxt[j];
    }
}

// ============== prep: u, w2, c0 (R6-verified) ==============
__global__ void prep_uwc_kernel(const float* __restrict__ wq,
                                const float* __restrict__ bk,
                                const float* __restrict__ wk,
                                const float* __restrict__ bq) {
    int k = blockIdx.x*128 + threadIdx.x;
    float su = 0.f, sw = 0.f;
    for (int n = 0; n < HH; n++) {
        su += wq[n*HH + k] * bk[n];
        sw += wk[n*HH + k] * bq[n];
    }
    g_u[k] = su; g_w2[k] = sw;
    if (blockIdx.x == 0 && threadIdx.x == 0) {
        float c = 0.f;
        for (int n = 0; n < HH; n++) c += bq[n]*bk[n];
        g_cc[0] = c;
    }
}

// ============== prep: Aop[n][k] = sum_j Wq[j][k]*Wk[j][n] (fp32) =============
__global__ void aop_kernel(const float* __restrict__ wq,
                           const float* __restrict__ wk) {
    int k  = blockIdx.x*128 + threadIdx.x;
    int n0 = blockIdx.y*16;
    float acc[16] = {};
    for (int j = 0; j < HH; j++) {
        float a = wq[j*HH + k];
        #pragma unroll
        for (int i = 0; i < 16; i++)
            acc[i] += a * wk[j*HH + n0 + i];
    }
    #pragma unroll
    for (int i = 0; i < 16; i++)
        g_Aop[(n0+i)*HH + k] = acc[i];
}

// ============== transpose fp32: mem3 (t,h,b) -> Xt (m=t*BB+b, k=h) ==========
__global__ __launch_bounds__(256) void xpose_kernel() {
    __shared__ float smt[32][129];
    int t = blockIdx.x, h0 = blockIdx.y*32;
    int tid = threadIdx.x;
    int b = tid & 127, hq = tid >> 7;   // 0..1
    #pragma unroll
    for (int i = 0; i < 16; i++) {
        int hh2 = hq*16 + i;
        smt[hh2][b] = g_bufB[((size_t)t*HH + h0 + hh2)*BB + b];
    }
    __syncthreads();
    int b2 = tid >> 1, half = tid & 1;
    float* dst = g_K + ((size_t)t*BB + b2)*HH + h0 + half*16;
    #pragma unroll
    for (int i = 0; i < 4; i++) {
        *(float4*)(dst + i*4) = make_float4(
            smt[half*16 + i*4 + 0][b2], smt[half*16 + i*4 + 1][b2],
            smt[half*16 + i*4 + 2][b2], smt[half*16 + i*4 + 3][b2]);
    }
}

// ============== c1[t,b]=X.u, c2[t,b]=X.w2 ==============
__global__ __launch_bounds__(128) void c12_kernel() {
    __shared__ float su[HH], sw[HH];
    int t = blockIdx.x, tid = threadIdx.x;
    for (int i = tid; i < HH; i += 128) { su[i] = g_u[i]; sw[i] = g_w2[i]; }
    __syncthreads();
    float c1 = 0.f, c2 = 0.f;
    const float* src = g_bufB + (size_t)t*HH*BB + tid;
    #pragma unroll 4
    for (int h = 0; h < HH; h++) {
        float v = src[(size_t)h*BB];
        c1 += v * su[h];
        c2 += v * sw[h];
    }
    g_c1[t*BB + tid] = c1;
    g_c2[t*BB + tid] = c2;
}

// ============== wmma GEMM pieces (R5/R7-identical mainloop) ==============
#define BK   32
#define LDA  40
#define LDAT 136
#define LDS  132
#define SM_DYN (128*LDS*4)   // 67584 B

__device__ __forceinline__ void load_split_tile(
        const float* __restrict__ src, size_t row_stride, int k0,
        __nv_bfloat16* sHi, __nv_bfloat16* sLo, int r, int half) {
    const float* p = src + (size_t)r*row_stride + k0 + half*16;
    uint32_t* dh = (uint32_t*)(sHi + r*LDA + half*16);
    uint32_t* dl = (uint32_t*)(sLo + r*LDA + half*16);
    #pragma unroll
    for (int i = 0; i < 4; i++) {
        float4 v = *(const float4*)(p + i*4);
        uint32_t h0, l0, h1, l1;
        split2(v.x, v.y, h0, l0); split2(v.z, v.w, h1, l1);
        dh[i*2] = h0; dh[i*2+1] = h1;
        dl[i*2] = l0; dl[i*2+1] = l1;
    }
}

typedef wmma::fragment<wmma::matrix_a, 16,16,16, __nv_bfloat16, wmma::row_major> FragA;
typedef wmma::fragment<wmma::matrix_a, 16,16,16, __nv_bfloat16, wmma::col_major> FragAc;
typedef wmma::fragment<wmma::matrix_b, 16,16,16, __nv_bfloat16, wmma::col_major> FragB;
typedef wmma::fragment<wmma::accumulator, 16,16,16, float> FragC;

// ============== VY: sel0 -> V = X Wv^T + bv;  sel1 -> Y = X Aop^T ============
__global__ __launch_bounds__(256) void vy_mma_kernel(
        const float* __restrict__ Wv, const float* __restrict__ bv) {
    extern __shared__ char sm[];
    __nv_bfloat16* sAhi = (__nv_bfloat16*)sm;
    __nv_bfloat16* sAlo = sAhi + 32*LDAT;
    __nv_bfloat16* sBhi = sAlo + 32*LDAT;
    __nv_bfloat16* sBlo = sBhi + 128*LDA;
    float* stage = (float*)sm;

    int bx = blockIdx.x;
    int ntile = bx & 3, sel = bx >> 2;
    int t = blockIdx.y;
    int n0 = ntile*128, m0 = t*128;
    const float* W = (sel == 0) ? Wv : g_Aop;
    float* C       = (sel == 0) ? g_V : g_Q;

    int tid = threadIdx.x, wid = tid >> 5;
    int wm = (wid & 1) * 64, wn = (wid >> 1) * 32;

    FragC acc[4][2];
    #pragma unroll
    for (int i = 0; i < 4; i++)
        #pragma unroll
        for (int j = 0; j < 2; j++)
            wmma::fill_fragment(acc[i][j], 0.0f);

    for (int k0 = 0; k0 < HH; k0 += BK) {
        {
            int k = tid >> 3;
            int bo_ = (tid & 7) * 4;
            const float* ap = g_bufB + ((size_t)t*HH + k0 + k)*BB;
            #pragma unroll
            for (int it = 0; it < 4; it++) {
                int bpos = bo_ + it*32;
                float4 v = *(const float4*)(ap + bpos);
                uint32_t h0, l0, h1, l1;
                split2(v.x, v.y, h0, l0); split2(v.z, v.w, h1, l1);
                *(uint32_t*)(sAhi + k*LDAT + bpos)     = h0;
                *(uint32_t*)(sAhi + k*LDAT + bpos + 2) = h1;
                *(uint32_t*)(sAlo + k*LDAT + bpos)     = l0;
                *(uint32_t*)(sAlo + k*LDAT + bpos + 2) = l1;
            }
        }
        load_split_tile(W + (size_t)n0*HH, HH, k0, sBhi, sBlo, tid >> 1, tid & 1);
        __syncthreads();
        #pragma unroll
        for (int kk = 0; kk < BK; kk += 16) {
            FragAc ah[4], al[4];
            #pragma unroll
            for (int i = 0; i < 4; i++) {
                wmma::load_matrix_sync(ah[i], sAhi + kk*LDAT + wm + i*16, LDAT);
                wmma::load_matrix_sync(al[i], sAlo + kk*LDAT + wm + i*16, LDAT);
            }
            #pragma unroll
            for (int j = 0; j < 2; j++) {
                FragB bh, bl;
                wmma::load_matrix_sync(bh, sBhi + (wn + j*16)*LDA + kk, LDA);
                wmma::load_matrix_sync(bl, sBlo + (wn + j*16)*LDA + kk, LDA);
                #pragma unroll
                for (int i = 0; i < 4; i++) {
                    wmma::mma_sync(acc[i][j], ah[i], bh, acc[i][j]);
                    wmma::mma_sync(acc[i][j], ah[i], bl, acc[i][j]);
                    wmma::mma_sync(acc[i][j], al[i], bh, acc[i][j]);
                }
            }
        }
        __syncthreads();
    }
    #pragma unroll
    for (int i = 0; i < 4; i++)
        #pragma unroll
        for (int j = 0; j < 2; j++)
            wmma::store_matrix_sync(stage + (wm + i*16)*LDS + wn + j*16,
                                    acc[i][j], LDS, wmma::mem_row_major);
    __syncthreads();

    int c = tid & 127, rr = tid >> 7;
    float bs = (sel == 0) ? bv[n0 + c] : 0.0f;
    for (int r2 = rr; r2 < 128; r2 += 2)
        C[(size_t)(m0 + r2)*HH + n0 + c] = stage[r2*LDS + c] + bs;
}

// ============== attention: sigmoid((Y.Xt + c1 + c2 + c0)*s) column sums ======
__device__ __forceinline__ void mma_tile_128(
        const float* baseA, size_t strideA,
        const float* baseB, size_t strideB,
        char* sm, float* stage) {
    __nv_bfloat16* sAhi = (__nv_bfloat16*)sm;
    __nv_bfloat16* sAlo = sAhi + 128*LDA;
    __nv_bfloat16* sBhi = sAlo + 128*LDA;
    __nv_bfloat16* sBlo = sBhi + 128*LDA;

    int tid = threadIdx.x, wid = tid >> 5;
    int r = tid >> 1, half = tid & 1;
    int wm = (wid & 1) * 64;
    int wn = (wid >> 1) * 32;

    FragC acc[4][2];
    #pragma unroll
    for (int i = 0; i < 4; i++)
        #pragma unroll
        for (int j = 0; j < 2; j++)
            wmma::fill_fragment(acc[i][j], 0.0f);

    for (int k0 = 0; k0 < HH; k0 += BK) {
        load_split_tile(baseA, strideA, k0, sAhi, sAlo, r, half);
        load_split_tile(baseB, strideB, k0, sBhi, sBlo, r, half);
        __syncthreads();
        #pragma unroll
        for (int kk = 0; kk < BK; kk += 16) {
            FragA ah[4], al[4];
            #pragma unroll
            for (int i = 0; i < 4; i++) {
                wmma::load_matrix_sync(ah[i], sAhi + (wm + i*16)*LDA + kk, LDA);
                wmma::load_matrix_sync(al[i], sAlo + (wm + i*16)*LDA + kk, LDA);
            }
            #pragma unroll
            for (int j = 0; j < 2; j++) {
                FragB bh, bl;
                wmma::load_matrix_sync(bh, sBhi + (wn + j*16)*LDA + kk, LDA);
                wmma::load_matrix_sync(bl, sBlo + (wn + j*16)*LDA + kk, LDA);
                #pragma unroll
                for (int i = 0; i < 4; i++) {
                    wmma::mma_sync(acc[i][j], ah[i], bh, acc[i][j]);
                    wmma::mma_sync(acc[i][j], ah[i], bl, acc[i][j]);
                    wmma::mma_sync(acc[i][j], al[i], bh, acc[i][j]);
                }
            }
        }
        __syncthreads();
    }
    #pragma unroll
    for (int i = 0; i < 4; i++)
        #pragma unroll
        for (int j = 0; j < 2; j++)
            wmma::store_matrix_sync(stage + (wm + i*16)*LDS + wn + j*16,
                                    acc[i][j], LDS, wmma::mem_row_major);
    __syncthreads();
}

__global__ __launch_bounds__(256) void attn_mma_kernel() {
    extern __shared__ char sm[];
    float* stage = (float*)sm;
    __shared__ float c1row[128];
    int b  = blockIdx.z;
    int n0 = blockIdx.x * 128;
    int m0 = blockIdx.y * 128;
    int tid = threadIdx.x;

    mma_tile_128(g_Q + ((size_t)m0*BB + b)*HH, (size_t)BB*HH,
                 g_K + ((size_t)n0*BB + b)*HH, (size_t)BB*HH, sm, stage);

    if (tid < 128) c1row[tid] = g_c1[(m0 + tid)*BB + b];
    __syncthreads();

    const float scale = 0.04419417382415922f;  // 512^-0.5
    if (tid < 128) {
        float c2v = g_c2[(n0 + tid)*BB + b] + g_cc[0];
        float s = 0.f;
        #pragma unroll 4
        for (int rr = 0; rr < 128; rr++) {
            float lg = stage[rr*LDS + tid] + c1row[rr] + c2v;
            s += 1.0f / (1.0f + __expf(-lg*scale));
        }
        g_wpart[blockIdx.y*(BB*TT) + b*TT + n0 + tid] = s;
    }
}

// ============== tail kernels (unchanged) ==============
__global__ void reduce_w_kernel() {
    int i = blockIdx.x*256 + threadIdx.x;
    g_wsum[i] = g_wpart[i] + g_wpart[BB*TT + i]
              + g_wpart[2*BB*TT + i] + g_wpart[3*BB*TT + i];
}

__global__ void feat_v_kernel() {
    int b = blockIdx.y;
    int d = blockIdx.x*128 + threadIdx.x;
    float acc = 0.f;
    #pragma unroll 4
    for (int s = 0; s < TT; s++)
        acc += g_wsum[b*TT + s] * g_V[((size_t)s*BB + b)*HH + d];
    g_feat[b*HH + d] = acc * (1.0f/TT);
}

__global__ void feat_bn_kernel(const float* __restrict__ g,
                               const float* __restrict__ bb) {
    int d = threadIdx.x;
    float s = 0.f, sq = 0.f;
    for (int b = 0; b < BB; b++) {
        float v = g_feat[b*HH + d];
        s += v; sq += v*v;
    }
    float m = s * (1.0f/BB);
    float rstd = rsqrtf(sq*(1.0f/BB) - m*m + 1e-5f);
    float gg = g[d]*rstd;
    float bo = bb[d] - m*gg;
    for (int b = 0; b < BB; b++)
        g_featn[b*HH + d] = g_feat[b*HH + d]*gg + bo;
}

__global__ void final_lin_kernel(const float* __restrict__ wh,
                                 const float* __restrict__ bh,
                                 float* __restrict__ out) {
    __shared__ float fs[HH];
    int b = blockIdx.x;
    int o = threadIdx.x;
    for (int i = o; i < HH; i += 96) fs[i] = g_featn[b*HH + i];
    __syncthreads();
    float acc = bh[o];
    for (int d = 0; d < HH; d++) acc += fs[d] * wh[o*HH + d];
    out[b*HORZ + o] = acc;
}

// ---------------- launch ------------------------------------------------------
extern "C" void kernel_launch(void* const* d_in, const int* in_sizes, int n_in,
                              void* d_out, int out_size) {
    const float* x        = (const float*)d_in[0];
    const float* conv_w   = (const float*)d_in[1];
    const float* conv_b   = (const float*)d_in[2];
    const float* bn1_g    = (const float*)d_in[3];
    const float* bn1_b    = (const float*)d_in[4];
    const float* beta_enc = (const float*)d_in[5];
    const float* bn2_g    = (const float*)d_in[6];
    const float* bn2_b    = (const float*)d_in[7];
    const float* beta2    = (const float*)d_in[8];
    const float* bn3_g    = (const float*)d_in[9];
    const float* bn3_b    = (const float*)d_in[10];
    const float* beta3    = (const float*)d_in[11];
    const float* wq       = (const float*)d_in[12];
    const float* bq       = (const float*)d_in[13];
    const float* wk       = (const float*)d_in[14];
    const float* bk       = (const float*)d_in[15];
    const float* wv       = (const float*)d_in[16];
    const float* bv       = (const float*)d_in[17];
    const float* bna_g    = (const float*)d_in[18];
    const float* bna_b    = (const float*)d_in[19];
    const float* wh       = (const float*)d_in[20];
    const float* bh       = (const float*)d_in[21];
    float* out = (float*)d_out;

    cudaFuncSetAttribute(vy_mma_kernel,   cudaFuncAttributeMaxDynamicSharedMemorySize, SM_DYN);
    cudaFuncSetAttribute(attn_mma_kernel, cudaFuncAttributeMaxDynamicSharedMemorySize, SM_DYN);

    // weight-side prep (independent of activations)
    prep_uwc_kernel<<<4, 128>>>(wq, bk, wk, bq);
    aop_kernel<<<dim3(4, 32), 128>>>(wq, wk);

    conv_kernel<<<dim3(NCHN/8, BB), 128>>>(x, conv_w, conv_b);
    chan_stats_kernel<<<NCHN, 256>>>();
    bn1t_kernel<<<dim3(NCHN, 4), 128>>>(bn1_g, bn1_b);

    snn_fused_kernel<<<HH, 128>>>(beta_enc, bn2_g, bn2_b, beta2, bn3_g, bn3_b, beta3);

    xpose_kernel<<<dim3(TT, 16), 256>>>();
    c12_kernel<<<TT, 128>>>();

    vy_mma_kernel<<<dim3(8, TT), 256, SM_DYN>>>(wv, bv);
    attn_mma_kernel<<<dim3(TT/128, TT/128, BB), 256, SM_DYN>>>();

    reduce_w_kernel<<<(BB*TT)/256, 256>>>();
    feat_v_kernel<<<dim3(HH/128, BB), 128>>>();
    feat_bn_kernel<<<1, HH>>>(bna_g, bna_b);
    final_lin_kernel<<<BB, HORZ>>>(wh, bh, out);
}

// round 9
// speedup vs baseline: 1.5501x; 1.0722x over previous
#include <cuda_runtime.h>
#include <cuda_bf16.h>
#include <mma.h>
#include <stdint.h>
#include <math.h>

using namespace nvcuda;

#define TT   512
#define BB   128
#define HH   512
#define CC   32
#define TIN  128
#define NCHN 2048
#define HORZ 96
#define NELEM (TT*BB*HH)

// ---------------- scratch ----------------
__device__ float g_conv[BB*NCHN*TIN];   // (B, 2048, Tin)
__device__ float g_bufA[NELEM];         // X after bn1: (tau, h, b)
__device__ float g_bufB[NELEM];         // mem3:        (tau, h, b)
__device__ float g_Q[NELEM];            // Y = X @ Aop^T   (m = t*BB+b, n)
__device__ float g_K[NELEM];            // Xt = mem3 in (m, k)
__device__ float g_V[NELEM];            // V = X @ Wv^T + bv (m, n)
__device__ float g_Aop[HH*HH];
__device__ float g_u[HH], g_w2[HH], g_cc[1];
__device__ float g_c1[TT*BB], g_c2[TT*BB];
__device__ float g_wpart[4*BB*TT];
__device__ float g_wsum[BB*TT];
__device__ float g_feat[BB*HH];
__device__ float g_featn[BB*HH];
__device__ float g_chm[NCHN];
__device__ float g_chr[NCHN];

__device__ __forceinline__ void split2(float x, float y, uint32_t& hi, uint32_t& lo) {
    __nv_bfloat16 hx = __float2bfloat16(x), hy = __float2bfloat16(y);
    __nv_bfloat16 lx = __float2bfloat16(x - __bfloat162float(hx));
    __nv_bfloat16 ly = __float2bfloat16(y - __bfloat162float(hy));
    __nv_bfloat162 h(hx, hy), l(lx, ly);
    hi = *(uint32_t*)&h; lo = *(uint32_t*)&l;
}

// ============== conv / chan_stats / bn1t / snn_fused (R8-identical) =========
__global__ __launch_bounds__(128) void conv_kernel(const float* __restrict__ x,
                            const float* __restrict__ w,
                            const float* __restrict__ cb) {
    __shared__ float xs2[32*136];
    __shared__ float ws4[8*32*4];
    int b  = blockIdx.y;
    int c0 = blockIdx.x * 8;
    int tid = threadIdx.x;

    for (int i = tid; i < 130*32; i += 128) {
        int r = i >> 5, ci = i & 31;
        int tt = r - 1;
        xs2[ci*136 + r] = (tt >= 0 && tt < TIN) ? x[(b*TIN + tt)*CC + ci] : 0.0f;
    }
    for (int i = tid; i < 256; i += 128) {
        int cc = i >> 5, ii = i & 31;
        const float* wp = w + (c0 + cc)*96 + ii*3;
        float* d = ws4 + i*4;
        d[0] = wp[0]; d[1] = wp[1]; d[2] = wp[2]; d[3] = 0.0f;
    }
    __syncthreads();

    int ccq = tid >> 5;
    int t4  = tid & 31;
    int t0  = t4 * 4;
    int cA = ccq*2, cB = ccq*2 + 1;

    float acc[2][4];
    acc[0][0] = acc[0][1] = acc[0][2] = acc[0][3] = cb[c0 + cA];
    acc[1][0] = acc[1][1] = acc[1][2] = acc[1][3] = cb[c0 + cB];

    #pragma unroll
    for (int i = 0; i < 32; i++) {
        float4 xa = *(const float4*)&xs2[i*136 + t0];
        float2 xb = *(const float2*)&xs2[i*136 + t0 + 4];
        #pragma unroll
        for (int c2 = 0; c2 < 2; c2++) {
            float4 wv = *(const float4*)&ws4[((ccq*2 + c2)*32 + i)*4];
            acc[c2][0] += wv.x*xa.x + wv.y*xa.y + wv.z*xa.z;
            acc[c2][1] += wv.x*xa.y + wv.y*xa.z + wv.z*xa.w;
            acc[c2][2] += wv.x*xa.z + wv.y*xa.w + wv.z*xb.x;
            acc[c2][3] += wv.x*xa.w + wv.y*xb.x + wv.z*xb.y;
        }
    }
    *(float4*)&g_conv[((size_t)b*NCHN + c0 + cA)*TIN + t0] =
        make_float4(acc[0][0], acc[0][1], acc[0][2], acc[0][3]);
    *(float4*)&g_conv[((size_t)b*NCHN + c0 + cB)*TIN + t0] =
        make_float4(acc[1][0], acc[1][1], acc[1][2], acc[1][3]);
}

__global__ void chan_stats_kernel() {
    int c = blockIdx.x;
    int tid = threadIdx.x;
    float s = 0.f, sq = 0.f;
    for (int i = tid; i < BB*TIN; i += 256) {
        int b = i >> 7, t = i & 127;
        float v = g_conv[(b*NCHN + c)*TIN + t];
        s += v; sq += v*v;
    }
    __shared__ float ss[256], sqs[256];
    ss[tid] = s; sqs[tid] = sq;
    __syncthreads();
    for (int o = 128; o > 0; o >>= 1) {
        if (tid < o) { ss[tid] += ss[tid+o]; sqs[tid] += sqs[tid+o]; }
        __syncthreads();
    }
    if (tid == 0) {
        float m   = ss[0] * (1.0f/(BB*TIN));
        float var = sqs[0] * (1.0f/(BB*TIN)) - m*m;
        g_chm[c] = m;
        g_chr[c] = rsqrtf(var + 1e-5f);
    }
}

__global__ void bn1t_kernel(const float* __restrict__ g,
                            const float* __restrict__ bb) {
    __shared__ float sm_t[128*33];
    int c = blockIdx.x, bq = blockIdx.y;
    int ts = c >> 9, h = c & 511;
    int tid = threadIdx.x;
    float chm = g_chm[c], chr = g_chr[c], gg = g[c], bo = bb[c];
    int bl = tid >> 2, tq = tid & 3;
    int b = bq*32 + bl;
    const float* src = g_conv + ((size_t)b*NCHN + c)*TIN;
    #pragma unroll
    for (int it = 0; it < 8; it++) {
        int tbase = (tq + it*4)*4;
        float4 v = *(const float4*)(src + tbase);
        sm_t[(tbase+0)*33 + bl] = (v.x - chm) * chr * gg + bo;
        sm_t[(tbase+1)*33 + bl] = (v.y - chm) * chr * gg + bo;
        sm_t[(tbase+2)*33 + bl] = (v.z - chm) * chr * gg + bo;
        sm_t[(tbase+3)*33 + bl] = (v.w - chm) * chr * gg + bo;
    }
    __syncthreads();
    int bl2 = tid & 31, tch = tid >> 5;
    #pragma unroll 8
    for (int it = 0; it < 32; it++) {
        int t = tch*32 + it;
        g_bufA[((size_t)(t*4 + ts)*HH + h)*BB + bq*32 + bl2] = sm_t[t*33 + bl2];
    }
}

__global__ __launch_bounds__(128) void snn_fused_kernel(
        const float* __restrict__ be,  const float* __restrict__ g2a,
        const float* __restrict__ b2a, const float* __restrict__ be2,
        const float* __restrict__ g3a, const float* __restrict__ b3a,
        const float* __restrict__ be3) {
    __shared__ int scnt[2][2][4];
    int tid = threadIdx.x;
    int h = blockIdx.x;
    int warp = tid >> 5, lane = tid & 31;
    float beta1 = fminf(fmaxf(be[h],  0.0f), 0.99f);
    float beta2 = fminf(fmaxf(be2[h], 0.0f), 0.99f);
    float beta3 = fminf(fmaxf(be3[h], 0.0f), 0.99f);
    float g2 = g2a[h], b2 = b2a[h], g3 = g3a[h], b3 = b3a[h];
    const float* src = g_bufA + (size_t)h*BB + tid;
    float* dst       = g_bufB + (size_t)h*BB + tid;
    float mem1 = 0.f, mem2 = 0.f, mem3 = 0.f;

    float cur[4];
    #pragma unroll
    for (int j = 0; j < 4; j++) cur[j] = src[(size_t)j*HH*BB];

    for (int t0 = 0; t0 < TT; t0 += 4) {
        float nxt[4] = {0.f, 0.f, 0.f, 0.f};
        if (t0 + 4 < TT) {
            #pragma unroll
            for (int j = 0; j < 4; j++) nxt[j] = src[(size_t)(t0+4+j)*HH*BB];
        }
        #pragma unroll
        for (int j = 0; j < 4; j++) {
            int t = t0 + j, par = t & 1;
            float reset = (mem1 > 1.0f) ? 1.0f : 0.0f;
            mem1 = beta1*mem1 + cur[j] - reset;
            float s1 = (mem1 > 1.0f) ? 1.0f : 0.0f;
            unsigned bal = __ballot_sync(0xffffffffu, mem1 > 1.0f);
            if (lane == 0) scnt[0][par][warp] = __popc(bal);
            __syncthreads();
            float sq = (float)(scnt[0][par][0] + scnt[0][par][1]
                             + scnt[0][par][2] + scnt[0][par][3]);
            float m    = sq * (1.0f/BB);
            float rstd = rsqrtf(sq*(1.0f/BB) - m*m + 1e-5f);
            float gg = g2*rstd;
            float bo = b2 - m*gg;
            float h2 = s1*gg + bo;

            float reset2 = (mem2 > 1.0f) ? 1.0f : 0.0f;
            mem2 = beta2*mem2 + h2 - reset2;
            float s2 = (mem2 > 1.0f) ? 1.0f : 0.0f;
            bal = __ballot_sync(0xffffffffu, mem2 > 1.0f);
            if (lane == 0) scnt[1][par][warp] = __popc(bal);
            __syncthreads();
            sq = (float)(scnt[1][par][0] + scnt[1][par][1]
                       + scnt[1][par][2] + scnt[1][par][3]);
            m    = sq * (1.0f/BB);
            rstd = rsqrtf(sq*(1.0f/BB) - m*m + 1e-5f);
            gg = g3*rstd;
            bo = b3 - m*gg;
            float h3 = s2*gg + bo;

            float reset3 = (mem3 > 1.0f) ? 1.0f : 0.0f;
            mem3 = beta3*mem3 + h3 - reset3;
            dst[(size_t)t*HH*BB] = mem3;
        }
        #pragma unroll
        for (int j = 0; j < 4; j++) cur[j] = nxt[j];
    }
}

// ============== prep kernels (R8-identical) ==============
__global__ void prep_uwc_kernel(const float* __restrict__ wq,
                                const float* __restrict__ bk,
                                const float* __restrict__ wk,
                                const float* __restrict__ bq) {
    int k = blockIdx.x*128 + threadIdx.x;
    float su = 0.f, sw = 0.f;
    for (int n = 0; n < HH; n++) {
        su += wq[n*HH + k] * bk[n];
        sw += wk[n*HH + k] * bq[n];
    }
    g_u[k] = su; g_w2[k] = sw;
    if (blockIdx.x == 0 && threadIdx.x == 0) {
        float c = 0.f;
        for (int n = 0; n < HH; n++) c += bq[n]*bk[n];
        g_cc[0] = c;
    }
}

__global__ void aop_kernel(const float* __restrict__ wq,
                           const float* __restrict__ wk) {
    int k  = blockIdx.x*128 + threadIdx.x;
    int n0 = blockIdx.y*16;
    float acc[16] = {};
    for (int j = 0; j < HH; j++) {
        float a = wq[j*HH + k];
        #pragma unroll
        for (int i = 0; i < 16; i++)
            acc[i] += a * wk[j*HH + n0 + i];
    }
    #pragma unroll
    for (int i = 0; i < 16; i++)
        g_Aop[(n0+i)*HH + k] = acc[i];
}

__global__ __launch_bounds__(256) void xpose_kernel() {
    __shared__ float smt[32][129];
    int t = blockIdx.x, h0 = blockIdx.y*32;
    int tid = threadIdx.x;
    int b = tid & 127, hq = tid >> 7;
    #pragma unroll
    for (int i = 0; i < 16; i++) {
        int hh2 = hq*16 + i;
        smt[hh2][b] = g_bufB[((size_t)t*HH + h0 + hh2)*BB + b];
    }
    __syncthreads();
    int b2 = tid >> 1, half = tid & 1;
    float* dst = g_K + ((size_t)t*BB + b2)*HH + h0 + half*16;
    #pragma unroll
    for (int i = 0; i < 4; i++) {
        *(float4*)(dst + i*4) = make_float4(
            smt[half*16 + i*4 + 0][b2], smt[half*16 + i*4 + 1][b2],
            smt[half*16 + i*4 + 2][b2], smt[half*16 + i*4 + 3][b2]);
    }
}

__global__ __launch_bounds__(128) void c12_kernel() {
    __shared__ float su[HH], sw[HH];
    int t = blockIdx.x, tid = threadIdx.x;
    for (int i = tid; i < HH; i += 128) { su[i] = g_u[i]; sw[i] = g_w2[i]; }
    __syncthreads();
    float c1 = 0.f, c2 = 0.f;
    const float* src = g_bufB + (size_t)t*HH*BB + tid;
    #pragma unroll 4
    for (int h = 0; h < HH; h++) {
        float v = src[(size_t)h*BB];
        c1 += v * su[h];
        c2 += v * sw[h];
    }
    g_c1[t*BB + tid] = c1;
    g_c2[t*BB + tid] = c2;
}

// ============== wmma GEMM: double-buffered, BK=16 ==============
#define LDA16 24          // bf16 row stride: 16 data + 8 pad (48B)
#define LDAT  136         // vy A tile: b-contiguous, stride 136 bf16
#define LDS   132         // fp32 epilogue stage stride
#define SM_DYN (128*LDS*4)        // 67584 B (stage; superset of buffers)
#define BUF_AT 12288              // bf16 elems per attn buffer set
#define BUF_VY 10496              // bf16 elems per vy buffer set

typedef wmma::fragment<wmma::matrix_a, 16,16,16, __nv_bfloat16, wmma::row_major> FragA;
typedef wmma::fragment<wmma::matrix_a, 16,16,16, __nv_bfloat16, wmma::col_major> FragAc;
typedef wmma::fragment<wmma::matrix_b, 16,16,16, __nv_bfloat16, wmma::col_major> FragB;
typedef wmma::fragment<wmma::accumulator, 16,16,16, float> FragC;

__device__ __forceinline__ void split_store16(const float4* pre,
        __nv_bfloat16* dhi, __nv_bfloat16* dlo) {
    uint32_t hbuf[8], lbuf[8];
    #pragma unroll
    for (int i = 0; i < 4; i++) {
        split2(pre[i].x, pre[i].y, hbuf[i*2],   lbuf[i*2]);
        split2(pre[i].z, pre[i].w, hbuf[i*2+1], lbuf[i*2+1]);
    }
    *(uint4*)dhi       = make_uint4(hbuf[0], hbuf[1], hbuf[2], hbuf[3]);
    *(uint4*)(dhi + 8) = make_uint4(hbuf[4], hbuf[5], hbuf[6], hbuf[7]);
    *(uint4*)dlo       = make_uint4(lbuf[0], lbuf[1], lbuf[2], lbuf[3]);
    *(uint4*)(dlo + 8) = make_uint4(lbuf[4], lbuf[5], lbuf[6], lbuf[7]);
}

// ---- attention core: A,B both 128 rows x 512 k, row-major fp32 ----
__device__ __forceinline__ void mma_tile_128_db(
        const float* baseA, size_t strideA,
        const float* baseB, size_t strideB,
        char* sm, float* stage) {
    int tid = threadIdx.x, wid = tid >> 5;
    int wm = (wid & 1) * 64, wn = (wid >> 1) * 32;
    int isB = tid >> 7;           // 0: A filler, 1: B filler
    int row = tid & 127;
    const float* gsrc = isB ? (baseB + (size_t)row*strideB)
                            : (baseA + (size_t)row*strideA);

    FragC acc[4][2];
    #pragma unroll
    for (int i = 0; i < 4; i++)
        #pragma unroll
        for (int j = 0; j < 2; j++)
            wmma::fill_fragment(acc[i][j], 0.0f);

    float4 pre[4];
    #pragma unroll
    for (int i = 0; i < 4; i++) pre[i] = *(const float4*)(gsrc + i*4);

    for (int ck = 0; ck < 32; ck++) {
        __nv_bfloat16* buf = (__nv_bfloat16*)sm + (ck & 1)*BUF_AT;
        __nv_bfloat16* dhi = buf + isB*6144 + row*LDA16;
        split_store16(pre, dhi, dhi + 3072);
        __syncthreads();
        if (ck < 31) {
            const float* p = gsrc + (ck + 1)*16;
            #pragma unroll
            for (int i = 0; i < 4; i++) pre[i] = *(const float4*)(p + i*4);
        }
        __nv_bfloat16* sA = buf;
        __nv_bfloat16* sB = buf + 6144;
        FragA ah[4], al[4];
        #pragma unroll
        for (int i = 0; i < 4; i++) {
            wmma::load_matrix_sync(ah[i], sA + (wm + i*16)*LDA16, LDA16);
            wmma::load_matrix_sync(al[i], sA + 3072 + (wm + i*16)*LDA16, LDA16);
        }
        #pragma unroll
        for (int j = 0; j < 2; j++) {
            FragB bh, bl;
            wmma::load_matrix_sync(bh, sB + (wn + j*16)*LDA16, LDA16);
            wmma::load_matrix_sync(bl, sB + 3072 + (wn + j*16)*LDA16, LDA16);
            #pragma unroll
            for (int i = 0; i < 4; i++) {
                wmma::mma_sync(acc[i][j], ah[i], bh, acc[i][j]);
                wmma::mma_sync(acc[i][j], ah[i], bl, acc[i][j]);
                wmma::mma_sync(acc[i][j], al[i], bh, acc[i][j]);
            }
        }
    }
    __syncthreads();
    #pragma unroll
    for (int i = 0; i < 4; i++)
        #pragma unroll
        for (int j = 0; j < 2; j++)
            wmma::store_matrix_sync(stage + (wm + i*16)*LDS + wn + j*16,
                                    acc[i][j], LDS, wmma::mem_row_major);
    __syncthreads();
}

// ============== VY: sel0 -> V = X Wv^T + bv;  sel1 -> Y = X Aop^T ============
// A from g_bufB (t, k, b) layout: natively col-major tiles.
__global__ __launch_bounds__(256, 2) void vy_mma_kernel(
        const float* __restrict__ Wv, const float* __restrict__ bv) {
    extern __shared__ char sm[];
    float* stage = (float*)sm;

    int bx = blockIdx.x;
    int ntile = bx & 3, sel = bx >> 2;
    int t = blockIdx.y;
    int n0 = ntile*128, m0 = t*128;
    const float* W = (sel == 0) ? Wv : g_Aop;
    float* C       = (sel == 0) ? g_V : g_Q;

    int tid = threadIdx.x, wid = tid >> 5;
    int wm = (wid & 1) * 64, wn = (wid >> 1) * 32;
    int isB = tid >> 7;
    // A filler: k = tid>>3 (0..15 within chunk), b0 = (tid&7)*16
    int ak = tid >> 3, ab0 = (tid & 7) * 16;
    // B filler: row = tid-128
    int brow = tid & 127;

    FragC acc[4][2];
    #pragma unroll
    for (int i = 0; i < 4; i++)
        #pragma unroll
        for (int j = 0; j < 2; j++)
            wmma::fill_fragment(acc[i][j], 0.0f);

    float4 pre[4];
    if (isB) {
        const float* p = W + (size_t)(n0 + brow)*HH;
        #pragma unroll
        for (int i = 0; i < 4; i++) pre[i] = *(const float4*)(p + i*4);
    } else {
        const float* p = g_bufB + ((size_t)t*HH + ak)*BB + ab0;
        #pragma unroll
        for (int i = 0; i < 4; i++) pre[i] = *(const float4*)(p + i*4);
    }

    for (int ck = 0; ck < 32; ck++) {
        __nv_bfloat16* buf = (__nv_bfloat16*)sm + (ck & 1)*BUF_VY;
        if (isB) {
            __nv_bfloat16* dhi = buf + 4352 + brow*LDA16;
            split_store16(pre, dhi, dhi + 3072);
        } else {
            __nv_bfloat16* dhi = buf + ak*LDAT + ab0;
            split_store16(pre, dhi, dhi + 2176);
        }
        __syncthreads();
        if (ck < 31) {
            if (isB) {
                const float* p = W + (size_t)(n0 + brow)*HH + (ck + 1)*16;
                #pragma unroll
                for (int i = 0; i < 4; i++) pre[i] = *(const float4*)(p + i*4);
            } else {
                const float* p = g_bufB + ((size_t)t*HH + (ck + 1)*16 + ak)*BB + ab0;
                #pragma unroll
                for (int i = 0; i < 4; i++) pre[i] = *(const float4*)(p + i*4);
            }
        }
        __nv_bfloat16* sA = buf;
        __nv_bfloat16* sB = buf + 4352;
        FragAc ah[4], al[4];
        #pragma unroll
        for (int i = 0; i < 4; i++) {
            wmma::load_matrix_sync(ah[i], sA + wm + i*16, LDAT);
            wmma::load_matrix_sync(al[i], sA + 2176 + wm + i*16, LDAT);
        }
        #pragma unroll
        for (int j = 0; j < 2; j++) {
            FragB bh, bl;
            wmma::load_matrix_sync(bh, sB + (wn + j*16)*LDA16, LDA16);
            wmma::load_matrix_sync(bl, sB + 3072 + (wn + j*16)*LDA16, LDA16);
            #pragma unroll
            for (int i = 0; i < 4; i++) {
                wmma::mma_sync(acc[i][j], ah[i], bh, acc[i][j]);
                wmma::mma_sync(acc[i][j], ah[i], bl, acc[i][j]);
                wmma::mma_sync(acc[i][j], al[i], bh, acc[i][j]);
            }
        }
    }
    __syncthreads();
    #pragma unroll
    for (int i = 0; i < 4; i++)
        #pragma unroll
        for (int j = 0; j < 2; j++)
            wmma::store_matrix_sync(stage + (wm + i*16)*LDS + wn + j*16,
                                    acc[i][j], LDS, wmma::mem_row_major);
    __syncthreads();

    int c = tid & 127, rr = tid >> 7;
    float bs = (sel == 0) ? bv[n0 + c] : 0.0f;
    for (int r2 = rr; r2 < 128; r2 += 2)
        C[(size_t)(m0 + r2)*HH + n0 + c] = stage[r2*LDS + c] + bs;
}

// ============== attention: sigmoid((Y.Xt + c1 + c2 + c0)*s) column sums ======
__global__ __launch_bounds__(256, 2) void attn_mma_kernel() {
    extern __shared__ char sm[];
    float* stage = (float*)sm;
    __shared__ float c1row[128];
    int b  = blockIdx.z;
    int n0 = blockIdx.x * 128;
    int m0 = blockIdx.y * 128;
    int tid = threadIdx.x;

    mma_tile_128_db(g_Q + ((size_t)m0*BB + b)*HH, (size_t)BB*HH,
                    g_K + ((size_t)n0*BB + b)*HH, (size_t)BB*HH, sm, stage);

    if (tid < 128) c1row[tid] = g_c1[(m0 + tid)*BB + b];
    __syncthreads();

    const float scale = 0.04419417382415922f;  // 512^-0.5
    if (tid < 128) {
        float c2v = g_c2[(n0 + tid)*BB + b] + g_cc[0];
        float s = 0.f;
        #pragma unroll 4
        for (int rr = 0; rr < 128; rr++) {
            float lg = stage[rr*LDS + tid] + c1row[rr] + c2v;
            s += 1.0f / (1.0f + __expf(-lg*scale));
        }
        g_wpart[blockIdx.y*(BB*TT) + b*TT + n0 + tid] = s;
    }
}

// ============== tail kernels (unchanged) ==============
__global__ void reduce_w_kernel() {
    int i = blockIdx.x*256 + threadIdx.x;
    g_wsum[i] = g_wpart[i] + g_wpart[BB*TT + i]
              + g_wpart[2*BB*TT + i] + g_wpart[3*BB*TT + i];
}

__global__ void feat_v_kernel() {
    int b = blockIdx.y;
    int d = blockIdx.x*128 + threadIdx.x;
    float acc = 0.f;
    #pragma unroll 4
    for (int s = 0; s < TT; s++)
        acc += g_wsum[b*TT + s] * g_V[((size_t)s*BB + b)*HH + d];
    g_feat[b*HH + d] = acc * (1.0f/TT);
}

__global__ void feat_bn_kernel(const float* __restrict__ g,
                               const float* __restrict__ bb) {
    int d = threadIdx.x;
    float s = 0.f, sq = 0.f;
    for (int b = 0; b < BB; b++) {
        float v = g_feat[b*HH + d];
        s += v; sq += v*v;
    }
    float m = s * (1.0f/BB);
    float rstd = rsqrtf(sq*(1.0f/BB) - m*m + 1e-5f);
    float gg = g[d]*rstd;
    float bo = bb[d] - m*gg;
    for (int b = 0; b < BB; b++)
        g_featn[b*HH + d] = g_feat[b*HH + d]*gg + bo;
}

__global__ void final_lin_kernel(const float* __restrict__ wh,
                                 const float* __restrict__ bh,
                                 float* __restrict__ out) {
    __shared__ float fs[HH];
    int b = blockIdx.x;
    int o = threadIdx.x;
    for (int i = o; i < HH; i += 96) fs[i] = g_featn[b*HH + i];
    __syncthreads();
    float acc = bh[o];
    for (int d = 0; d < HH; d++) acc += fs[d] * wh[o*HH + d];
    out[b*HORZ + o] = acc;
}

// ---------------- launch ------------------------------------------------------
extern "C" void kernel_launch(void* const* d_in, const int* in_sizes, int n_in,
                              void* d_out, int out_size) {
    const float* x        = (const float*)d_in[0];
    const float* conv_w   = (const float*)d_in[1];
    const float* conv_b   = (const float*)d_in[2];
    const float* bn1_g    = (const float*)d_in[3];
    const float* bn1_b    = (const float*)d_in[4];
    const float* beta_enc = (const float*)d_in[5];
    const float* bn2_g    = (const float*)d_in[6];
    const float* bn2_b    = (const float*)d_in[7];
    const float* beta2    = (const float*)d_in[8];
    const float* bn3_g    = (const float*)d_in[9];
    const float* bn3_b    = (const float*)d_in[10];
    const float* beta3    = (const float*)d_in[11];
    const float* wq       = (const float*)d_in[12];
    const float* bq       = (const float*)d_in[13];
    const float* wk       = (const float*)d_in[14];
    const float* bk       = (const float*)d_in[15];
    const float* wv       = (const float*)d_in[16];
    const float* bv       = (const float*)d_in[17];
    const float* bna_g    = (const float*)d_in[18];
    const float* bna_b    = (const float*)d_in[19];
    const float* wh       = (const float*)d_in[20];
    const float* bh       = (const float*)d_in[21];
    float* out = (float*)d_out;

    cudaFuncSetAttribute(vy_mma_kernel,   cudaFuncAttributeMaxDynamicSharedMemorySize, SM_DYN);
    cudaFuncSetAttribute(attn_mma_kernel, cudaFuncAttributeMaxDynamicSharedMemorySize, SM_DYN);

    prep_uwc_kernel<<<4, 128>>>(wq, bk, wk, bq);
    aop_kernel<<<dim3(4, 32), 128>>>(wq, wk);

    conv_kernel<<<dim3(NCHN/8, BB), 128>>>(x, conv_w, conv_b);
    chan_stats_kernel<<<NCHN, 256>>>();
    bn1t_kernel<<<dim3(NCHN, 4), 128>>>(bn1_g, bn1_b);

    snn_fused_kernel<<<HH, 128>>>(beta_enc, bn2_g, bn2_b, beta2, bn3_g, bn3_b, beta3);

    xpose_kernel<<<dim3(TT, 16), 256>>>();
    c12_kernel<<<TT, 128>>>();

    vy_mma_kernel<<<dim3(8, TT), 256, SM_DYN>>>(wv, bv);
    attn_mma_kernel<<<dim3(TT/128, TT/128, BB), 256, SM_DYN>>>();

    reduce_w_kernel<<<(BB*TT)/256, 256>>>();
    feat_v_kernel<<<dim3(HH/128, BB), 128>>>();
    feat_bn_kernel<<<1, HH>>>(bna_g, bna_b);
    final_lin_kernel<<<BB, HORZ>>>(wh, bh, out);
}

// round 10
// speedup vs baseline: 1.7890x; 1.1541x over previous
#include <cuda_runtime.h>
#include <cuda_bf16.h>
#include <mma.h>
#include <stdint.h>
#include <math.h>

using namespace nvcuda;

#define TT   512
#define BB   128
#define HH   512
#define CC   32
#define TIN  128
#define NCHN 2048
#define HORZ 96
#define NELEM (TT*BB*HH)

// ---------------- scratch ----------------
__device__ float g_conv[BB*NCHN*TIN];   // (B, 2048, Tin)
__device__ float g_bufA[NELEM];         // X after bn1: (tau, h, b)
__device__ float g_bufB[NELEM];         // mem3:        (tau, h, b)
__device__ float g_Q[NELEM];            // Y = X @ Aop^T   (m = t*BB+b, n)
__device__ float g_K[NELEM];            // Xt = mem3 in (m, k)
__device__ float g_Aop[HH*HH];
__device__ float g_u[HH], g_w2[HH], g_cc[1];
__device__ float g_c1[TT*BB], g_c2[TT*BB];
__device__ float g_wpart[4*BB*TT];
__device__ float g_wsum[BB*TT];
__device__ float g_z[BB*HH];
__device__ float g_sw[BB];
__device__ float g_feat[BB*HH];
__device__ float g_featn[BB*HH];
__device__ float g_chm[NCHN];
__device__ float g_chr[NCHN];

__device__ __forceinline__ void split2(float x, float y, uint32_t& hi, uint32_t& lo) {
    __nv_bfloat16 hx = __float2bfloat16(x), hy = __float2bfloat16(y);
    __nv_bfloat16 lx = __float2bfloat16(x - __bfloat162float(hx));
    __nv_bfloat16 ly = __float2bfloat16(y - __bfloat162float(hy));
    __nv_bfloat162 h(hx, hy), l(lx, ly);
    hi = *(uint32_t*)&h; lo = *(uint32_t*)&l;
}

// ============== conv / chan_stats / bn1t / snn_fused (R9-identical) =========
__global__ __launch_bounds__(128) void conv_kernel(const float* __restrict__ x,
                            const float* __restrict__ w,
                            const float* __restrict__ cb) {
    __shared__ float xs2[32*136];
    __shared__ float ws4[8*32*4];
    int b  = blockIdx.y;
    int c0 = blockIdx.x * 8;
    int tid = threadIdx.x;

    for (int i = tid; i < 130*32; i += 128) {
        int r = i >> 5, ci = i & 31;
        int tt = r - 1;
        xs2[ci*136 + r] = (tt >= 0 && tt < TIN) ? x[(b*TIN + tt)*CC + ci] : 0.0f;
    }
    for (int i = tid; i < 256; i += 128) {
        int cc = i >> 5, ii = i & 31;
        const float* wp = w + (c0 + cc)*96 + ii*3;
        float* d = ws4 + i*4;
        d[0] = wp[0]; d[1] = wp[1]; d[2] = wp[2]; d[3] = 0.0f;
    }
    __syncthreads();

    int ccq = tid >> 5;
    int t4  = tid & 31;
    int t0  = t4 * 4;
    int cA = ccq*2, cB = ccq*2 + 1;

    float acc[2][4];
    acc[0][0] = acc[0][1] = acc[0][2] = acc[0][3] = cb[c0 + cA];
    acc[1][0] = acc[1][1] = acc[1][2] = acc[1][3] = cb[c0 + cB];

    #pragma unroll
    for (int i = 0; i < 32; i++) {
        float4 xa = *(const float4*)&xs2[i*136 + t0];
        float2 xb = *(const float2*)&xs2[i*136 + t0 + 4];
        #pragma unroll
        for (int c2 = 0; c2 < 2; c2++) {
            float4 wv = *(const float4*)&ws4[((ccq*2 + c2)*32 + i)*4];
            acc[c2][0] += wv.x*xa.x + wv.y*xa.y + wv.z*xa.z;
            acc[c2][1] += wv.x*xa.y + wv.y*xa.z + wv.z*xa.w;
            acc[c2][2] += wv.x*xa.z + wv.y*xa.w + wv.z*xb.x;
            acc[c2][3] += wv.x*xa.w + wv.y*xb.x + wv.z*xb.y;
        }
    }
    *(float4*)&g_conv[((size_t)b*NCHN + c0 + cA)*TIN + t0] =
        make_float4(acc[0][0], acc[0][1], acc[0][2], acc[0][3]);
    *(float4*)&g_conv[((size_t)b*NCHN + c0 + cB)*TIN + t0] =
        make_float4(acc[1][0], acc[1][1], acc[1][2], acc[1][3]);
}

__global__ void chan_stats_kernel() {
    int c = blockIdx.x;
    int tid = threadIdx.x;
    float s = 0.f, sq = 0.f;
    for (int i = tid; i < BB*TIN; i += 256) {
        int b = i >> 7, t = i & 127;
        float v = g_conv[(b*NCHN + c)*TIN + t];
        s += v; sq += v*v;
    }
    __shared__ float ss[256], sqs[256];
    ss[tid] = s; sqs[tid] = sq;
    __syncthreads();
    for (int o = 128; o > 0; o >>= 1) {
        if (tid < o) { ss[tid] += ss[tid+o]; sqs[tid] += sqs[tid+o]; }
        __syncthreads();
    }
    if (tid == 0) {
        float m   = ss[0] * (1.0f/(BB*TIN));
        float var = sqs[0] * (1.0f/(BB*TIN)) - m*m;
        g_chm[c] = m;
        g_chr[c] = rsqrtf(var + 1e-5f);
    }
}

__global__ void bn1t_kernel(const float* __restrict__ g,
                            const float* __restrict__ bb) {
    __shared__ float sm_t[128*33];
    int c = blockIdx.x, bq = blockIdx.y;
    int ts = c >> 9, h = c & 511;
    int tid = threadIdx.x;
    float chm = g_chm[c], chr = g_chr[c], gg = g[c], bo = bb[c];
    int bl = tid >> 2, tq = tid & 3;
    int b = bq*32 + bl;
    const float* src = g_conv + ((size_t)b*NCHN + c)*TIN;
    #pragma unroll
    for (int it = 0; it < 8; it++) {
        int tbase = (tq + it*4)*4;
        float4 v = *(const float4*)(src + tbase);
        sm_t[(tbase+0)*33 + bl] = (v.x - chm) * chr * gg + bo;
        sm_t[(tbase+1)*33 + bl] = (v.y - chm) * chr * gg + bo;
        sm_t[(tbase+2)*33 + bl] = (v.z - chm) * chr * gg + bo;
        sm_t[(tbase+3)*33 + bl] = (v.w - chm) * chr * gg + bo;
    }
    __syncthreads();
    int bl2 = tid & 31, tch = tid >> 5;
    #pragma unroll 8
    for (int it = 0; it < 32; it++) {
        int t = tch*32 + it;
        g_bufA[((size_t)(t*4 + ts)*HH + h)*BB + bq*32 + bl2] = sm_t[t*33 + bl2];
    }
}

__global__ __launch_bounds__(128) void snn_fused_kernel(
        const float* __restrict__ be,  const float* __restrict__ g2a,
        const float* __restrict__ b2a, const float* __restrict__ be2,
        const float* __restrict__ g3a, const float* __restrict__ b3a,
        const float* __restrict__ be3) {
    __shared__ int scnt[2][2][4];
    int tid = threadIdx.x;
    int h = blockIdx.x;
    int warp = tid >> 5, lane = tid & 31;
    float beta1 = fminf(fmaxf(be[h],  0.0f), 0.99f);
    float beta2 = fminf(fmaxf(be2[h], 0.0f), 0.99f);
    float beta3 = fminf(fmaxf(be3[h], 0.0f), 0.99f);
    float g2 = g2a[h], b2 = b2a[h], g3 = g3a[h], b3 = b3a[h];
    const float* src = g_bufA + (size_t)h*BB + tid;
    float* dst       = g_bufB + (size_t)h*BB + tid;
    float mem1 = 0.f, mem2 = 0.f, mem3 = 0.f;

    float cur[4];
    #pragma unroll
    for (int j = 0; j < 4; j++) cur[j] = src[(size_t)j*HH*BB];

    for (int t0 = 0; t0 < TT; t0 += 4) {
        float nxt[4] = {0.f, 0.f, 0.f, 0.f};
        if (t0 + 4 < TT) {
            #pragma unroll
            for (int j = 0; j < 4; j++) nxt[j] = src[(size_t)(t0+4+j)*HH*BB];
        }
        #pragma unroll
        for (int j = 0; j < 4; j++) {
            int t = t0 + j, par = t & 1;
            float reset = (mem1 > 1.0f) ? 1.0f : 0.0f;
            mem1 = beta1*mem1 + cur[j] - reset;
            float s1 = (mem1 > 1.0f) ? 1.0f : 0.0f;
            unsigned bal = __ballot_sync(0xffffffffu, mem1 > 1.0f);
            if (lane == 0) scnt[0][par][warp] = __popc(bal);
            __syncthreads();
            float sq = (float)(scnt[0][par][0] + scnt[0][par][1]
                             + scnt[0][par][2] + scnt[0][par][3]);
            float m    = sq * (1.0f/BB);
            float rstd = rsqrtf(sq*(1.0f/BB) - m*m + 1e-5f);
            float gg = g2*rstd;
            float bo = b2 - m*gg;
            float h2 = s1*gg + bo;

            float reset2 = (mem2 > 1.0f) ? 1.0f : 0.0f;
            mem2 = beta2*mem2 + h2 - reset2;
            float s2 = (mem2 > 1.0f) ? 1.0f : 0.0f;
            bal = __ballot_sync(0xffffffffu, mem2 > 1.0f);
            if (lane == 0) scnt[1][par][warp] = __popc(bal);
            __syncthreads();
            sq = (float)(scnt[1][par][0] + scnt[1][par][1]
                       + scnt[1][par][2] + scnt[1][par][3]);
            m    = sq * (1.0f/BB);
            rstd = rsqrtf(sq*(1.0f/BB) - m*m + 1e-5f);
            gg = g3*rstd;
            bo = b3 - m*gg;
            float h3 = s2*gg + bo;

            float reset3 = (mem3 > 1.0f) ? 1.0f : 0.0f;
            mem3 = beta3*mem3 + h3 - reset3;
            dst[(size_t)t*HH*BB] = mem3;
        }
        #pragma unroll
        for (int j = 0; j < 4; j++) cur[j] = nxt[j];
    }
}

// ============== prep kernels (R9-identical) ==============
__global__ void prep_uwc_kernel(const float* __restrict__ wq,
                                const float* __restrict__ bk,
                                const float* __restrict__ wk,
                                const float* __restrict__ bq) {
    int k = blockIdx.x*128 + threadIdx.x;
    float su = 0.f, sw = 0.f;
    for (int n = 0; n < HH; n++) {
        su += wq[n*HH + k] * bk[n];
        sw += wk[n*HH + k] * bq[n];
    }
    g_u[k] = su; g_w2[k] = sw;
    if (blockIdx.x == 0 && threadIdx.x == 0) {
        float c = 0.f;
        for (int n = 0; n < HH; n++) c += bq[n]*bk[n];
        g_cc[0] = c;
    }
}

__global__ void aop_kernel(const float* __restrict__ wq,
                           const float* __restrict__ wk) {
    int k  = blockIdx.x*128 + threadIdx.x;
    int n0 = blockIdx.y*16;
    float acc[16] = {};
    for (int j = 0; j < HH; j++) {
        float a = wq[j*HH + k];
        #pragma unroll
        for (int i = 0; i < 16; i++)
            acc[i] += a * wk[j*HH + n0 + i];
    }
    #pragma unroll
    for (int i = 0; i < 16; i++)
        g_Aop[(n0+i)*HH + k] = acc[i];
}

__global__ __launch_bounds__(256) void xpose_kernel() {
    __shared__ float smt[32][129];
    int t = blockIdx.x, h0 = blockIdx.y*32;
    int tid = threadIdx.x;
    int b = tid & 127, hq = tid >> 7;
    #pragma unroll
    for (int i = 0; i < 16; i++) {
        int hh2 = hq*16 + i;
        smt[hh2][b] = g_bufB[((size_t)t*HH + h0 + hh2)*BB + b];
    }
    __syncthreads();
    int b2 = tid >> 1, half = tid & 1;
    float* dst = g_K + ((size_t)t*BB + b2)*HH + h0 + half*16;
    #pragma unroll
    for (int i = 0; i < 4; i++) {
        *(float4*)(dst + i*4) = make_float4(
            smt[half*16 + i*4 + 0][b2], smt[half*16 + i*4 + 1][b2],
            smt[half*16 + i*4 + 2][b2], smt[half*16 + i*4 + 3][b2]);
    }
}

__global__ __launch_bounds__(128) void c12_kernel() {
    __shared__ float su[HH], sw[HH];
    int t = blockIdx.x, tid = threadIdx.x;
    for (int i = tid; i < HH; i += 128) { su[i] = g_u[i]; sw[i] = g_w2[i]; }
    __syncthreads();
    float c1 = 0.f, c2 = 0.f;
    const float* src = g_bufB + (size_t)t*HH*BB + tid;
    #pragma unroll 4
    for (int h = 0; h < HH; h++) {
        float v = src[(size_t)h*BB];
        c1 += v * su[h];
        c2 += v * sw[h];
    }
    g_c1[t*BB + tid] = c1;
    g_c2[t*BB + tid] = c2;
}

// ============== wmma GEMM: double-buffered, BK=16 (R9-identical core) ========
#define LDA16 24
#define LDAT  136
#define LDS   132
#define SM_DYN (128*LDS*4)
#define BUF_AT 12288
#define BUF_VY 10496

typedef wmma::fragment<wmma::matrix_a, 16,16,16, __nv_bfloat16, wmma::row_major> FragA;
typedef wmma::fragment<wmma::matrix_a, 16,16,16, __nv_bfloat16, wmma::col_major> FragAc;
typedef wmma::fragment<wmma::matrix_b, 16,16,16, __nv_bfloat16, wmma::col_major> FragB;
typedef wmma::fragment<wmma::accumulator, 16,16,16, float> FragC;

__device__ __forceinline__ void split_store16(const float4* pre,
        __nv_bfloat16* dhi, __nv_bfloat16* dlo) {
    uint32_t hbuf[8], lbuf[8];
    #pragma unroll
    for (int i = 0; i < 4; i++) {
        split2(pre[i].x, pre[i].y, hbuf[i*2],   lbuf[i*2]);
        split2(pre[i].z, pre[i].w, hbuf[i*2+1], lbuf[i*2+1]);
    }
    *(uint4*)dhi       = make_uint4(hbuf[0], hbuf[1], hbuf[2], hbuf[3]);
    *(uint4*)(dhi + 8) = make_uint4(hbuf[4], hbuf[5], hbuf[6], hbuf[7]);
    *(uint4*)dlo       = make_uint4(lbuf[0], lbuf[1], lbuf[2], lbuf[3]);
    *(uint4*)(dlo + 8) = make_uint4(lbuf[4], lbuf[5], lbuf[6], lbuf[7]);
}

__device__ __forceinline__ void mma_tile_128_db(
        const float* baseA, size_t strideA,
        const float* baseB, size_t strideB,
        char* sm, float* stage) {
    int tid = threadIdx.x, wid = tid >> 5;
    int wm = (wid & 1) * 64, wn = (wid >> 1) * 32;
    int isB = tid >> 7;
    int row = tid & 127;
    const float* gsrc = isB ? (baseB + (size_t)row*strideB)
                            : (baseA + (size_t)row*strideA);

    FragC acc[4][2];
    #pragma unroll
    for (int i = 0; i < 4; i++)
        #pragma unroll
        for (int j = 0; j < 2; j++)
            wmma::fill_fragment(acc[i][j], 0.0f);

    float4 pre[4];
    #pragma unroll
    for (int i = 0; i < 4; i++) pre[i] = *(const float4*)(gsrc + i*4);

    for (int ck = 0; ck < 32; ck++) {
        __nv_bfloat16* buf = (__nv_bfloat16*)sm + (ck & 1)*BUF_AT;
        __nv_bfloat16* dhi = buf + isB*6144 + row*LDA16;
        split_store16(pre, dhi, dhi + 3072);
        __syncthreads();
        if (ck < 31) {
            const float* p = gsrc + (ck + 1)*16;
            #pragma unroll
            for (int i = 0; i < 4; i++) pre[i] = *(const float4*)(p + i*4);
        }
        __nv_bfloat16* sA = buf;
        __nv_bfloat16* sB = buf + 6144;
        FragA ah[4], al[4];
        #pragma unroll
        for (int i = 0; i < 4; i++) {
            wmma::load_matrix_sync(ah[i], sA + (wm + i*16)*LDA16, LDA16);
            wmma::load_matrix_sync(al[i], sA + 3072 + (wm + i*16)*LDA16, LDA16);
        }
        #pragma unroll
        for (int j = 0; j < 2; j++) {
            FragB bh, bl;
            wmma::load_matrix_sync(bh, sB + (wn + j*16)*LDA16, LDA16);
            wmma::load_matrix_sync(bl, sB + 3072 + (wn + j*16)*LDA16, LDA16);
            #pragma unroll
            for (int i = 0; i < 4; i++) {
                wmma::mma_sync(acc[i][j], ah[i], bh, acc[i][j]);
                wmma::mma_sync(acc[i][j], ah[i], bl, acc[i][j]);
                wmma::mma_sync(acc[i][j], al[i], bh, acc[i][j]);
            }
        }
    }
    __syncthreads();
    #pragma unroll
    for (int i = 0; i < 4; i++)
        #pragma unroll
        for (int j = 0; j < 2; j++)
            wmma::store_matrix_sync(stage + (wm + i*16)*LDS + wn + j*16,
                                    acc[i][j], LDS, wmma::mem_row_major);
    __syncthreads();
}

// ============== Y = X Aop^T  (V GEMM eliminated algebraically) ==============
__global__ __launch_bounds__(256, 2) void y_mma_kernel() {
    extern __shared__ char sm[];
    float* stage = (float*)sm;

    int ntile = blockIdx.x;
    int t = blockIdx.y;
    int n0 = ntile*128, m0 = t*128;
    const float* W = g_Aop;
    float* C       = g_Q;

    int tid = threadIdx.x, wid = tid >> 5;
    int wm = (wid & 1) * 64, wn = (wid >> 1) * 32;
    int isB = tid >> 7;
    int ak = tid >> 3, ab0 = (tid & 7) * 16;
    int brow = tid & 127;

    FragC acc[4][2];
    #pragma unroll
    for (int i = 0; i < 4; i++)
        #pragma unroll
        for (int j = 0; j < 2; j++)
            wmma::fill_fragment(acc[i][j], 0.0f);

    float4 pre[4];
    if (isB) {
        const float* p = W + (size_t)(n0 + brow)*HH;
        #pragma unroll
        for (int i = 0; i < 4; i++) pre[i] = *(const float4*)(p + i*4);
    } else {
        const float* p = g_bufB + ((size_t)t*HH + ak)*BB + ab0;
        #pragma unroll
        for (int i = 0; i < 4; i++) pre[i] = *(const float4*)(p + i*4);
    }

    for (int ck = 0; ck < 32; ck++) {
        __nv_bfloat16* buf = (__nv_bfloat16*)sm + (ck & 1)*BUF_VY;
        if (isB) {
            __nv_bfloat16* dhi = buf + 4352 + brow*LDA16;
            split_store16(pre, dhi, dhi + 3072);
        } else {
            __nv_bfloat16* dhi = buf + ak*LDAT + ab0;
            split_store16(pre, dhi, dhi + 2176);
        }
        __syncthreads();
        if (ck < 31) {
            if (isB) {
                const float* p = W + (size_t)(n0 + brow)*HH + (ck + 1)*16;
                #pragma unroll
                for (int i = 0; i < 4; i++) pre[i] = *(const float4*)(p + i*4);
            } else {
                const float* p = g_bufB + ((size_t)t*HH + (ck + 1)*16 + ak)*BB + ab0;
                #pragma unroll
                for (int i = 0; i < 4; i++) pre[i] = *(const float4*)(p + i*4);
            }
        }
        __nv_bfloat16* sA = buf;
        __nv_bfloat16* sB = buf + 4352;
        FragAc ah[4], al[4];
        #pragma unroll
        for (int i = 0; i < 4; i++) {
            wmma::load_matrix_sync(ah[i], sA + wm + i*16, LDAT);
            wmma::load_matrix_sync(al[i], sA + 2176 + wm + i*16, LDAT);
        }
        #pragma unroll
        for (int j = 0; j < 2; j++) {
            FragB bh, bl;
            wmma::load_matrix_sync(bh, sB + (wn + j*16)*LDA16, LDA16);
            wmma::load_matrix_sync(bl, sB + 3072 + (wn + j*16)*LDA16, LDA16);
            #pragma unroll
            for (int i = 0; i < 4; i++) {
                wmma::mma_sync(acc[i][j], ah[i], bh, acc[i][j]);
                wmma::mma_sync(acc[i][j], ah[i], bl, acc[i][j]);
                wmma::mma_sync(acc[i][j], al[i], bh, acc[i][j]);
            }
        }
    }
    __syncthreads();
    #pragma unroll
    for (int i = 0; i < 4; i++)
        #pragma unroll
        for (int j = 0; j < 2; j++)
            wmma::store_matrix_sync(stage + (wm + i*16)*LDS + wn + j*16,
                                    acc[i][j], LDS, wmma::mem_row_major);
    __syncthreads();

    int c = tid & 127, rr = tid >> 7;
    for (int r2 = rr; r2 < 128; r2 += 2)
        C[(size_t)(m0 + r2)*HH + n0 + c] = stage[r2*LDS + c];
}

// ============== attention: sigmoid((Y.Xt + c1 + c2 + c0)*s) column sums ======
__global__ __launch_bounds__(256, 2) void attn_mma_kernel() {
    extern __shared__ char sm[];
    float* stage = (float*)sm;
    __shared__ float c1row[128];
    int b  = blockIdx.z;
    int n0 = blockIdx.x * 128;
    int m0 = blockIdx.y * 128;
    int tid = threadIdx.x;

    mma_tile_128_db(g_Q + ((size_t)m0*BB + b)*HH, (size_t)BB*HH,
                    g_K + ((size_t)n0*BB + b)*HH, (size_t)BB*HH, sm, stage);

    if (tid < 128) c1row[tid] = g_c1[(m0 + tid)*BB + b];
    __syncthreads();

    const float scale = 0.04419417382415922f;  // 512^-0.5
    if (tid < 128) {
        float c2v = g_c2[(n0 + tid)*BB + b] + g_cc[0];
        float s = 0.f;
        #pragma unroll 4
        for (int rr = 0; rr < 128; rr++) {
            float lg = stage[rr*LDS + tid] + c1row[rr] + c2v;
            s += 1.0f / (1.0f + __expf(-lg*scale));
        }
        g_wpart[blockIdx.y*(BB*TT) + b*TT + n0 + tid] = s;
    }
}

// ============== tails ==============
__global__ void reduce_w_kernel() {
    int i = blockIdx.x*256 + threadIdx.x;
    g_wsum[i] = g_wpart[i] + g_wpart[BB*TT + i]
              + g_wpart[2*BB*TT + i] + g_wpart[3*BB*TT + i];
}

// z[b,k] = sum_s wsum[b,s] * Xt[s,b,k];  sw[b] = sum_s wsum[b,s]
__global__ __launch_bounds__(128) void zsum_kernel() {
    int kq = blockIdx.x, b = blockIdx.y;
    int k = kq*128 + threadIdx.x;
    float acc = 0.f, sw = 0.f;
    const float* wrow = g_wsum + b*TT;
    #pragma unroll 4
    for (int s = 0; s < TT; s++) {
        float w = wrow[s];
        sw += w;
        acc += w * g_K[((size_t)s*BB + b)*HH + k];
    }
    g_z[b*HH + k] = acc;
    if (kq == 0 && threadIdx.x == 0) g_sw[b] = sw;
}

// feat[b,d] = (z[b,:].Wv[d,:] + sw[b]*bv[d]) / TT
__global__ __launch_bounds__(128) void featw_kernel(
        const float* __restrict__ wv, const float* __restrict__ bv) {
    __shared__ float zs[HH];
    int b = blockIdx.y;
    int d = blockIdx.x*128 + threadIdx.x;
    for (int i = threadIdx.x; i < HH; i += 128) zs[i] = g_z[b*HH + i];
    __syncthreads();
    const float* wr = wv + (size_t)d*HH;
    float acc = 0.f;
    #pragma unroll 4
    for (int k = 0; k < HH; k++) acc += zs[k] * wr[k];
    g_feat[b*HH + d] = (acc + g_sw[b]*bv[d]) * (1.0f/TT);
}

__global__ void feat_bn_kernel(const float* __restrict__ g,
                               const float* __restrict__ bb) {
    int d = threadIdx.x;
    float s = 0.f, sq = 0.f;
    for (int b = 0; b < BB; b++) {
        float v = g_feat[b*HH + d];
        s += v; sq += v*v;
    }
    float m = s * (1.0f/BB);
    float rstd = rsqrtf(sq*(1.0f/BB) - m*m + 1e-5f);
    float gg = g[d]*rstd;
    float bo = bb[d] - m*gg;
    for (int b = 0; b < BB; b++)
        g_featn[b*HH + d] = g_feat[b*HH + d]*gg + bo;
}

__global__ void final_lin_kernel(const float* __restrict__ wh,
                                 const float* __restrict__ bh,
                                 float* __restrict__ out) {
    __shared__ float fs[HH];
    int b = blockIdx.x;
    int o = threadIdx.x;
    for (int i = o; i < HH; i += 96) fs[i] = g_featn[b*HH + i];
    __syncthreads();
    float acc = bh[o];
    for (int d = 0; d < HH; d++) acc += fs[d] * wh[o*HH + d];
    out[b*HORZ + o] = acc;
}

// ---------------- launch ------------------------------------------------------
extern "C" void kernel_launch(void* const* d_in, const int* in_sizes, int n_in,
                              void* d_out, int out_size) {
    const float* x        = (const float*)d_in[0];
    const float* conv_w   = (const float*)d_in[1];
    const float* conv_b   = (const float*)d_in[2];
    const float* bn1_g    = (const float*)d_in[3];
    const float* bn1_b    = (const float*)d_in[4];
    const float* beta_enc = (const float*)d_in[5];
    const float* bn2_g    = (const float*)d_in[6];
    const float* bn2_b    = (const float*)d_in[7];
    const float* beta2    = (const float*)d_in[8];
    const float* bn3_g    = (const float*)d_in[9];
    const float* bn3_b    = (const float*)d_in[10];
    const float* beta3    = (const float*)d_in[11];
    const float* wq       = (const float*)d_in[12];
    const float* bq       = (const float*)d_in[13];
    const float* wk       = (const float*)d_in[14];
    const float* bk       = (const float*)d_in[15];
    const float* wv       = (const float*)d_in[16];
    const float* bv       = (const float*)d_in[17];
    const float* bna_g    = (const float*)d_in[18];
    const float* bna_b    = (const float*)d_in[19];
    const float* wh       = (const float*)d_in[20];
    const float* bh       = (const float*)d_in[21];
    float* out = (float*)d_out;

    cudaFuncSetAttribute(y_mma_kernel,    cudaFuncAttributeMaxDynamicSharedMemorySize, SM_DYN);
    cudaFuncSetAttribute(attn_mma_kernel, cudaFuncAttributeMaxDynamicSharedMemorySize, SM_DYN);

    prep_uwc_kernel<<<4, 128>>>(wq, bk, wk, bq);
    aop_kernel<<<dim3(4, 32), 128>>>(wq, wk);

    conv_kernel<<<dim3(NCHN/8, BB), 128>>>(x, conv_w, conv_b);
    chan_stats_kernel<<<NCHN, 256>>>();
    bn1t_kernel<<<dim3(NCHN, 4), 128>>>(bn1_g, bn1_b);

    snn_fused_kernel<<<HH, 128>>>(beta_enc, bn2_g, bn2_b, beta2, bn3_g, bn3_b, beta3);

    xpose_kernel<<<dim3(TT, 16), 256>>>();
    c12_kernel<<<TT, 128>>>();

    y_mma_kernel<<<dim3(4, TT), 256, SM_DYN>>>();
    attn_mma_kernel<<<dim3(TT/128, TT/128, BB), 256, SM_DYN>>>();

    reduce_w_kernel<<<(BB*TT)/256, 256>>>();
    zsum_kernel<<<dim3(4, BB), 128>>>();
    featw_kernel<<<dim3(4, BB), 128>>>(wv, bv);
    feat_bn_kernel<<<1, HH>>>(bna_g, bna_b);
    final_lin_kernel<<<BB, HORZ>>>(wh, bh, out);
}

// round 11
// speedup vs baseline: 1.8313x; 1.0237x over previous
#include <cuda_runtime.h>
#include <cuda_bf16.h>
#include <mma.h>
#include <stdint.h>
#include <math.h>

using namespace nvcuda;

#define TT   512
#define BB   128
#define HH   512
#define CC   32
#define TIN  128
#define NCHN 2048
#define HORZ 96
#define NELEM (TT*BB*HH)

// ---------------- scratch ----------------
__device__ float g_conv[BB*NCHN*TIN];   // (B, 2048, Tin)
__device__ float g_bufA[NELEM];         // X after bn1: (tau, h, b)
__device__ float g_bufB[NELEM];         // mem3:        (tau, h, b)
__device__ __nv_bfloat16 g_Xhi[NELEM];  // mem3 (m = t*BB+b, k) split
__device__ __nv_bfloat16 g_Xlo[NELEM];
__device__ __nv_bfloat16 g_Yhi[NELEM];  // Y = X @ Aop^T (m, n) split
__device__ __nv_bfloat16 g_Ylo[NELEM];
__device__ __nv_bfloat16 g_Aophi[HH*HH], g_Aoplo[HH*HH];
__device__ float g_u[HH], g_w2[HH], g_cc[1];
__device__ float g_c1[TT*BB], g_c2[TT*BB];
__device__ float g_wpart[4*BB*TT];
__device__ float g_wsum[BB*TT];
__device__ float g_z[BB*HH];
__device__ float g_sw[BB];
__device__ float g_feat[BB*HH];
__device__ float g_featn[BB*HH];
__device__ float g_chm[NCHN];
__device__ float g_chr[NCHN];

__device__ __forceinline__ void split1(float x, __nv_bfloat16& hi, __nv_bfloat16& lo) {
    hi = __float2bfloat16(x);
    lo = __float2bfloat16(x - __bfloat162float(hi));
}

// ============== conv / chan_stats / bn1t / snn_fused (R10-identical) =========
__global__ __launch_bounds__(128) void conv_kernel(const float* __restrict__ x,
                            const float* __restrict__ w,
                            const float* __restrict__ cb) {
    __shared__ float xs2[32*136];
    __shared__ float ws4[8*32*4];
    int b  = blockIdx.y;
    int c0 = blockIdx.x * 8;
    int tid = threadIdx.x;

    for (int i = tid; i < 130*32; i += 128) {
        int r = i >> 5, ci = i & 31;
        int tt = r - 1;
        xs2[ci*136 + r] = (tt >= 0 && tt < TIN) ? x[(b*TIN + tt)*CC + ci] : 0.0f;
    }
    for (int i = tid; i < 256; i += 128) {
        int cc = i >> 5, ii = i & 31;
        const float* wp = w + (c0 + cc)*96 + ii*3;
        float* d = ws4 + i*4;
        d[0] = wp[0]; d[1] = wp[1]; d[2] = wp[2]; d[3] = 0.0f;
    }
    __syncthreads();

    int ccq = tid >> 5;
    int t4  = tid & 31;
    int t0  = t4 * 4;
    int cA = ccq*2, cB = ccq*2 + 1;

    float acc[2][4];
    acc[0][0] = acc[0][1] = acc[0][2] = acc[0][3] = cb[c0 + cA];
    acc[1][0] = acc[1][1] = acc[1][2] = acc[1][3] = cb[c0 + cB];

    #pragma unroll
    for (int i = 0; i < 32; i++) {
        float4 xa = *(const float4*)&xs2[i*136 + t0];
        float2 xb = *(const float2*)&xs2[i*136 + t0 + 4];
        #pragma unroll
        for (int c2 = 0; c2 < 2; c2++) {
            float4 wv = *(const float4*)&ws4[((ccq*2 + c2)*32 + i)*4];
            acc[c2][0] += wv.x*xa.x + wv.y*xa.y + wv.z*xa.z;
            acc[c2][1] += wv.x*xa.y + wv.y*xa.z + wv.z*xa.w;
            acc[c2][2] += wv.x*xa.z + wv.y*xa.w + wv.z*xb.x;
            acc[c2][3] += wv.x*xa.w + wv.y*xb.x + wv.z*xb.y;
        }
    }
    *(float4*)&g_conv[((size_t)b*NCHN + c0 + cA)*TIN + t0] =
        make_float4(acc[0][0], acc[0][1], acc[0][2], acc[0][3]);
    *(float4*)&g_conv[((size_t)b*NCHN + c0 + cB)*TIN + t0] =
        make_float4(acc[1][0], acc[1][1], acc[1][2], acc[1][3]);
}

__global__ void chan_stats_kernel() {
    int c = blockIdx.x;
    int tid = threadIdx.x;
    float s = 0.f, sq = 0.f;
    for (int i = tid; i < BB*TIN; i += 256) {
        int b = i >> 7, t = i & 127;
        float v = g_conv[(b*NCHN + c)*TIN + t];
        s += v; sq += v*v;
    }
    __shared__ float ss[256], sqs[256];
    ss[tid] = s; sqs[tid] = sq;
    __syncthreads();
    for (int o = 128; o > 0; o >>= 1) {
        if (tid < o) { ss[tid] += ss[tid+o]; sqs[tid] += sqs[tid+o]; }
        __syncthreads();
    }
    if (tid == 0) {
        float m   = ss[0] * (1.0f/(BB*TIN));
        float var = sqs[0] * (1.0f/(BB*TIN)) - m*m;
        g_chm[c] = m;
        g_chr[c] = rsqrtf(var + 1e-5f);
    }
}

__global__ void bn1t_kernel(const float* __restrict__ g,
                            const float* __restrict__ bb) {
    __shared__ float sm_t[128*33];
    int c = blockIdx.x, bq = blockIdx.y;
    int ts = c >> 9, h = c & 511;
    int tid = threadIdx.x;
    float chm = g_chm[c], chr = g_chr[c], gg = g[c], bo = bb[c];
    int bl = tid >> 2, tq = tid & 3;
    int b = bq*32 + bl;
    const float* src = g_conv + ((size_t)b*NCHN + c)*TIN;
    #pragma unroll
    for (int it = 0; it < 8; it++) {
        int tbase = (tq + it*4)*4;
        float4 v = *(const float4*)(src + tbase);
        sm_t[(tbase+0)*33 + bl] = (v.x - chm) * chr * gg + bo;
        sm_t[(tbase+1)*33 + bl] = (v.y - chm) * chr * gg + bo;
        sm_t[(tbase+2)*33 + bl] = (v.z - chm) * chr * gg + bo;
        sm_t[(tbase+3)*33 + bl] = (v.w - chm) * chr * gg + bo;
    }
    __syncthreads();
    int bl2 = tid & 31, tch = tid >> 5;
    #pragma unroll 8
    for (int it = 0; it < 32; it++) {
        int t = tch*32 + it;
        g_bufA[((size_t)(t*4 + ts)*HH + h)*BB + bq*32 + bl2] = sm_t[t*33 + bl2];
    }
}

__global__ __launch_bounds__(128) void snn_fused_kernel(
        const float* __restrict__ be,  const float* __restrict__ g2a,
        const float* __restrict__ b2a, const float* __restrict__ be2,
        const float* __restrict__ g3a, const float* __restrict__ b3a,
        const float* __restrict__ be3) {
    __shared__ int scnt[2][2][4];
    int tid = threadIdx.x;
    int h = blockIdx.x;
    int warp = tid >> 5, lane = tid & 31;
    float beta1 = fminf(fmaxf(be[h],  0.0f), 0.99f);
    float beta2 = fminf(fmaxf(be2[h], 0.0f), 0.99f);
    float beta3 = fminf(fmaxf(be3[h], 0.0f), 0.99f);
    float g2 = g2a[h], b2 = b2a[h], g3 = g3a[h], b3 = b3a[h];
    const float* src = g_bufA + (size_t)h*BB + tid;
    float* dst       = g_bufB + (size_t)h*BB + tid;
    float mem1 = 0.f, mem2 = 0.f, mem3 = 0.f;

    float cur[4];
    #pragma unroll
    for (int j = 0; j < 4; j++) cur[j] = src[(size_t)j*HH*BB];

    for (int t0 = 0; t0 < TT; t0 += 4) {
        float nxt[4] = {0.f, 0.f, 0.f, 0.f};
        if (t0 + 4 < TT) {
            #pragma unroll
            for (int j = 0; j < 4; j++) nxt[j] = src[(size_t)(t0+4+j)*HH*BB];
        }
        #pragma unroll
        for (int j = 0; j < 4; j++) {
            int t = t0 + j, par = t & 1;
            float reset = (mem1 > 1.0f) ? 1.0f : 0.0f;
            mem1 = beta1*mem1 + cur[j] - reset;
            float s1 = (mem1 > 1.0f) ? 1.0f : 0.0f;
            unsigned bal = __ballot_sync(0xffffffffu, mem1 > 1.0f);
            if (lane == 0) scnt[0][par][warp] = __popc(bal);
            __syncthreads();
            float sq = (float)(scnt[0][par][0] + scnt[0][par][1]
                             + scnt[0][par][2] + scnt[0][par][3]);
            float m    = sq * (1.0f/BB);
            float rstd = rsqrtf(sq*(1.0f/BB) - m*m + 1e-5f);
            float gg = g2*rstd;
            float bo = b2 - m*gg;
            float h2 = s1*gg + bo;

            float reset2 = (mem2 > 1.0f) ? 1.0f : 0.0f;
            mem2 = beta2*mem2 + h2 - reset2;
            float s2 = (mem2 > 1.0f) ? 1.0f : 0.0f;
            bal = __ballot_sync(0xffffffffu, mem2 > 1.0f);
            if (lane == 0) scnt[1][par][warp] = __popc(bal);
            __syncthreads();
            sq = (float)(scnt[1][par][0] + scnt[1][par][1]
                       + scnt[1][par][2] + scnt[1][par][3]);
            m    = sq * (1.0f/BB);
            rstd = rsqrtf(sq*(1.0f/BB) - m*m + 1e-5f);
            gg = g3*rstd;
            bo = b3 - m*gg;
            float h3 = s2*gg + bo;

            float reset3 = (mem3 > 1.0f) ? 1.0f : 0.0f;
            mem3 = beta3*mem3 + h3 - reset3;
            dst[(size_t)t*HH*BB] = mem3;
        }
        #pragma unroll
        for (int j = 0; j < 4; j++) cur[j] = nxt[j];
    }
}

// ============== prep kernels ==============
__global__ void prep_uwc_kernel(const float* __restrict__ wq,
                                const float* __restrict__ bk,
                                const float* __restrict__ wk,
                                const float* __restrict__ bq) {
    int k = blockIdx.x*128 + threadIdx.x;
    float su = 0.f, sw = 0.f;
    for (int n = 0; n < HH; n++) {
        su += wq[n*HH + k] * bk[n];
        sw += wk[n*HH + k] * bq[n];
    }
    g_u[k] = su; g_w2[k] = sw;
    if (blockIdx.x == 0 && threadIdx.x == 0) {
        float c = 0.f;
        for (int n = 0; n < HH; n++) c += bq[n]*bk[n];
        g_cc[0] = c;
    }
}

// Aop[n][k] = sum_j Wq[j][k]*Wk[j][n], emitted pre-split bf16 hi/lo
__global__ void aop_kernel(const float* __restrict__ wq,
                           const float* __restrict__ wk) {
    int k  = blockIdx.x*128 + threadIdx.x;
    int n0 = blockIdx.y*16;
    float acc[16] = {};
    for (int j = 0; j < HH; j++) {
        float a = wq[j*HH + k];
        #pragma unroll
        for (int i = 0; i < 16; i++)
            acc[i] += a * wk[j*HH + n0 + i];
    }
    #pragma unroll
    for (int i = 0; i < 16; i++) {
        __nv_bfloat16 hi, lo;
        split1(acc[i], hi, lo);
        g_Aophi[(n0+i)*HH + k] = hi;
        g_Aoplo[(n0+i)*HH + k] = lo;
    }
}

// transpose+split: mem3 (t,h,b) -> Xhi/Xlo (m=t*BB+b, k=h)
__global__ __launch_bounds__(256) void xpose_kernel() {
    __shared__ float smt[32][129];
    int t = blockIdx.x, h0 = blockIdx.y*32;
    int tid = threadIdx.x;
    int b = tid & 127, hq = tid >> 7;
    #pragma unroll
    for (int i = 0; i < 16; i++) {
        int hh2 = hq*16 + i;
        smt[hh2][b] = g_bufB[((size_t)t*HH + h0 + hh2)*BB + b];
    }
    __syncthreads();
    int b2 = tid & 127, half = tid >> 7;
    __nv_bfloat16 hi16[16], lo16[16];
    #pragma unroll
    for (int i = 0; i < 16; i++)
        split1(smt[half*16 + i][b2], hi16[i], lo16[i]);
    size_t base = ((size_t)t*BB + b2)*HH + h0 + half*16;
    *(uint4*)&g_Xhi[base]     = *(uint4*)&hi16[0];
    *(uint4*)&g_Xhi[base + 8] = *(uint4*)&hi16[8];
    *(uint4*)&g_Xlo[base]     = *(uint4*)&lo16[0];
    *(uint4*)&g_Xlo[base + 8] = *(uint4*)&lo16[8];
}

__global__ __launch_bounds__(128) void c12_kernel() {
    __shared__ float su[HH], sw[HH];
    int t = blockIdx.x, tid = threadIdx.x;
    for (int i = tid; i < HH; i += 128) { su[i] = g_u[i]; sw[i] = g_w2[i]; }
    __syncthreads();
    float c1 = 0.f, c2 = 0.f;
    const float* src = g_bufB + (size_t)t*HH*BB + tid;
    #pragma unroll 4
    for (int h = 0; h < HH; h++) {
        float v = src[(size_t)h*BB];
        c1 += v * su[h];
        c2 += v * sw[h];
    }
    g_c1[t*BB + tid] = c1;
    g_c2[t*BB + tid] = c2;
}

// ============== wmma GEMM: double-buffered, BK=16, PRE-SPLIT operands =======
#define LDA16 24
#define LDS   132
#define SM_DYN (128*LDS*4)
#define BUF_AT 12288

typedef wmma::fragment<wmma::matrix_a, 16,16,16, __nv_bfloat16, wmma::row_major> FragA;
typedef wmma::fragment<wmma::matrix_b, 16,16,16, __nv_bfloat16, wmma::col_major> FragB;
typedef wmma::fragment<wmma::accumulator, 16,16,16, float> FragC;

// A,B 128 rows x 512 k, bf16 hi/lo row-major. Smem layout identical to R10.
__device__ __forceinline__ void mma_tile_pre(
        const __nv_bfloat16* Ahi, const __nv_bfloat16* Alo, size_t sA,
        const __nv_bfloat16* Bhi, const __nv_bfloat16* Blo, size_t sB,
        char* sm, float* stage) {
    int tid = threadIdx.x, wid = tid >> 5;
    int wm = (wid & 1) * 64, wn = (wid >> 1) * 32;
    int isB = tid >> 7;
    int row = tid & 127;
    const __nv_bfloat16* ghi = isB ? (Bhi + (size_t)row*sB) : (Ahi + (size_t)row*sA);
    const __nv_bfloat16* glo = isB ? (Blo + (size_t)row*sB) : (Alo + (size_t)row*sA);

    FragC acc[4][2];
    #pragma unroll
    for (int i = 0; i < 4; i++)
        #pragma unroll
        for (int j = 0; j < 2; j++)
            wmma::fill_fragment(acc[i][j], 0.0f);

    uint4 ph0 = *(const uint4*)(ghi);
    uint4 ph1 = *(const uint4*)(ghi + 8);
    uint4 pl0 = *(const uint4*)(glo);
    uint4 pl1 = *(const uint4*)(glo + 8);

    for (int ck = 0; ck < 32; ck++) {
        __nv_bfloat16* buf = (__nv_bfloat16*)sm + (ck & 1)*BUF_AT;
        __nv_bfloat16* dhi = buf + isB*6144 + row*LDA16;
        *(uint4*)dhi              = ph0;
        *(uint4*)(dhi + 8)        = ph1;
        *(uint4*)(dhi + 3072)     = pl0;
        *(uint4*)(dhi + 3072 + 8) = pl1;
        __syncthreads();
        if (ck < 31) {
            ph0 = *(const uint4*)(ghi + (ck+1)*16);
            ph1 = *(const uint4*)(ghi + (ck+1)*16 + 8);
            pl0 = *(const uint4*)(glo + (ck+1)*16);
            pl1 = *(const uint4*)(glo + (ck+1)*16 + 8);
        }
        __nv_bfloat16* sA_ = buf;
        __nv_bfloat16* sB_ = buf + 6144;
        FragA ah[4], al[4];
        #pragma unroll
        for (int i = 0; i < 4; i++) {
            wmma::load_matrix_sync(ah[i], sA_ + (wm + i*16)*LDA16, LDA16);
            wmma::load_matrix_sync(al[i], sA_ + 3072 + (wm + i*16)*LDA16, LDA16);
        }
        #pragma unroll
        for (int j = 0; j < 2; j++) {
            FragB bh, bl;
            wmma::load_matrix_sync(bh, sB_ + (wn + j*16)*LDA16, LDA16);
            wmma::load_matrix_sync(bl, sB_ + 3072 + (wn + j*16)*LDA16, LDA16);
            #pragma unroll
            for (int i = 0; i < 4; i++) {
                wmma::mma_sync(acc[i][j], ah[i], bh, acc[i][j]);
                wmma::mma_sync(acc[i][j], ah[i], bl, acc[i][j]);
                wmma::mma_sync(acc[i][j], al[i], bh, acc[i][j]);
            }
        }
    }
    __syncthreads();
    #pragma unroll
    for (int i = 0; i < 4; i++)
        #pragma unroll
        for (int j = 0; j < 2; j++)
            wmma::store_matrix_sync(stage + (wm + i*16)*LDS + wn + j*16,
                                    acc[i][j], LDS, wmma::mem_row_major);
    __syncthreads();
}

// ============== Y = X Aop^T, output pre-split bf16 ==============
__global__ __launch_bounds__(256, 2) void y_mma_kernel() {
    extern __shared__ char sm[];
    float* stage = (float*)sm;
    int n0 = blockIdx.x*128, m0 = blockIdx.y*128;
    int tid = threadIdx.x;

    mma_tile_pre(g_Xhi + (size_t)m0*HH,   g_Xlo + (size_t)m0*HH,   HH,
                 g_Aophi + (size_t)n0*HH, g_Aoplo + (size_t)n0*HH, HH,
                 sm, stage);

    int c = tid & 127, rr = tid >> 7;
    for (int r2 = rr; r2 < 128; r2 += 2) {
        __nv_bfloat16 hi, lo;
        split1(stage[r2*LDS + c], hi, lo);
        g_Yhi[(size_t)(m0 + r2)*HH + n0 + c] = hi;
        g_Ylo[(size_t)(m0 + r2)*HH + n0 + c] = lo;
    }
}

// ============== attention: sigmoid((Y.X + c1 + c2 + c0)*s) column sums =======
__global__ __launch_bounds__(256, 2) void attn_mma_kernel() {
    extern __shared__ char sm[];
    float* stage = (float*)sm;
    __shared__ float c1row[128];
    int b  = blockIdx.z;
    int n0 = blockIdx.x * 128;
    int m0 = blockIdx.y * 128;
    int tid = threadIdx.x;

    mma_tile_pre(g_Yhi + ((size_t)m0*BB + b)*HH, g_Ylo + ((size_t)m0*BB + b)*HH, (size_t)BB*HH,
                 g_Xhi + ((size_t)n0*BB + b)*HH, g_Xlo + ((size_t)n0*BB + b)*HH, (size_t)BB*HH,
                 sm, stage);

    if (tid < 128) c1row[tid] = g_c1[(m0 + tid)*BB + b];
    __syncthreads();

    const float scale = 0.04419417382415922f;  // 512^-0.5
    if (tid < 128) {
        float c2v = g_c2[(n0 + tid)*BB + b] + g_cc[0];
        float s = 0.f;
        #pragma unroll 4
        for (int rr = 0; rr < 128; rr++) {
            float lg = stage[rr*LDS + tid] + c1row[rr] + c2v;
            s += 1.0f / (1.0f + __expf(-lg*scale));
        }
        g_wpart[blockIdx.y*(BB*TT) + b*TT + n0 + tid] = s;
    }
}

// ============== tails ==============
__global__ void reduce_w_kernel() {
    int i = blockIdx.x*256 + threadIdx.x;
    g_wsum[i] = g_wpart[i] + g_wpart[BB*TT + i]
              + g_wpart[2*BB*TT + i] + g_wpart[3*BB*TT + i];
}

// z[b,k] = sum_s wsum[b,s] * X[s,b,k] (X reconstructed hi+lo); sw[b] = sum_s w
__global__ __launch_bounds__(128) void zsum_kernel() {
    int kq = blockIdx.x, b = blockIdx.y;
    int k = kq*128 + threadIdx.x;
    float acc = 0.f, sw = 0.f;
    const float* wrow = g_wsum + b*TT;
    #pragma unroll 4
    for (int s = 0; s < TT; s++) {
        float w = wrow[s];
        sw += w;
        size_t idx = ((size_t)s*BB + b)*HH + k;
        float xv = __bfloat162float(g_Xhi[idx]) + __bfloat162float(g_Xlo[idx]);
        acc += w * xv;
    }
    g_z[b*HH + k] = acc;
    if (kq == 0 && threadIdx.x == 0) g_sw[b] = sw;
}

__global__ __launch_bounds__(128) void featw_kernel(
        const float* __restrict__ wv, const float* __restrict__ bv) {
    __shared__ float zs[HH];
    int b = blockIdx.y;
    int d = blockIdx.x*128 + threadIdx.x;
    for (int i = threadIdx.x; i < HH; i += 128) zs[i] = g_z[b*HH + i];
    __syncthreads();
    const float* wr = wv + (size_t)d*HH;
    float acc = 0.f;
    #pragma unroll 4
    for (int k = 0; k < HH; k++) acc += zs[k] * wr[k];
    g_feat[b*HH + d] = (acc + g_sw[b]*bv[d]) * (1.0f/TT);
}

__global__ void feat_bn_kernel(const float* __restrict__ g,
                               const float* __restrict__ bb) {
    int d = threadIdx.x;
    float s = 0.f, sq = 0.f;
    for (int b = 0; b < BB; b++) {
        float v = g_feat[b*HH + d];
        s += v; sq += v*v;
    }
    float m = s * (1.0f/BB);
    float rstd = rsqrtf(sq*(1.0f/BB) - m*m + 1e-5f);
    float gg = g[d]*rstd;
    float bo = bb[d] - m*gg;
    for (int b = 0; b < BB; b++)
        g_featn[b*HH + d] = g_feat[b*HH + d]*gg + bo;
}

__global__ void final_lin_kernel(const float* __restrict__ wh,
                                 const float* __restrict__ bh,
                                 float* __restrict__ out) {
    __shared__ float fs[HH];
    int b = blockIdx.x;
    int o = threadIdx.x;
    for (int i = o; i < HH; i += 96) fs[i] = g_featn[b*HH + i];
    __syncthreads();
    float acc = bh[o];
    for (int d = 0; d < HH; d++) acc += fs[d] * wh[o*HH + d];
    out[b*HORZ + o] = acc;
}

// ---------------- launch ------------------------------------------------------
extern "C" void kernel_launch(void* const* d_in, const int* in_sizes, int n_in,
                              void* d_out, int out_size) {
    const float* x        = (const float*)d_in[0];
    const float* conv_w   = (const float*)d_in[1];
    const float* conv_b   = (const float*)d_in[2];
    const float* bn1_g    = (const float*)d_in[3];
    const float* bn1_b    = (const float*)d_in[4];
    const float* beta_enc = (const float*)d_in[5];
    const float* bn2_g    = (const float*)d_in[6];
    const float* bn2_b    = (const float*)d_in[7];
    const float* beta2    = (const float*)d_in[8];
    const float* bn3_g    = (const float*)d_in[9];
    const float* bn3_b    = (const float*)d_in[10];
    const float* beta3    = (const float*)d_in[11];
    const float* wq       = (const float*)d_in[12];
    const float* bq       = (const float*)d_in[13];
    const float* wk       = (const float*)d_in[14];
    const float* bk       = (const float*)d_in[15];
    const float* wv       = (const float*)d_in[16];
    const float* bv       = (const float*)d_in[17];
    const float* bna_g    = (const float*)d_in[18];
    const float* bna_b    = (const float*)d_in[19];
    const float* wh       = (const float*)d_in[20];
    const float* bh       = (const float*)d_in[21];
    float* out = (float*)d_out;

    cudaFuncSetAttribute(y_mma_kernel,    cudaFuncAttributeMaxDynamicSharedMemorySize, SM_DYN);
    cudaFuncSetAttribute(attn_mma_kernel, cudaFuncAttributeMaxDynamicSharedMemorySize, SM_DYN);

    prep_uwc_kernel<<<4, 128>>>(wq, bk, wk, bq);
    aop_kernel<<<dim3(4, 32), 128>>>(wq, wk);

    conv_kernel<<<dim3(NCHN/8, BB), 128>>>(x, conv_w, conv_b);
    chan_stats_kernel<<<NCHN, 256>>>();
    bn1t_kernel<<<dim3(NCHN, 4), 128>>>(bn1_g, bn1_b);

    snn_fused_kernel<<<HH, 128>>>(beta_enc, bn2_g, bn2_b, beta2, bn3_g, bn3_b, beta3);

    xpose_kernel<<<dim3(TT, 16), 256>>>();
    c12_kernel<<<TT, 128>>>();

    y_mma_kernel<<<dim3(4, TT), 256, SM_DYN>>>();
    attn_mma_kernel<<<dim3(TT/128, TT/128, BB), 256, SM_DYN>>>();

    reduce_w_kernel<<<(BB*TT)/256, 256>>>();
    zsum_kernel<<<dim3(4, BB), 128>>>();
    featw_kernel<<<dim3(4, BB), 128>>>(wv, bv);
    feat_bn_kernel<<<1, HH>>>(bna_g, bna_b);
    final_lin_kernel<<<BB, HORZ>>>(wh, bh, out);
}

// round 12
// speedup vs baseline: 2.0243x; 1.1054x over previous
#include <cuda_runtime.h>
#include <cuda_bf16.h>
#include <mma.h>
#include <stdint.h>
#include <math.h>

using namespace nvcuda;

#define TT   512
#define BB   128
#define HH   512
#define CC   32
#define TIN  128
#define NCHN 2048
#define HORZ 96
#define NELEM (TT*BB*HH)

// ---------------- scratch ----------------
__device__ float g_conv[BB*NCHN*TIN];   // (B, 2048, Tin)
__device__ float g_bufA[NELEM];         // X after bn1: (tau, h, b)
__device__ float g_bufB[NELEM];         // mem3:        (tau, h, b)
__device__ __nv_bfloat16 g_Xhi[NELEM];  // mem3 (m = t*BB+b, k) split
__device__ __nv_bfloat16 g_Xlo[NELEM];
__device__ __nv_bfloat16 g_Yhi[NELEM];  // Y = X @ Aop^T (m, n), hi only
__device__ __nv_bfloat16 g_Aophi[HH*HH], g_Aoplo[HH*HH];
__device__ float g_u[HH], g_w2[HH], g_cc[1];
__device__ float g_c1[TT*BB], g_c2[TT*BB];
__device__ float g_wpart[4*BB*TT];
__device__ float g_wsum[BB*TT];
__device__ float g_z[BB*HH];
__device__ float g_sw[BB];
__device__ float g_feat[BB*HH];
__device__ float g_featn[BB*HH];
__device__ float g_chm[NCHN];
__device__ float g_chr[NCHN];

__device__ __forceinline__ void split1(float x, __nv_bfloat16& hi, __nv_bfloat16& lo) {
    hi = __float2bfloat16(x);
    lo = __float2bfloat16(x - __bfloat162float(hi));
}

// ============== conv: 16 channels/block, per-output arithmetic identical =====
__global__ __launch_bounds__(128) void conv_kernel(const float* __restrict__ x,
                            const float* __restrict__ w,
                            const float* __restrict__ cb) {
    __shared__ float xs2[32*136];
    __shared__ float ws4[16*32*4];
    int b  = blockIdx.y;
    int c0 = blockIdx.x * 16;
    int tid = threadIdx.x;

    for (int i = tid; i < 130*32; i += 128) {
        int r = i >> 5, ci = i & 31;
        int tt = r - 1;
        xs2[ci*136 + r] = (tt >= 0 && tt < TIN) ? x[(b*TIN + tt)*CC + ci] : 0.0f;
    }
    for (int i = tid; i < 512; i += 128) {
        int cc = i >> 5, ii = i & 31;
        const float* wp = w + (c0 + cc)*96 + ii*3;
        float* d = ws4 + i*4;
        d[0] = wp[0]; d[1] = wp[1]; d[2] = wp[2]; d[3] = 0.0f;
    }
    __syncthreads();

    int ccq = tid >> 5;          // 0..3 -> 4 channels each
    int t4  = tid & 31;
    int t0  = t4 * 4;

    float acc[4][4];
    #pragma unroll
    for (int c2 = 0; c2 < 4; c2++) {
        float bias = cb[c0 + ccq*4 + c2];
        acc[c2][0] = acc[c2][1] = acc[c2][2] = acc[c2][3] = bias;
    }

    #pragma unroll
    for (int i = 0; i < 32; i++) {
        float4 xa = *(const float4*)&xs2[i*136 + t0];
        float2 xb = *(const float2*)&xs2[i*136 + t0 + 4];
        #pragma unroll
        for (int c2 = 0; c2 < 4; c2++) {
            float4 wv = *(const float4*)&ws4[((ccq*4 + c2)*32 + i)*4];
            acc[c2][0] += wv.x*xa.x + wv.y*xa.y + wv.z*xa.z;
            acc[c2][1] += wv.x*xa.y + wv.y*xa.z + wv.z*xa.w;
            acc[c2][2] += wv.x*xa.z + wv.y*xa.w + wv.z*xb.x;
            acc[c2][3] += wv.x*xa.w + wv.y*xb.x + wv.z*xb.y;
        }
    }
    #pragma unroll
    for (int c2 = 0; c2 < 4; c2++)
        *(float4*)&g_conv[((size_t)b*NCHN + c0 + ccq*4 + c2)*TIN + t0] =
            make_float4(acc[c2][0], acc[c2][1], acc[c2][2], acc[c2][3]);
}

__global__ void chan_stats_kernel() {
    int c = blockIdx.x;
    int tid = threadIdx.x;
    float s = 0.f, sq = 0.f;
    for (int i = tid; i < BB*TIN; i += 256) {
        int b = i >> 7, t = i & 127;
        float v = g_conv[(b*NCHN + c)*TIN + t];
        s += v; sq += v*v;
    }
    __shared__ float ss[256], sqs[256];
    ss[tid] = s; sqs[tid] = sq;
    __syncthreads();
    for (int o = 128; o > 0; o >>= 1) {
        if (tid < o) { ss[tid] += ss[tid+o]; sqs[tid] += sqs[tid+o]; }
        __syncthreads();
    }
    if (tid == 0) {
        float m   = ss[0] * (1.0f/(BB*TIN));
        float var = sqs[0] * (1.0f/(BB*TIN)) - m*m;
        g_chm[c] = m;
        g_chr[c] = rsqrtf(var + 1e-5f);
    }
}

__global__ void bn1t_kernel(const float* __restrict__ g,
                            const float* __restrict__ bb) {
    __shared__ float sm_t[128*33];
    int c = blockIdx.x, bq = blockIdx.y;
    int ts = c >> 9, h = c & 511;
    int tid = threadIdx.x;
    float chm = g_chm[c], chr = g_chr[c], gg = g[c], bo = bb[c];
    int bl = tid >> 2, tq = tid & 3;
    int b = bq*32 + bl;
    const float* src = g_conv + ((size_t)b*NCHN + c)*TIN;
    #pragma unroll
    for (int it = 0; it < 8; it++) {
        int tbase = (tq + it*4)*4;
        float4 v = *(const float4*)(src + tbase);
        sm_t[(tbase+0)*33 + bl] = (v.x - chm) * chr * gg + bo;
        sm_t[(tbase+1)*33 + bl] = (v.y - chm) * chr * gg + bo;
        sm_t[(tbase+2)*33 + bl] = (v.z - chm) * chr * gg + bo;
        sm_t[(tbase+3)*33 + bl] = (v.w - chm) * chr * gg + bo;
    }
    __syncthreads();
    int bl2 = tid & 31, tch = tid >> 5;
    #pragma unroll 8
    for (int it = 0; it < 32; it++) {
        int t = tch*32 + it;
        g_bufA[((size_t)(t*4 + ts)*HH + h)*BB + bq*32 + bl2] = sm_t[t*33 + bl2];
    }
}

__global__ __launch_bounds__(128) void snn_fused_kernel(
        const float* __restrict__ be,  const float* __restrict__ g2a,
        const float* __restrict__ b2a, const float* __restrict__ be2,
        const float* __restrict__ g3a, const float* __restrict__ b3a,
        const float* __restrict__ be3) {
    __shared__ int scnt[2][2][4];
    int tid = threadIdx.x;
    int h = blockIdx.x;
    int warp = tid >> 5, lane = tid & 31;
    float beta1 = fminf(fmaxf(be[h],  0.0f), 0.99f);
    float beta2 = fminf(fmaxf(be2[h], 0.0f), 0.99f);
    float beta3 = fminf(fmaxf(be3[h], 0.0f), 0.99f);
    float g2 = g2a[h], b2 = b2a[h], g3 = g3a[h], b3 = b3a[h];
    const float* src = g_bufA + (size_t)h*BB + tid;
    float* dst       = g_bufB + (size_t)h*BB + tid;
    float mem1 = 0.f, mem2 = 0.f, mem3 = 0.f;

    float cur[4];
    #pragma unroll
    for (int j = 0; j < 4; j++) cur[j] = src[(size_t)j*HH*BB];

    for (int t0 = 0; t0 < TT; t0 += 4) {
        float nxt[4] = {0.f, 0.f, 0.f, 0.f};
        if (t0 + 4 < TT) {
            #pragma unroll
            for (int j = 0; j < 4; j++) nxt[j] = src[(size_t)(t0+4+j)*HH*BB];
        }
        #pragma unroll
        for (int j = 0; j < 4; j++) {
            int t = t0 + j, par = t & 1;
            float reset = (mem1 > 1.0f) ? 1.0f : 0.0f;
            mem1 = beta1*mem1 + cur[j] - reset;
            float s1 = (mem1 > 1.0f) ? 1.0f : 0.0f;
            unsigned bal = __ballot_sync(0xffffffffu, mem1 > 1.0f);
            if (lane == 0) scnt[0][par][warp] = __popc(bal);
            __syncthreads();
            float sq = (float)(scnt[0][par][0] + scnt[0][par][1]
                             + scnt[0][par][2] + scnt[0][par][3]);
            float m    = sq * (1.0f/BB);
            float rstd = rsqrtf(sq*(1.0f/BB) - m*m + 1e-5f);
            float gg = g2*rstd;
            float bo = b2 - m*gg;
            float h2 = s1*gg + bo;

            float reset2 = (mem2 > 1.0f) ? 1.0f : 0.0f;
            mem2 = beta2*mem2 + h2 - reset2;
            float s2 = (mem2 > 1.0f) ? 1.0f : 0.0f;
            bal = __ballot_sync(0xffffffffu, mem2 > 1.0f);
            if (lane == 0) scnt[1][par][warp] = __popc(bal);
            __syncthreads();
            sq = (float)(scnt[1][par][0] + scnt[1][par][1]
                       + scnt[1][par][2] + scnt[1][par][3]);
            m    = sq * (1.0f/BB);
            rstd = rsqrtf(sq*(1.0f/BB) - m*m + 1e-5f);
            gg = g3*rstd;
            bo = b3 - m*gg;
            float h3 = s2*gg + bo;

            float reset3 = (mem3 > 1.0f) ? 1.0f : 0.0f;
            mem3 = beta3*mem3 + h3 - reset3;
            dst[(size_t)t*HH*BB] = mem3;
        }
        #pragma unroll
        for (int j = 0; j < 4; j++) cur[j] = nxt[j];
    }
}

// ============== prep kernels ==============
__global__ void prep_uwc_kernel(const float* __restrict__ wq,
                                const float* __restrict__ bk,
                                const float* __restrict__ wk,
                                const float* __restrict__ bq) {
    int k = blockIdx.x*128 + threadIdx.x;
    float su = 0.f, sw = 0.f;
    for (int n = 0; n < HH; n++) {
        su += wq[n*HH + k] * bk[n];
        sw += wk[n*HH + k] * bq[n];
    }
    g_u[k] = su; g_w2[k] = sw;
    if (blockIdx.x == 0 && threadIdx.x == 0) {
        float c = 0.f;
        for (int n = 0; n < HH; n++) c += bq[n]*bk[n];
        g_cc[0] = c;
    }
}

__global__ void aop_kernel(const float* __restrict__ wq,
                           const float* __restrict__ wk) {
    int k  = blockIdx.x*128 + threadIdx.x;
    int n0 = blockIdx.y*16;
    float acc[16] = {};
    for (int j = 0; j < HH; j++) {
        float a = wq[j*HH + k];
        #pragma unroll
        for (int i = 0; i < 16; i++)
            acc[i] += a * wk[j*HH + n0 + i];
    }
    #pragma unroll
    for (int i = 0; i < 16; i++) {
        __nv_bfloat16 hi, lo;
        split1(acc[i], hi, lo);
        g_Aophi[(n0+i)*HH + k] = hi;
        g_Aoplo[(n0+i)*HH + k] = lo;
    }
}

__global__ __launch_bounds__(256) void xpose_kernel() {
    __shared__ float smt[32][129];
    int t = blockIdx.x, h0 = blockIdx.y*32;
    int tid = threadIdx.x;
    int b = tid & 127, hq = tid >> 7;
    #pragma unroll
    for (int i = 0; i < 16; i++) {
        int hh2 = hq*16 + i;
        smt[hh2][b] = g_bufB[((size_t)t*HH + h0 + hh2)*BB + b];
    }
    __syncthreads();
    int b2 = tid & 127, half = tid >> 7;
    __nv_bfloat16 hi16[16], lo16[16];
    #pragma unroll
    for (int i = 0; i < 16; i++)
        split1(smt[half*16 + i][b2], hi16[i], lo16[i]);
    size_t base = ((size_t)t*BB + b2)*HH + h0 + half*16;
    *(uint4*)&g_Xhi[base]     = *(uint4*)&hi16[0];
    *(uint4*)&g_Xhi[base + 8] = *(uint4*)&hi16[8];
    *(uint4*)&g_Xlo[base]     = *(uint4*)&lo16[0];
    *(uint4*)&g_Xlo[base + 8] = *(uint4*)&lo16[8];
}

__global__ __launch_bounds__(128) void c12_kernel() {
    __shared__ float su[HH], sw[HH];
    int t = blockIdx.x, tid = threadIdx.x;
    for (int i = tid; i < HH; i += 128) { su[i] = g_u[i]; sw[i] = g_w2[i]; }
    __syncthreads();
    float c1 = 0.f, c2 = 0.f;
    const float* src = g_bufB + (size_t)t*HH*BB + tid;
    #pragma unroll 4
    for (int h = 0; h < HH; h++) {
        float v = src[(size_t)h*BB];
        c1 += v * su[h];
        c2 += v * sw[h];
    }
    g_c1[t*BB + tid] = c1;
    g_c2[t*BB + tid] = c2;
}

// ============== wmma GEMM: double-buffered, BK=16, pre-split operands =======
#define LDA16 24
#define LDS   132
#define SM_DYN (128*LDS*4)
#define BUF_AT 12288

typedef wmma::fragment<wmma::matrix_a, 16,16,16, __nv_bfloat16, wmma::row_major> FragA;
typedef wmma::fragment<wmma::matrix_b, 16,16,16, __nv_bfloat16, wmma::col_major> FragB;
typedef wmma::fragment<wmma::accumulator, 16,16,16, float> FragC;

// 3-term core (used by y_mma). Layout identical to R11.
__device__ __forceinline__ void mma_tile_pre(
        const __nv_bfloat16* Ahi, const __nv_bfloat16* Alo, size_t sA,
        const __nv_bfloat16* Bhi, const __nv_bfloat16* Blo, size_t sB,
        char* sm, float* stage) {
    int tid = threadIdx.x, wid = tid >> 5;
    int wm = (wid & 1) * 64, wn = (wid >> 1) * 32;
    int isB = tid >> 7;
    int row = tid & 127;
    const __nv_bfloat16* ghi = isB ? (Bhi + (size_t)row*sB) : (Ahi + (size_t)row*sA);
    const __nv_bfloat16* glo = isB ? (Blo + (size_t)row*sB) : (Alo + (size_t)row*sA);

    FragC acc[4][2];
    #pragma unroll
    for (int i = 0; i < 4; i++)
        #pragma unroll
        for (int j = 0; j < 2; j++)
            wmma::fill_fragment(acc[i][j], 0.0f);

    uint4 ph0 = *(const uint4*)(ghi);
    uint4 ph1 = *(const uint4*)(ghi + 8);
    uint4 pl0 = *(const uint4*)(glo);
    uint4 pl1 = *(const uint4*)(glo + 8);

    for (int ck = 0; ck < 32; ck++) {
        __nv_bfloat16* buf = (__nv_bfloat16*)sm + (ck & 1)*BUF_AT;
        __nv_bfloat16* dhi = buf + isB*6144 + row*LDA16;
        *(uint4*)dhi              = ph0;
        *(uint4*)(dhi + 8)        = ph1;
        *(uint4*)(dhi + 3072)     = pl0;
        *(uint4*)(dhi + 3072 + 8) = pl1;
        __syncthreads();
        if (ck < 31) {
            ph0 = *(const uint4*)(ghi + (ck+1)*16);
            ph1 = *(const uint4*)(ghi + (ck+1)*16 + 8);
            pl0 = *(const uint4*)(glo + (ck+1)*16);
            pl1 = *(const uint4*)(glo + (ck+1)*16 + 8);
        }
        __nv_bfloat16* sA_ = buf;
        __nv_bfloat16* sB_ = buf + 6144;
        FragA ah[4], al[4];
        #pragma unroll
        for (int i = 0; i < 4; i++) {
            wmma::load_matrix_sync(ah[i], sA_ + (wm + i*16)*LDA16, LDA16);
            wmma::load_matrix_sync(al[i], sA_ + 3072 + (wm + i*16)*LDA16, LDA16);
        }
        #pragma unroll
        for (int j = 0; j < 2; j++) {
            FragB bh, bl;
            wmma::load_matrix_sync(bh, sB_ + (wn + j*16)*LDA16, LDA16);
            wmma::load_matrix_sync(bl, sB_ + 3072 + (wn + j*16)*LDA16, LDA16);
            #pragma unroll
            for (int i = 0; i < 4; i++) {
                wmma::mma_sync(acc[i][j], ah[i], bh, acc[i][j]);
                wmma::mma_sync(acc[i][j], ah[i], bl, acc[i][j]);
                wmma::mma_sync(acc[i][j], al[i], bh, acc[i][j]);
            }
        }
    }
    __syncthreads();
    #pragma unroll
    for (int i = 0; i < 4; i++)
        #pragma unroll
        for (int j = 0; j < 2; j++)
            wmma::store_matrix_sync(stage + (wm + i*16)*LDS + wn + j*16,
                                    acc[i][j], LDS, wmma::mem_row_major);
    __syncthreads();
}

// 2-term core (attention): A hi-only, B hi+lo.
__device__ __forceinline__ void mma_tile_pre2(
        const __nv_bfloat16* Ahi, size_t sA,
        const __nv_bfloat16* Bhi, const __nv_bfloat16* Blo, size_t sB,
        char* sm, float* stage) {
    int tid = threadIdx.x, wid = tid >> 5;
    int wm = (wid & 1) * 64, wn = (wid >> 1) * 32;
    int isB = tid >> 7;
    int row = tid & 127;
    const __nv_bfloat16* ghi = isB ? (Bhi + (size_t)row*sB) : (Ahi + (size_t)row*sA);
    const __nv_bfloat16* glo = isB ? (Blo + (size_t)row*sB) : (Ahi + (size_t)row*sA);

    FragC acc[4][2];
    #pragma unroll
    for (int i = 0; i < 4; i++)
        #pragma unroll
        for (int j = 0; j < 2; j++)
            wmma::fill_fragment(acc[i][j], 0.0f);

    uint4 ph0 = *(const uint4*)(ghi);
    uint4 ph1 = *(const uint4*)(ghi + 8);
    uint4 pl0, pl1;
    if (isB) { pl0 = *(const uint4*)(glo); pl1 = *(const uint4*)(glo + 8); }

    for (int ck = 0; ck < 32; ck++) {
        __nv_bfloat16* buf = (__nv_bfloat16*)sm + (ck & 1)*BUF_AT;
        __nv_bfloat16* dhi = buf + isB*6144 + row*LDA16;
        *(uint4*)dhi       = ph0;
        *(uint4*)(dhi + 8) = ph1;
        if (isB) {
            *(uint4*)(dhi + 3072)     = pl0;
            *(uint4*)(dhi + 3072 + 8) = pl1;
        }
        __syncthreads();
        if (ck < 31) {
            ph0 = *(const uint4*)(ghi + (ck+1)*16);
            ph1 = *(const uint4*)(ghi + (ck+1)*16 + 8);
            if (isB) {
                pl0 = *(const uint4*)(glo + (ck+1)*16);
                pl1 = *(const uint4*)(glo + (ck+1)*16 + 8);
            }
        }
        __nv_bfloat16* sA_ = buf;
        __nv_bfloat16* sB_ = buf + 6144;
        FragA ah[4];
        #pragma unroll
        for (int i = 0; i < 4; i++)
            wmma::load_matrix_sync(ah[i], sA_ + (wm + i*16)*LDA16, LDA16);
        #pragma unroll
        for (int j = 0; j < 2; j++) {
            FragB bh, bl;
            wmma::load_matrix_sync(bh, sB_ + (wn + j*16)*LDA16, LDA16);
            wmma::load_matrix_sync(bl, sB_ + 3072 + (wn + j*16)*LDA16, LDA16);
            #pragma unroll
            for (int i = 0; i < 4; i++) {
                wmma::mma_sync(acc[i][j], ah[i], bh, acc[i][j]);
                wmma::mma_sync(acc[i][j], ah[i], bl, acc[i][j]);
            }
        }
    }
    __syncthreads();
    #pragma unroll
    for (int i = 0; i < 4; i++)
        #pragma unroll
        for (int j = 0; j < 2; j++)
            wmma::store_matrix_sync(stage + (wm + i*16)*LDS + wn + j*16,
                                    acc[i][j], LDS, wmma::mem_row_major);
    __syncthreads();
}

// ============== Y = X Aop^T, output bf16 hi only ==============
__global__ __launch_bounds__(256, 2) void y_mma_kernel() {
    extern __shared__ char sm[];
    float* stage = (float*)sm;
    int n0 = blockIdx.x*128, m0 = blockIdx.y*128;
    int tid = threadIdx.x;

    mma_tile_pre(g_Xhi + (size_t)m0*HH,   g_Xlo + (size_t)m0*HH,   HH,
                 g_Aophi + (size_t)n0*HH, g_Aoplo + (size_t)n0*HH, HH,
                 sm, stage);

    int c = tid & 127, rr = tid >> 7;
    for (int r2 = rr; r2 < 128; r2 += 2)
        g_Yhi[(size_t)(m0 + r2)*HH + n0 + c] = __float2bfloat16(stage[r2*LDS + c]);
}

// ============== attention: sigmoid((Yhi.(Xhi+Xlo) + c1 + c2 + c0)*s) sums ====
__global__ __launch_bounds__(256, 2) void attn_mma_kernel() {
    extern __shared__ char sm[];
    float* stage = (float*)sm;
    __shared__ float c1row[128];
    int b  = blockIdx.z;
    int n0 = blockIdx.x * 128;
    int m0 = blockIdx.y * 128;
    int tid = threadIdx.x;

    mma_tile_pre2(g_Yhi + ((size_t)m0*BB + b)*HH, (size_t)BB*HH,
                  g_Xhi + ((size_t)n0*BB + b)*HH, g_Xlo + ((size_t)n0*BB + b)*HH,
                  (size_t)BB*HH, sm, stage);

    if (tid < 128) c1row[tid] = g_c1[(m0 + tid)*BB + b];
    __syncthreads();

    const float scale = 0.04419417382415922f;  // 512^-0.5
    if (tid < 128) {
        float c2v = g_c2[(n0 + tid)*BB + b] + g_cc[0];
        float s = 0.f;
        #pragma unroll 4
        for (int rr = 0; rr < 128; rr++) {
            float lg = stage[rr*LDS + tid] + c1row[rr] + c2v;
            s += 1.0f / (1.0f + __expf(-lg*scale));
        }
        g_wpart[blockIdx.y*(BB*TT) + b*TT + n0 + tid] = s;
    }
}

// ============== tails ==============
__global__ void reduce_w_kernel() {
    int i = blockIdx.x*256 + threadIdx.x;
    g_wsum[i] = g_wpart[i] + g_wpart[BB*TT + i]
              + g_wpart[2*BB*TT + i] + g_wpart[3*BB*TT + i];
}

__global__ __launch_bounds__(128) void zsum_kernel() {
    int kq = blockIdx.x, b = blockIdx.y;
    int k = kq*128 + threadIdx.x;
    float acc = 0.f, sw = 0.f;
    const float* wrow = g_wsum + b*TT;
    #pragma unroll 4
    for (int s = 0; s < TT; s++) {
        float w = wrow[s];
        sw += w;
        size_t idx = ((size_t)s*BB + b)*HH + k;
        float xv = __bfloat162float(g_Xhi[idx]) + __bfloat162float(g_Xlo[idx]);
        acc += w * xv;
    }
    g_z[b*HH + k] = acc;
    if (kq == 0 && threadIdx.x == 0) g_sw[b] = sw;
}

__global__ __launch_bounds__(128) void featw_kernel(
        const float* __restrict__ wv, const float* __restrict__ bv) {
    __shared__ float zs[HH];
    int b = blockIdx.y;
    int d = blockIdx.x*128 + threadIdx.x;
    for (int i = threadIdx.x; i < HH; i += 128) zs[i] = g_z[b*HH + i];
    __syncthreads();
    const float* wr = wv + (size_t)d*HH;
    float acc = 0.f;
    #pragma unroll 4
    for (int k = 0; k < HH; k++) acc += zs[k] * wr[k];
    g_feat[b*HH + d] = (acc + g_sw[b]*bv[d]) * (1.0f/TT);
}

__global__ void feat_bn_kernel(const float* __restrict__ g,
                               const float* __restrict__ bb) {
    int d = threadIdx.x;
    float s = 0.f, sq = 0.f;
    for (int b = 0; b < BB; b++) {
        float v = g_feat[b*HH + d];
        s += v; sq += v*v;
    }
    float m = s * (1.0f/BB);
    float rstd = rsqrtf(sq*(1.0f/BB) - m*m + 1e-5f);
    float gg = g[d]*rstd;
    float bo = bb[d] - m*gg;
    for (int b = 0; b < BB; b++)
        g_featn[b*HH + d] = g_feat[b*HH + d]*gg + bo;
}

__global__ void final_lin_kernel(const float* __restrict__ wh,
                                 const float* __restrict__ bh,
                                 float* __restrict__ out) {
    __shared__ float fs[HH];
    int b = blockIdx.x;
    int o = threadIdx.x;
    for (int i = o; i < HH; i += 96) fs[i] = g_featn[b*HH + i];
    __syncthreads();
    float acc = bh[o];
    for (int d = 0; d < HH; d++) acc += fs[d] * wh[o*HH + d];
    out[b*HORZ + o] = acc;
}

// ---------------- launch ------------------------------------------------------
extern "C" void kernel_launch(void* const* d_in, const int* in_sizes, int n_in,
                              void* d_out, int out_size) {
    const float* x        = (const float*)d_in[0];
    const float* conv_w   = (const float*)d_in[1];
    const float* conv_b   = (const float*)d_in[2];
    const float* bn1_g    = (const float*)d_in[3];
    const float* bn1_b    = (const float*)d_in[4];
    const float* beta_enc = (const float*)d_in[5];
    const float* bn2_g    = (const float*)d_in[6];
    const float* bn2_b    = (const float*)d_in[7];
    const float* beta2    = (const float*)d_in[8];
    const float* bn3_g    = (const float*)d_in[9];
    const float* bn3_b    = (const float*)d_in[10];
    const float* beta3    = (const float*)d_in[11];
    const float* wq       = (const float*)d_in[12];
    const float* bq       = (const float*)d_in[13];
    const float* wk       = (const float*)d_in[14];
    const float* bk       = (const float*)d_in[15];
    const float* wv       = (const float*)d_in[16];
    const float* bv       = (const float*)d_in[17];
    const float* bna_g    = (const float*)d_in[18];
    const float* bna_b    = (const float*)d_in[19];
    const float* wh       = (const float*)d_in[20];
    const float* bh       = (const float*)d_in[21];
    float* out = (float*)d_out;

    cudaFuncSetAttribute(y_mma_kernel,    cudaFuncAttributeMaxDynamicSharedMemorySize, SM_DYN);
    cudaFuncSetAttribute(attn_mma_kernel, cudaFuncAttributeMaxDynamicSharedMemorySize, SM_DYN);

    prep_uwc_kernel<<<4, 128>>>(wq, bk, wk, bq);
    aop_kernel<<<dim3(4, 32), 128>>>(wq, wk);

    conv_kernel<<<dim3(NCHN/16, BB), 128>>>(x, conv_w, conv_b);
    chan_stats_kernel<<<NCHN, 256>>>();
    bn1t_kernel<<<dim3(NCHN, 4), 128>>>(bn1_g, bn1_b);

    snn_fused_kernel<<<HH, 128>>>(beta_enc, bn2_g, bn2_b, beta2, bn3_g, bn3_b, beta3);

    xpose_kernel<<<dim3(TT, 16), 256>>>();
    c12_kernel<<<TT, 128>>>();

    y_mma_kernel<<<dim3(4, TT), 256, SM_DYN>>>();
    attn_mma_kernel<<<dim3(TT/128, TT/128, BB), 256, SM_DYN>>>();

    reduce_w_kernel<<<(BB*TT)/256, 256>>>();
    zsum_kernel<<<dim3(4, BB), 128>>>();
    featw_kernel<<<dim3(4, BB), 128>>>(wv, bv);
    feat_bn_kernel<<<1, HH>>>(bna_g, bna_b);
    final_lin_kernel<<<BB, HORZ>>>(wh, bh, out);
}

// round 13
// speedup vs baseline: 2.2641x; 1.1185x over previous
#include <cuda_runtime.h>
#include <cuda_bf16.h>
#include <mma.h>
#include <stdint.h>
#include <math.h>

using namespace nvcuda;

#define TT   512
#define BB   128
#define HH   512
#define CC   32
#define TIN  128
#define NCHN 2048
#define HORZ 96
#define NELEM (TT*BB*HH)

// ---------------- scratch ----------------
__device__ float g_conv[BB*NCHN*TIN];   // (B, 2048, Tin)
__device__ float g_bufA[NELEM];         // X after bn1: (tau, h, b)
__device__ float g_bufB[NELEM];         // mem3:        (tau, h, b)
__device__ __nv_bfloat16 g_Xhi[NELEM];  // mem3 (m = t*BB+b, k) split
__device__ __nv_bfloat16 g_Xlo[NELEM];
__device__ __nv_bfloat16 g_Yhi[NELEM];  // Y = X @ Aop^T (m, n), hi only
__device__ __nv_bfloat16 g_Aophi[HH*HH], g_Aoplo[HH*HH];
__device__ float g_u[HH], g_w2[HH], g_cc[1];
__device__ float g_c1[TT*BB], g_c2[TT*BB];
__device__ float g_wpart[4*BB*TT];
__device__ float g_wsum[BB*TT];
__device__ float g_z[BB*HH];
__device__ float g_sw[BB];
__device__ float g_feat[BB*HH];
__device__ float g_featn[BB*HH];
__device__ float g_chm[NCHN];
__device__ float g_chr[NCHN];

__device__ __forceinline__ void split1(float x, __nv_bfloat16& hi, __nv_bfloat16& lo) {
    hi = __float2bfloat16(x);
    lo = __float2bfloat16(x - __bfloat162float(hi));
}

// ============== conv: 16 channels/block (R12-identical) ==============
__global__ __launch_bounds__(128) void conv_kernel(const float* __restrict__ x,
                            const float* __restrict__ w,
                            const float* __restrict__ cb) {
    __shared__ float xs2[32*136];
    __shared__ float ws4[16*32*4];
    int b  = blockIdx.y;
    int c0 = blockIdx.x * 16;
    int tid = threadIdx.x;

    for (int i = tid; i < 130*32; i += 128) {
        int r = i >> 5, ci = i & 31;
        int tt = r - 1;
        xs2[ci*136 + r] = (tt >= 0 && tt < TIN) ? x[(b*TIN + tt)*CC + ci] : 0.0f;
    }
    for (int i = tid; i < 512; i += 128) {
        int cc = i >> 5, ii = i & 31;
        const float* wp = w + (c0 + cc)*96 + ii*3;
        float* d = ws4 + i*4;
        d[0] = wp[0]; d[1] = wp[1]; d[2] = wp[2]; d[3] = 0.0f;
    }
    __syncthreads();

    int ccq = tid >> 5;
    int t4  = tid & 31;
    int t0  = t4 * 4;

    float acc[4][4];
    #pragma unroll
    for (int c2 = 0; c2 < 4; c2++) {
        float bias = cb[c0 + ccq*4 + c2];
        acc[c2][0] = acc[c2][1] = acc[c2][2] = acc[c2][3] = bias;
    }

    #pragma unroll
    for (int i = 0; i < 32; i++) {
        float4 xa = *(const float4*)&xs2[i*136 + t0];
        float2 xb = *(const float2*)&xs2[i*136 + t0 + 4];
        #pragma unroll
        for (int c2 = 0; c2 < 4; c2++) {
            float4 wv = *(const float4*)&ws4[((ccq*4 + c2)*32 + i)*4];
            acc[c2][0] += wv.x*xa.x + wv.y*xa.y + wv.z*xa.z;
            acc[c2][1] += wv.x*xa.y + wv.y*xa.z + wv.z*xa.w;
            acc[c2][2] += wv.x*xa.z + wv.y*xa.w + wv.z*xb.x;
            acc[c2][3] += wv.x*xa.w + wv.y*xb.x + wv.z*xb.y;
        }
    }
    #pragma unroll
    for (int c2 = 0; c2 < 4; c2++)
        *(float4*)&g_conv[((size_t)b*NCHN + c0 + ccq*4 + c2)*TIN + t0] =
            make_float4(acc[c2][0], acc[c2][1], acc[c2][2], acc[c2][3]);
}

__global__ void chan_stats_kernel() {
    int c = blockIdx.x;
    int tid = threadIdx.x;
    float s = 0.f, sq = 0.f;
    for (int i = tid; i < BB*TIN; i += 256) {
        int b = i >> 7, t = i & 127;
        float v = g_conv[(b*NCHN + c)*TIN + t];
        s += v; sq += v*v;
    }
    __shared__ float ss[256], sqs[256];
    ss[tid] = s; sqs[tid] = sq;
    __syncthreads();
    for (int o = 128; o > 0; o >>= 1) {
        if (tid < o) { ss[tid] += ss[tid+o]; sqs[tid] += sqs[tid+o]; }
        __syncthreads();
    }
    if (tid == 0) {
        float m   = ss[0] * (1.0f/(BB*TIN));
        float var = sqs[0] * (1.0f/(BB*TIN)) - m*m;
        g_chm[c] = m;
        g_chr[c] = rsqrtf(var + 1e-5f);
    }
}

__global__ void bn1t_kernel(const float* __restrict__ g,
                            const float* __restrict__ bb) {
    __shared__ float sm_t[128*33];
    int c = blockIdx.x, bq = blockIdx.y;
    int ts = c >> 9, h = c & 511;
    int tid = threadIdx.x;
    float chm = g_chm[c], chr = g_chr[c], gg = g[c], bo = bb[c];
    int bl = tid >> 2, tq = tid & 3;
    int b = bq*32 + bl;
    const float* src = g_conv + ((size_t)b*NCHN + c)*TIN;
    #pragma unroll
    for (int it = 0; it < 8; it++) {
        int tbase = (tq + it*4)*4;
        float4 v = *(const float4*)(src + tbase);
        sm_t[(tbase+0)*33 + bl] = (v.x - chm) * chr * gg + bo;
        sm_t[(tbase+1)*33 + bl] = (v.y - chm) * chr * gg + bo;
        sm_t[(tbase+2)*33 + bl] = (v.z - chm) * chr * gg + bo;
        sm_t[(tbase+3)*33 + bl] = (v.w - chm) * chr * gg + bo;
    }
    __syncthreads();
    int bl2 = tid & 31, tch = tid >> 5;
    #pragma unroll 8
    for (int it = 0; it < 32; it++) {
        int t = tch*32 + it;
        g_bufA[((size_t)(t*4 + ts)*HH + h)*BB + bq*32 + bl2] = sm_t[t*33 + bl2];
    }
}

__global__ __launch_bounds__(128) void snn_fused_kernel(
        const float* __restrict__ be,  const float* __restrict__ g2a,
        const float* __restrict__ b2a, const float* __restrict__ be2,
        const float* __restrict__ g3a, const float* __restrict__ b3a,
        const float* __restrict__ be3) {
    __shared__ int scnt[2][2][4];
    int tid = threadIdx.x;
    int h = blockIdx.x;
    int warp = tid >> 5, lane = tid & 31;
    float beta1 = fminf(fmaxf(be[h],  0.0f), 0.99f);
    float beta2 = fminf(fmaxf(be2[h], 0.0f), 0.99f);
    float beta3 = fminf(fmaxf(be3[h], 0.0f), 0.99f);
    float g2 = g2a[h], b2 = b2a[h], g3 = g3a[h], b3 = b3a[h];
    const float* src = g_bufA + (size_t)h*BB + tid;
    float* dst       = g_bufB + (size_t)h*BB + tid;
    float mem1 = 0.f, mem2 = 0.f, mem3 = 0.f;

    float cur[4];
    #pragma unroll
    for (int j = 0; j < 4; j++) cur[j] = src[(size_t)j*HH*BB];

    for (int t0 = 0; t0 < TT; t0 += 4) {
        float nxt[4] = {0.f, 0.f, 0.f, 0.f};
        if (t0 + 4 < TT) {
            #pragma unroll
            for (int j = 0; j < 4; j++) nxt[j] = src[(size_t)(t0+4+j)*HH*BB];
        }
        #pragma unroll
        for (int j = 0; j < 4; j++) {
            int t = t0 + j, par = t & 1;
            float reset = (mem1 > 1.0f) ? 1.0f : 0.0f;
            mem1 = beta1*mem1 + cur[j] - reset;
            float s1 = (mem1 > 1.0f) ? 1.0f : 0.0f;
            unsigned bal = __ballot_sync(0xffffffffu, mem1 > 1.0f);
            if (lane == 0) scnt[0][par][warp] = __popc(bal);
            __syncthreads();
            float sq = (float)(scnt[0][par][0] + scnt[0][par][1]
                             + scnt[0][par][2] + scnt[0][par][3]);
            float m    = sq * (1.0f/BB);
            float rstd = rsqrtf(sq*(1.0f/BB) - m*m + 1e-5f);
            float gg = g2*rstd;
            float bo = b2 - m*gg;
            float h2 = s1*gg + bo;

            float reset2 = (mem2 > 1.0f) ? 1.0f : 0.0f;
            mem2 = beta2*mem2 + h2 - reset2;
            float s2 = (mem2 > 1.0f) ? 1.0f : 0.0f;
            bal = __ballot_sync(0xffffffffu, mem2 > 1.0f);
            if (lane == 0) scnt[1][par][warp] = __popc(bal);
            __syncthreads();
            sq = (float)(scnt[1][par][0] + scnt[1][par][1]
                       + scnt[1][par][2] + scnt[1][par][3]);
            m    = sq * (1.0f/BB);
            rstd = rsqrtf(sq*(1.0f/BB) - m*m + 1e-5f);
            gg = g3*rstd;
            bo = b3 - m*gg;
            float h3 = s2*gg + bo;

            float reset3 = (mem3 > 1.0f) ? 1.0f : 0.0f;
            mem3 = beta3*mem3 + h3 - reset3;
            dst[(size_t)t*HH*BB] = mem3;
        }
        #pragma unroll
        for (int j = 0; j < 4; j++) cur[j] = nxt[j];
    }
}

// ============== prep kernels ==============
__global__ void prep_uwc_kernel(const float* __restrict__ wq,
                                const float* __restrict__ bk,
                                const float* __restrict__ wk,
                                const float* __restrict__ bq) {
    int k = blockIdx.x*128 + threadIdx.x;
    float su = 0.f, sw = 0.f;
    for (int n = 0; n < HH; n++) {
        su += wq[n*HH + k] * bk[n];
        sw += wk[n*HH + k] * bq[n];
    }
    g_u[k] = su; g_w2[k] = sw;
    if (blockIdx.x == 0 && threadIdx.x == 0) {
        float c = 0.f;
        for (int n = 0; n < HH; n++) c += bq[n]*bk[n];
        g_cc[0] = c;
    }
}

__global__ void aop_kernel(const float* __restrict__ wq,
                           const float* __restrict__ wk) {
    int k  = blockIdx.x*128 + threadIdx.x;
    int n0 = blockIdx.y*16;
    float acc[16] = {};
    for (int j = 0; j < HH; j++) {
        float a = wq[j*HH + k];
        #pragma unroll
        for (int i = 0; i < 16; i++)
            acc[i] += a * wk[j*HH + n0 + i];
    }
    #pragma unroll
    for (int i = 0; i < 16; i++) {
        __nv_bfloat16 hi, lo;
        split1(acc[i], hi, lo);
        g_Aophi[(n0+i)*HH + k] = hi;
        g_Aoplo[(n0+i)*HH + k] = lo;
    }
}

__global__ __launch_bounds__(256) void xpose_kernel() {
    __shared__ float smt[32][129];
    int t = blockIdx.x, h0 = blockIdx.y*32;
    int tid = threadIdx.x;
    int b = tid & 127, hq = tid >> 7;
    #pragma unroll
    for (int i = 0; i < 16; i++) {
        int hh2 = hq*16 + i;
        smt[hh2][b] = g_bufB[((size_t)t*HH + h0 + hh2)*BB + b];
    }
    __syncthreads();
    int b2 = tid & 127, half = tid >> 7;
    __nv_bfloat16 hi16[16], lo16[16];
    #pragma unroll
    for (int i = 0; i < 16; i++)
        split1(smt[half*16 + i][b2], hi16[i], lo16[i]);
    size_t base = ((size_t)t*BB + b2)*HH + h0 + half*16;
    *(uint4*)&g_Xhi[base]     = *(uint4*)&hi16[0];
    *(uint4*)&g_Xhi[base + 8] = *(uint4*)&hi16[8];
    *(uint4*)&g_Xlo[base]     = *(uint4*)&lo16[0];
    *(uint4*)&g_Xlo[base + 8] = *(uint4*)&lo16[8];
}

__global__ __launch_bounds__(128) void c12_kernel() {
    __shared__ float su[HH], sw[HH];
    int t = blockIdx.x, tid = threadIdx.x;
    for (int i = tid; i < HH; i += 128) { su[i] = g_u[i]; sw[i] = g_w2[i]; }
    __syncthreads();
    float c1 = 0.f, c2 = 0.f;
    const float* src = g_bufB + (size_t)t*HH*BB + tid;
    #pragma unroll 4
    for (int h = 0; h < HH; h++) {
        float v = src[(size_t)h*BB];
        c1 += v * su[h];
        c2 += v * sw[h];
    }
    g_c1[t*BB + tid] = c1;
    g_c2[t*BB + tid] = c2;
}

// ============== wmma GEMM cores ==============
#define LDA16 24
#define LDS   132
#define SM_DYN (128*LDS*4)
#define BUF_AT 12288

typedef wmma::fragment<wmma::matrix_a, 16,16,16, __nv_bfloat16, wmma::row_major> FragA;
typedef wmma::fragment<wmma::matrix_b, 16,16,16, __nv_bfloat16, wmma::col_major> FragB;
typedef wmma::fragment<wmma::accumulator, 16,16,16, float> FragC;

// 2-term core: A hi-only, B hi+lo.  (used by y_mma)
__device__ __forceinline__ void mma_tile_pre2(
        const __nv_bfloat16* Ahi, size_t sA,
        const __nv_bfloat16* Bhi, const __nv_bfloat16* Blo, size_t sB,
        char* sm, float* stage) {
    int tid = threadIdx.x, wid = tid >> 5;
    int wm = (wid & 1) * 64, wn = (wid >> 1) * 32;
    int isB = tid >> 7;
    int row = tid & 127;
    const __nv_bfloat16* ghi = isB ? (Bhi + (size_t)row*sB) : (Ahi + (size_t)row*sA);
    const __nv_bfloat16* glo = isB ? (Blo + (size_t)row*sB) : (Ahi + (size_t)row*sA);

    FragC acc[4][2];
    #pragma unroll
    for (int i = 0; i < 4; i++)
        #pragma unroll
        for (int j = 0; j < 2; j++)
            wmma::fill_fragment(acc[i][j], 0.0f);

    uint4 ph0 = *(const uint4*)(ghi);
    uint4 ph1 = *(const uint4*)(ghi + 8);
    uint4 pl0, pl1;
    if (isB) { pl0 = *(const uint4*)(glo); pl1 = *(const uint4*)(glo + 8); }

    for (int ck = 0; ck < 32; ck++) {
        __nv_bfloat16* buf = (__nv_bfloat16*)sm + (ck & 1)*BUF_AT;
        __nv_bfloat16* dhi = buf + isB*6144 + row*LDA16;
        *(uint4*)dhi       = ph0;
        *(uint4*)(dhi + 8) = ph1;
        if (isB) {
            *(uint4*)(dhi + 3072)     = pl0;
            *(uint4*)(dhi + 3072 + 8) = pl1;
        }
        __syncthreads();
        if (ck < 31) {
            ph0 = *(const uint4*)(ghi + (ck+1)*16);
            ph1 = *(const uint4*)(ghi + (ck+1)*16 + 8);
            if (isB) {
                pl0 = *(const uint4*)(glo + (ck+1)*16);
                pl1 = *(const uint4*)(glo + (ck+1)*16 + 8);
            }
        }
        __nv_bfloat16* sA_ = buf;
        __nv_bfloat16* sB_ = buf + 6144;
        FragA ah[4];
        #pragma unroll
        for (int i = 0; i < 4; i++)
            wmma::load_matrix_sync(ah[i], sA_ + (wm + i*16)*LDA16, LDA16);
        #pragma unroll
        for (int j = 0; j < 2; j++) {
            FragB bh, bl;
            wmma::load_matrix_sync(bh, sB_ + (wn + j*16)*LDA16, LDA16);
            wmma::load_matrix_sync(bl, sB_ + 3072 + (wn + j*16)*LDA16, LDA16);
            #pragma unroll
            for (int i = 0; i < 4; i++) {
                wmma::mma_sync(acc[i][j], ah[i], bh, acc[i][j]);
                wmma::mma_sync(acc[i][j], ah[i], bl, acc[i][j]);
            }
        }
    }
    __syncthreads();
    #pragma unroll
    for (int i = 0; i < 4; i++)
        #pragma unroll
        for (int j = 0; j < 2; j++)
            wmma::store_matrix_sync(stage + (wm + i*16)*LDS + wn + j*16,
                                    acc[i][j], LDS, wmma::mem_row_major);
    __syncthreads();
}

// 1-term core: A hi, B hi.  (used by attention)
__device__ __forceinline__ void mma_tile_pre1(
        const __nv_bfloat16* Ahi, size_t sA,
        const __nv_bfloat16* Bhi, size_t sB,
        char* sm, float* stage) {
    int tid = threadIdx.x, wid = tid >> 5;
    int wm = (wid & 1) * 64, wn = (wid >> 1) * 32;
    int isB = tid >> 7;
    int row = tid & 127;
    const __nv_bfloat16* ghi = isB ? (Bhi + (size_t)row*sB) : (Ahi + (size_t)row*sA);

    FragC acc[4][2];
    #pragma unroll
    for (int i = 0; i < 4; i++)
        #pragma unroll
        for (int j = 0; j < 2; j++)
            wmma::fill_fragment(acc[i][j], 0.0f);

    uint4 ph0 = *(const uint4*)(ghi);
    uint4 ph1 = *(const uint4*)(ghi + 8);

    for (int ck = 0; ck < 32; ck++) {
        __nv_bfloat16* buf = (__nv_bfloat16*)sm + (ck & 1)*BUF_AT;
        __nv_bfloat16* dhi = buf + isB*6144 + row*LDA16;
        *(uint4*)dhi       = ph0;
        *(uint4*)(dhi + 8) = ph1;
        __syncthreads();
        if (ck < 31) {
            ph0 = *(const uint4*)(ghi + (ck+1)*16);
            ph1 = *(const uint4*)(ghi + (ck+1)*16 + 8);
        }
        __nv_bfloat16* sA_ = buf;
        __nv_bfloat16* sB_ = buf + 6144;
        FragA ah[4];
        #pragma unroll
        for (int i = 0; i < 4; i++)
            wmma::load_matrix_sync(ah[i], sA_ + (wm + i*16)*LDA16, LDA16);
        #pragma unroll
        for (int j = 0; j < 2; j++) {
            FragB bh;
            wmma::load_matrix_sync(bh, sB_ + (wn + j*16)*LDA16, LDA16);
            #pragma unroll
            for (int i = 0; i < 4; i++)
                wmma::mma_sync(acc[i][j], ah[i], bh, acc[i][j]);
        }
    }
    __syncthreads();
    #pragma unroll
    for (int i = 0; i < 4; i++)
        #pragma unroll
        for (int j = 0; j < 2; j++)
            wmma::store_matrix_sync(stage + (wm + i*16)*LDS + wn + j*16,
                                    acc[i][j], LDS, wmma::mem_row_major);
    __syncthreads();
}

// ============== Y = Xhi (Aophi+Aoplo)^T, output bf16 hi only ==============
__global__ __launch_bounds__(256, 2) void y_mma_kernel() {
    extern __shared__ char sm[];
    float* stage = (float*)sm;
    int n0 = blockIdx.x*128, m0 = blockIdx.y*128;
    int tid = threadIdx.x;

    mma_tile_pre2(g_Xhi + (size_t)m0*HH, HH,
                  g_Aophi + (size_t)n0*HH, g_Aoplo + (size_t)n0*HH, HH,
                  sm, stage);

    int c = tid & 127, rr = tid >> 7;
    for (int r2 = rr; r2 < 128; r2 += 2)
        g_Yhi[(size_t)(m0 + r2)*HH + n0 + c] = __float2bfloat16(stage[r2*LDS + c]);
}

// ============== attention: sigmoid((Yhi.Xhi + c1 + c2 + c0)*s) sums ==========
__global__ __launch_bounds__(256, 2) void attn_mma_kernel() {
    extern __shared__ char sm[];
    float* stage = (float*)sm;
    __shared__ float c1row[128];
    int b  = blockIdx.z;
    int n0 = blockIdx.x * 128;
    int m0 = blockIdx.y * 128;
    int tid = threadIdx.x;

    mma_tile_pre1(g_Yhi + ((size_t)m0*BB + b)*HH, (size_t)BB*HH,
                  g_Xhi + ((size_t)n0*BB + b)*HH, (size_t)BB*HH,
                  sm, stage);

    if (tid < 128) c1row[tid] = g_c1[(m0 + tid)*BB + b];
    __syncthreads();

    const float scale = 0.04419417382415922f;  // 512^-0.5
    if (tid < 128) {
        float c2v = g_c2[(n0 + tid)*BB + b] + g_cc[0];
        float s = 0.f;
        #pragma unroll 4
        for (int rr = 0; rr < 128; rr++) {
            float lg = stage[rr*LDS + tid] + c1row[rr] + c2v;
            s += 1.0f / (1.0f + __expf(-lg*scale));
        }
        g_wpart[blockIdx.y*(BB*TT) + b*TT + n0 + tid] = s;
    }
}

// ============== tails ==============
__global__ void reduce_w_kernel() {
    int i = blockIdx.x*256 + threadIdx.x;
    g_wsum[i] = g_wpart[i] + g_wpart[BB*TT + i]
              + g_wpart[2*BB*TT + i] + g_wpart[3*BB*TT + i];
}

__global__ __launch_bounds__(128) void zsum_kernel() {
    int kq = blockIdx.x, b = blockIdx.y;
    int k = kq*128 + threadIdx.x;
    float acc = 0.f, sw = 0.f;
    const float* wrow = g_wsum + b*TT;
    #pragma unroll 4
    for (int s = 0; s < TT; s++) {
        float w = wrow[s];
        sw += w;
        size_t idx = ((size_t)s*BB + b)*HH + k;
        float xv = __bfloat162float(g_Xhi[idx]) + __bfloat162float(g_Xlo[idx]);
        acc += w * xv;
    }
    g_z[b*HH + k] = acc;
    if (kq == 0 && threadIdx.x == 0) g_sw[b] = sw;
}

__global__ __launch_bounds__(128) void featw_kernel(
        const float* __restrict__ wv, const float* __restrict__ bv) {
    __shared__ float zs[HH];
    int b = blockIdx.y;
    int d = blockIdx.x*128 + threadIdx.x;
    for (int i = threadIdx.x; i < HH; i += 128) zs[i] = g_z[b*HH + i];
    __syncthreads();
    const float* wr = wv + (size_t)d*HH;
    float acc = 0.f;
    #pragma unroll 4
    for (int k = 0; k < HH; k++) acc += zs[k] * wr[k];
    g_feat[b*HH + d] = (acc + g_sw[b]*bv[d]) * (1.0f/TT);
}

__global__ void feat_bn_kernel(const float* __restrict__ g,
                               const float* __restrict__ bb) {
    int d = threadIdx.x;
    float s = 0.f, sq = 0.f;
    for (int b = 0; b < BB; b++) {
        float v = g_feat[b*HH + d];
        s += v; sq += v*v;
    }
    float m = s * (1.0f/BB);
    float rstd = rsqrtf(sq*(1.0f/BB) - m*m + 1e-5f);
    float gg = g[d]*rstd;
    float bo = bb[d] - m*gg;
    for (int b = 0; b < BB; b++)
        g_featn[b*HH + d] = g_feat[b*HH + d]*gg + bo;
}

__global__ void final_lin_kernel(const float* __restrict__ wh,
                                 const float* __restrict__ bh,
                                 float* __restrict__ out) {
    __shared__ float fs[HH];
    int b = blockIdx.x;
    int o = threadIdx.x;
    for (int i = o; i < HH; i += 96) fs[i] = g_featn[b*HH + i];
    __syncthreads();
    float acc = bh[o];
    for (int d = 0; d < HH; d++) acc += fs[d] * wh[o*HH + d];
    out[b*HORZ + o] = acc;
}

// ---------------- launch ------------------------------------------------------
extern "C" void kernel_launch(void* const* d_in, const int* in_sizes, int n_in,
                              void* d_out, int out_size) {
    const float* x        = (const float*)d_in[0];
    const float* conv_w   = (const float*)d_in[1];
    const float* conv_b   = (const float*)d_in[2];
    const float* bn1_g    = (const float*)d_in[3];
    const float* bn1_b    = (const float*)d_in[4];
    const float* beta_enc = (const float*)d_in[5];
    const float* bn2_g    = (const float*)d_in[6];
    const float* bn2_b    = (const float*)d_in[7];
    const float* beta2    = (const float*)d_in[8];
    const float* bn3_g    = (const float*)d_in[9];
    const float* bn3_b    = (const float*)d_in[10];
    const float* beta3    = (const float*)d_in[11];
    const float* wq       = (const float*)d_in[12];
    const float* bq       = (const float*)d_in[13];
    const float* wk       = (const float*)d_in[14];
    const float* bk       = (const float*)d_in[15];
    const float* wv       = (const float*)d_in[16];
    const float* bv       = (const float*)d_in[17];
    const float* bna_g    = (const float*)d_in[18];
    const float* bna_b    = (const float*)d_in[19];
    const float* wh       = (const float*)d_in[20];
    const float* bh       = (const float*)d_in[21];
    float* out = (float*)d_out;

    cudaFuncSetAttribute(y_mma_kernel,    cudaFuncAttributeMaxDynamicSharedMemorySize, SM_DYN);
    cudaFuncSetAttribute(attn_mma_kernel, cudaFuncAttributeMaxDynamicSharedMemorySize, SM_DYN);

    prep_uwc_kernel<<<4, 128>>>(wq, bk, wk, bq);
    aop_kernel<<<dim3(4, 32), 128>>>(wq, wk);

    conv_kernel<<<dim3(NCHN/16, BB), 128>>>(x, conv_w, conv_b);
    chan_stats_kernel<<<NCHN, 256>>>();
    bn1t_kernel<<<dim3(NCHN, 4), 128>>>(bn1_g, bn1_b);

    snn_fused_kernel<<<HH, 128>>>(beta_enc, bn2_g, bn2_b, beta2, bn3_g, bn3_b, beta3);

    xpose_kernel<<<dim3(TT, 16), 256>>>();
    c12_kernel<<<TT, 128>>>();

    y_mma_kernel<<<dim3(4, TT), 256, SM_DYN>>>();
    attn_mma_kernel<<<dim3(TT/128, TT/128, BB), 256, SM_DYN>>>();

    reduce_w_kernel<<<(BB*TT)/256, 256>>>();
    zsum_kernel<<<dim3(4, BB), 128>>>();
    featw_kernel<<<dim3(4, BB), 128>>>(wv, bv);
    feat_bn_kernel<<<1, HH>>>(bna_g, bna_b);
    final_lin_kernel<<<BB, HORZ>>>(wh, bh, out);
}